// round 4
// baseline (speedup 1.0000x reference)
#include <cuda_runtime.h>
#include <cuda_bf16.h>
#include <cstdint>
#include <math.h>

#define NB 4
#define HH 64
#define WW 64
#define HW 4096
#define CIN 256
#define DC 64
#define COUT 256
#define KP 6912      /* 3 * 2304: [hi | lo | hi] split-K */
#define KROW (KP * 2)          /* bytes per K-row: 13824 */
#define KCHUNKS 108            /* KP / 64 */

// ---------------- device scratch ----------------
__device__ float g_cols[(size_t)NB * 576 * HW];            // stage-2 f32 cols
__device__ float g_offsets[(size_t)NB * 18 * HW];
__device__ float g_mask[(size_t)NB * 9 * HW];
__device__ __nv_bfloat16 g_colsbf[(size_t)NB * HW * KP];   // 226 MB
__device__ __nv_bfloat16 g_wbf[(size_t)COUT * KP];

// ---------------- PTX helpers ----------------
__device__ __forceinline__ uint32_t smem_u32(const void* p) {
    uint32_t a;
    asm("{ .reg .u64 t; cvta.to.shared.u64 t, %1; cvt.u32.u64 %0, t; }"
        : "=r"(a) : "l"(p));
    return a;
}

__device__ __forceinline__ void cp_async16(uint32_t dst, const void* src) {
    asm volatile("cp.async.cg.shared.global [%0], [%1], 16;"
                 :: "r"(dst), "l"(src) : "memory");
}
__device__ __forceinline__ void cp_commit() {
    asm volatile("cp.async.commit_group;" ::: "memory");
}
template <int N>
__device__ __forceinline__ void cp_wait() {
    asm volatile("cp.async.wait_group %0;" :: "n"(N) : "memory");
}

__device__ __forceinline__ void ldsm_x4(uint32_t (&r)[4], uint32_t addr) {
    asm volatile("ldmatrix.sync.aligned.m8n8.x4.shared.b16 {%0,%1,%2,%3}, [%4];"
                 : "=r"(r[0]), "=r"(r[1]), "=r"(r[2]), "=r"(r[3]) : "r"(addr));
}

__device__ __forceinline__ void mma16816(float (&d)[4], const uint32_t (&a)[4],
                                         uint32_t b0, uint32_t b1) {
    asm volatile(
        "mma.sync.aligned.m16n8k16.row.col.f32.bf16.bf16.f32 "
        "{%0,%1,%2,%3}, {%4,%5,%6,%7}, {%8,%9}, {%0,%1,%2,%3};"
        : "+f"(d[0]), "+f"(d[1]), "+f"(d[2]), "+f"(d[3])
        : "r"(a[0]), "r"(a[1]), "r"(a[2]), "r"(a[3]), "r"(b0), "r"(b1));
}

// ---------------------------------------------------------------------------
// Weight prep: W[cout][c][k] f32 -> wbf[cout][pass*2304 + k*256 + c]
// pass0=hi, pass1=hi, pass2=lo
// ---------------------------------------------------------------------------
__global__ void prep_w_kernel(const float* __restrict__ w,
                              __nv_bfloat16* __restrict__ wbf) {
    int cout = blockIdx.x;
    int c = threadIdx.x;
#pragma unroll
    for (int k = 0; k < 9; k++) {
        float v = w[((size_t)cout * 256 + c) * 9 + k];
        __nv_bfloat16 hb = __float2bfloat16(v);
        __nv_bfloat16 lb = __float2bfloat16(v - __bfloat162float(hb));
        size_t b = (size_t)cout * KP + k * 256 + c;
        wbf[b] = hb;
        wbf[b + 2304] = hb;
        wbf[b + 4608] = lb;
    }
}

// ---------------------------------------------------------------------------
// Stage-1 GEMM with IMPLICIT im2col of cat(x, depth). M=18, K=2880.
// ---------------------------------------------------------------------------
__global__ void __launch_bounds__(256, 2)
sgemm_s1(const float* __restrict__ x, const float* __restrict__ depth,
         const float* __restrict__ A, const float* __restrict__ bias,
         float* __restrict__ C) {
    const int M = 18, K = 2880;
    __shared__ float As[16][36];
    __shared__ float Bs[16][128];
    const int tid = threadIdx.x;
    const int n0 = blockIdx.x * 128;
    const int n = blockIdx.z;
    const int tx = tid % 16, ty = tid / 16;

    float acc[2][8];
#pragma unroll
    for (int i = 0; i < 2; i++)
#pragma unroll
        for (int j = 0; j < 8; j++) acc[i][j] = 0.f;

    float4 ra;
    float rbv[8];

    auto loadA = [&](int k0) {
        if (tid < 128) {
            int row = tid / 4, kq = tid % 4;
            ra = (row < M) ? *reinterpret_cast<const float4*>(&A[(size_t)row * K + k0 + kq * 4])
                           : make_float4(0.f, 0.f, 0.f, 0.f);
        }
    };
    auto loadB = [&](int k0) {
#pragma unroll
        for (int t = 0; t < 8; t++) {
            int idx = tid + t * 256;
            int row = idx >> 7, col = idx & 127;
            int gk = k0 + row;
            int c = gk / 9;
            int kk = gk - 9 * c;
            int kh = kk / 3, kw = kk - 3 * kh;
            int p = n0 + col;
            int h = p >> 6, w = p & 63;
            int iy = h + kh - 1, ix = w + kw - 1;
            const float* s = (c < CIN) ? x + ((size_t)n * CIN + c) * HW
                                       : depth + ((size_t)n * DC + (c - CIN)) * HW;
            rbv[t] = (iy >= 0 && iy < HH && ix >= 0 && ix < WW) ? s[iy * WW + ix] : 0.f;
        }
    };
    auto storeA = [&]() {
        if (tid < 128) {
            int row = tid / 4, kq = tid % 4;
            As[kq * 4 + 0][row] = ra.x;
            As[kq * 4 + 1][row] = ra.y;
            As[kq * 4 + 2][row] = ra.z;
            As[kq * 4 + 3][row] = ra.w;
        }
    };
    auto storeB = [&]() {
#pragma unroll
        for (int t = 0; t < 8; t++) {
            int idx = tid + t * 256;
            Bs[idx >> 7][idx & 127] = rbv[t];
        }
    };

    loadA(0); loadB(0);
    storeA(); storeB();
    __syncthreads();

    const int ktiles = K / 16;
    for (int t = 0; t < ktiles; t++) {
        if (t + 1 < ktiles) { loadA((t + 1) * 16); loadB((t + 1) * 16); }
#pragma unroll
        for (int kk = 0; kk < 16; kk++) {
            float a0 = As[kk][ty * 2], a1 = As[kk][ty * 2 + 1];
            float b[8];
#pragma unroll
            for (int j = 0; j < 8; j++) b[j] = Bs[kk][tx * 8 + j];
#pragma unroll
            for (int j = 0; j < 8; j++) { acc[0][j] += a0 * b[j]; acc[1][j] += a1 * b[j]; }
        }
        __syncthreads();
        if (t + 1 < ktiles) { storeA(); storeB(); __syncthreads(); }
    }

#pragma unroll
    for (int i = 0; i < 2; i++) {
        int gm = ty * 2 + i;
        if (gm < M) {
            float bi = bias[gm];
            float* cp = &C[((size_t)n * M + gm) * HW + n0 + tx * 8];
#pragma unroll
            for (int j = 0; j < 8; j += 4)
                *reinterpret_cast<float4*>(cp + j) =
                    make_float4(acc[i][j] + bi, acc[i][j + 1] + bi,
                                acc[i][j + 2] + bi, acc[i][j + 3] + bi);
        }
    }
}

// ---------------------------------------------------------------------------
// Stage-2 deformable im2col (f32, depth, no mask): cols[n][(c*9+k)][p]
// ---------------------------------------------------------------------------
__global__ void deform_im2col_f32(const float* __restrict__ xin,
                                  const float* __restrict__ offs,
                                  float* __restrict__ cols) {
    int p = blockIdx.x * blockDim.x + threadIdx.x;
    int c = blockIdx.y;
    int n = blockIdx.z;
    int h = p >> 6, w = p & 63;
    const float* src = xin + ((size_t)n * DC + c) * HW;
    const float* offn = offs + (size_t)n * 18 * HW;
    float* dst = cols + ((size_t)n * DC * 9 + (size_t)c * 9) * HW + p;
#pragma unroll
    for (int k = 0; k < 9; k++) {
        int kh = k / 3, kw = k % 3;
        float dy = offn[(size_t)(2 * k + 0) * HW + p];
        float dx = offn[(size_t)(2 * k + 1) * HW + p];
        float y = (float)(h - 1 + kh) + dy;
        float xx = (float)(w - 1 + kw) + dx;
        float y0f = floorf(y), x0f = floorf(xx);
        float ly = y - y0f, lx = xx - x0f;
        int y0 = (int)y0f, x0 = (int)x0f;
        int y1 = y0 + 1, x1 = x0 + 1;
        bool vy0 = (y0 >= 0) & (y0 < HH);
        bool vy1 = (y1 >= 0) & (y1 < HH);
        bool vx0 = (x0 >= 0) & (x0 < WW);
        bool vx1 = (x1 >= 0) & (x1 < WW);
        float v00 = (vy0 & vx0) ? src[y0 * WW + x0] : 0.f;
        float v01 = (vy0 & vx1) ? src[y0 * WW + x1] : 0.f;
        float v10 = (vy1 & vx0) ? src[y1 * WW + x0] : 0.f;
        float v11 = (vy1 & vx1) ? src[y1 * WW + x1] : 0.f;
        float v = v00 * (1.f - ly) * (1.f - lx) + v01 * (1.f - ly) * lx
                + v10 * ly * (1.f - lx) + v11 * ly * lx;
        dst[(size_t)k * HW] = v;
    }
}

// ---------------------------------------------------------------------------
// Small SGEMM for stage-2 mask (M=9, K=576), sigmoid epilogue.
// ---------------------------------------------------------------------------
__global__ void __launch_bounds__(256, 2)
sgemm_mask(const float* __restrict__ A, const float* __restrict__ B,
           const float* __restrict__ bias, float* __restrict__ C) {
    const int M = 9, K = 576;
    __shared__ float As[16][36];
    __shared__ float Bs[16][128];
    const int tid = threadIdx.x;
    const int n0 = blockIdx.x * 128;
    const int n = blockIdx.z;
    const float* Bb = B + (size_t)n * K * HW;
    const int tx = tid % 16, ty = tid / 16;

    float acc[2][8];
#pragma unroll
    for (int i = 0; i < 2; i++)
#pragma unroll
        for (int j = 0; j < 8; j++) acc[i][j] = 0.f;

    float4 ra, rb[2];
    auto loadA = [&](int k0) {
        if (tid < 128) {
            int row = tid / 4, kq = tid % 4;
            ra = (row < M) ? *reinterpret_cast<const float4*>(&A[(size_t)row * K + k0 + kq * 4])
                           : make_float4(0.f, 0.f, 0.f, 0.f);
        }
    };
    auto loadB = [&](int k0) {
#pragma unroll
        for (int t = 0; t < 2; t++) {
            int idx = tid + t * 256;
            int row = idx / 32, c4 = idx % 32;
            rb[t] = *reinterpret_cast<const float4*>(
                &Bb[(size_t)(k0 + row) * HW + n0 + c4 * 4]);
        }
    };
    auto storeAB = [&]() {
        if (tid < 128) {
            int row = tid / 4, kq = tid % 4;
            As[kq * 4 + 0][row] = ra.x;
            As[kq * 4 + 1][row] = ra.y;
            As[kq * 4 + 2][row] = ra.z;
            As[kq * 4 + 3][row] = ra.w;
        }
#pragma unroll
        for (int t = 0; t < 2; t++) {
            int idx = tid + t * 256;
            int row = idx / 32, c4 = idx % 32;
            *reinterpret_cast<float4*>(&Bs[row][c4 * 4]) = rb[t];
        }
    };

    loadA(0); loadB(0); storeAB();
    __syncthreads();
    const int ktiles = K / 16;
    for (int t = 0; t < ktiles; t++) {
        if (t + 1 < ktiles) { loadA((t + 1) * 16); loadB((t + 1) * 16); }
#pragma unroll
        for (int kk = 0; kk < 16; kk++) {
            float a0 = As[kk][ty * 2], a1 = As[kk][ty * 2 + 1];
            float b[8];
#pragma unroll
            for (int j = 0; j < 8; j++) b[j] = Bs[kk][tx * 8 + j];
#pragma unroll
            for (int j = 0; j < 8; j++) { acc[0][j] += a0 * b[j]; acc[1][j] += a1 * b[j]; }
        }
        __syncthreads();
        if (t + 1 < ktiles) { storeAB(); __syncthreads(); }
    }
#pragma unroll
    for (int i = 0; i < 2; i++) {
        int gm = ty * 2 + i;
        if (gm < M) {
            float bi = bias[gm];
            float* cp = &C[((size_t)n * M + gm) * HW + n0 + tx * 8];
#pragma unroll
            for (int j = 0; j < 8; j++) {
                float v = acc[i][j] + bi;
                cp[j] = 1.f / (1.f + expf(-v));
            }
        }
    }
}

// ---------------------------------------------------------------------------
// Stage-3 deformable im2col -> bf16 split-K transposed layout:
// colsT[n][p][pass*2304 + k*256 + c], pass0=hi, pass1=lo, pass2=hi.
// grid (32, 9, NB), block 128
// ---------------------------------------------------------------------------
__global__ void __launch_bounds__(128)
deform_im2col_bf16(const float* __restrict__ x, const float* __restrict__ offs,
                   const float* __restrict__ mask, __nv_bfloat16* __restrict__ colsT) {
    int p = blockIdx.x * 128 + threadIdx.x;
    int k = blockIdx.y;
    int n = blockIdx.z;
    int h = p >> 6, w = p & 63;
    const float* offn = offs + (size_t)n * 18 * HW;
    float dy = offn[(size_t)(2 * k) * HW + p];
    float dx = offn[(size_t)(2 * k + 1) * HW + p];
    float mk = mask[((size_t)n * 9 + k) * HW + p];
    float y = (float)(h - 1 + k / 3) + dy;
    float xx = (float)(w - 1 + k % 3) + dx;
    float y0f = floorf(y), x0f = floorf(xx);
    float ly = y - y0f, lx = xx - x0f;
    int y0 = (int)y0f, x0 = (int)x0f;
    int y1 = y0 + 1, x1 = x0 + 1;
    bool vy0 = (y0 >= 0) & (y0 < HH);
    bool vy1 = (y1 >= 0) & (y1 < HH);
    bool vx0 = (x0 >= 0) & (x0 < WW);
    bool vx1 = (x1 >= 0) & (x1 < WW);
    float w00 = (vy0 & vx0) ? (1.f - ly) * (1.f - lx) * mk : 0.f;
    float w01 = (vy0 & vx1) ? (1.f - ly) * lx * mk : 0.f;
    float w10 = (vy1 & vx0) ? ly * (1.f - lx) * mk : 0.f;
    float w11 = (vy1 & vx1) ? ly * lx * mk : 0.f;
    int i00 = (vy0 & vx0) ? y0 * WW + x0 : 0;
    int i01 = (vy0 & vx1) ? y0 * WW + x1 : 0;
    int i10 = (vy1 & vx0) ? y1 * WW + x0 : 0;
    int i11 = (vy1 & vx1) ? y1 * WW + x1 : 0;

    const float* src = x + (size_t)n * CIN * HW;
    __nv_bfloat16* base = colsT + ((size_t)(n * HW) + p) * KP + k * 256;

    for (int c8 = 0; c8 < 256; c8 += 8) {
        __align__(16) __nv_bfloat16 hi[8];
        __align__(16) __nv_bfloat16 lo[8];
#pragma unroll
        for (int j = 0; j < 8; j++) {
            const float* s = src + (size_t)(c8 + j) * HW;
            float v = w00 * s[i00] + w01 * s[i01] + w10 * s[i10] + w11 * s[i11];
            __nv_bfloat16 hb = __float2bfloat16(v);
            hi[j] = hb;
            lo[j] = __float2bfloat16(v - __bfloat162float(hb));
        }
        uint4 H = *reinterpret_cast<uint4*>(hi);
        uint4 L = *reinterpret_cast<uint4*>(lo);
        *reinterpret_cast<uint4*>(base + c8) = H;
        *reinterpret_cast<uint4*>(base + 2304 + c8) = L;
        *reinterpret_cast<uint4*>(base + 4608 + c8) = H;
    }
}

// ---------------------------------------------------------------------------
// Stage-3 HMMA GEMM: out[p 128][cout 256] = colsT[p][K'] . wbf[cout][K']
// mma.sync m16n8k16 bf16, BK=64 (128B rows, xor-8 swizzle), cp.async 2-stage.
// 8 warps as 2(M)x4(N), warp tile 64x64. grid (32, 1, NB), 256 thr, 96KB smem.
// ---------------------------------------------------------------------------
#define ABYTES 16384            /* 128 rows * 128B */
#define BBYTES 32768            /* 256 rows * 128B */
#define STAGEB (ABYTES + BBYTES)

__global__ void __launch_bounds__(256, 1)
hmma_gemm(const __nv_bfloat16* __restrict__ colsT,
          const __nv_bfloat16* __restrict__ wbf,
          const float* __restrict__ bias, float* __restrict__ out) {
    extern __shared__ char smem[];
    const uint32_t sb = smem_u32(smem);
    const int tid = threadIdx.x;
    const int wid = tid >> 5, lane = tid & 31;
    const int wm = wid >> 2, wn = wid & 3;      // 2 x 4 warp grid
    const int p0 = blockIdx.x * 128;
    const int n = blockIdx.z;

    const char* Ag = (const char*)(colsT + (size_t)(n * HW + p0) * KP);
    const char* Bg = (const char*)wbf;

    float acc[4][8][4];
#pragma unroll
    for (int i = 0; i < 4; i++)
#pragma unroll
        for (int j = 0; j < 8; j++)
#pragma unroll
            for (int r = 0; r < 4; r++) acc[i][j][r] = 0.f;

    auto load_chunk = [&](int kt, int buf) {
        uint32_t dA = sb + buf * STAGEB;
        uint32_t dB = dA + ABYTES;
        // A: 128 rows x 8 x 16B -> 4 per thread
#pragma unroll
        for (int u = 0; u < 4; u++) {
            int idx = tid + u * 256;
            int row = idx >> 3, c = idx & 7;
            cp_async16(dA + row * 128 + ((c ^ (row & 7)) << 4),
                       Ag + (size_t)row * KROW + kt * 128 + c * 16);
        }
        // B: 256 rows x 8 x 16B -> 8 per thread
#pragma unroll
        for (int u = 0; u < 8; u++) {
            int idx = tid + u * 256;
            int row = idx >> 3, c = idx & 7;
            cp_async16(dB + row * 128 + ((c ^ (row & 7)) << 4),
                       Bg + (size_t)row * KROW + kt * 128 + c * 16);
        }
        cp_commit();
    };

    auto compute_chunk = [&](int buf) {
        uint32_t Ab = sb + buf * STAGEB;
        uint32_t Bb = Ab + ABYTES;
        const int rbase = ((lane >> 3) & 1) * 8 + (lane & 7);
        const int chi = (lane >> 4);            // 0 or 1 (k-half select)
#pragma unroll
        for (int ks = 0; ks < 4; ks++) {
            int c = ks * 2 + chi;
            uint32_t af[4][4], bf[4][4];
#pragma unroll
            for (int i = 0; i < 4; i++) {
                int row = wm * 64 + i * 16 + rbase;
                ldsm_x4(af[i], Ab + row * 128 + ((c ^ (row & 7)) << 4));
            }
#pragma unroll
            for (int j = 0; j < 4; j++) {
                int row = wn * 64 + j * 16 + rbase;
                ldsm_x4(bf[j], Bb + row * 128 + ((c ^ (row & 7)) << 4));
            }
#pragma unroll
            for (int i = 0; i < 4; i++)
#pragma unroll
                for (int j = 0; j < 4; j++)
#pragma unroll
                    for (int s = 0; s < 2; s++)
                        mma16816(acc[i][j * 2 + s], af[i], bf[j][s], bf[j][s + 2]);
        }
    };

    load_chunk(0, 0);
    for (int kt = 0; kt < KCHUNKS; kt++) {
        int buf = kt & 1;
        if (kt + 1 < KCHUNKS) {
            load_chunk(kt + 1, buf ^ 1);
            cp_wait<1>();
        } else {
            cp_wait<0>();
        }
        __syncthreads();
        compute_chunk(buf);
        __syncthreads();
    }

    // Epilogue: bias + scattered f32 stores (out is [n][cout][HW])
#pragma unroll
    for (int i = 0; i < 4; i++) {
        int m = wm * 64 + i * 16 + (lane >> 2);
#pragma unroll
        for (int j = 0; j < 4; j++)
#pragma unroll
            for (int s = 0; s < 2; s++) {
                int cout = wn * 64 + j * 16 + s * 8 + (lane & 3) * 2;
                float b0 = bias[cout], b1 = bias[cout + 1];
                float* o = out + ((size_t)n * COUT + cout) * HW + p0;
                const float* a = acc[i][j * 2 + s];
                o[m]          = a[0] + b0;
                o[HW + m]     = a[1] + b1;
                o[m + 8]      = a[2] + b0;
                o[HW + m + 8] = a[3] + b1;
            }
    }
}

// ---------------------------------------------------------------------------
extern "C" void kernel_launch(void* const* d_in, const int* in_sizes, int n_in,
                              void* d_out, int out_size) {
    const float* x      = (const float*)d_in[0];
    const float* depth  = (const float*)d_in[1];
    const float* weight = (const float*)d_in[2];
    const float* bias   = (const float*)d_in[3];
    const float* off_w  = (const float*)d_in[4];
    const float* off_b  = (const float*)d_in[5];
    const float* mask_w = (const float*)d_in[6];
    const float* mask_b = (const float*)d_in[7];
    float* out = (float*)d_out;

    void *pc, *po, *pm, *pcb, *pwb;
    cudaGetSymbolAddress(&pc, g_cols);
    cudaGetSymbolAddress(&po, g_offsets);
    cudaGetSymbolAddress(&pm, g_mask);
    cudaGetSymbolAddress(&pcb, g_colsbf);
    cudaGetSymbolAddress(&pwb, g_wbf);
    float* cols = (float*)pc;
    float* offsets = (float*)po;
    float* maskbuf = (float*)pm;
    __nv_bfloat16* colsbf = (__nv_bfloat16*)pcb;
    __nv_bfloat16* wbf = (__nv_bfloat16*)pwb;

    // Weight split prep (tiny)
    prep_w_kernel<<<COUT, 256>>>(weight, wbf);

    // Stage 1: offset conv via implicit-im2col SGEMM
    sgemm_s1<<<dim3(HW / 128, 1, NB), 256>>>(x, depth, off_w, off_b, offsets);

    // Stage 2: mask = sigmoid(deform_conv(depth, offset))
    deform_im2col_f32<<<dim3(HW / 256, DC, NB), 256>>>(depth, offsets, cols);
    sgemm_mask<<<dim3(HW / 128, 1, NB), 256>>>(mask_w, cols, mask_b, maskbuf);

    // Stage 3: modulated deformable conv via HMMA bf16 split-K GEMM
    deform_im2col_bf16<<<dim3(HW / 128, 9, NB), 128>>>(x, offsets, maskbuf, colsbf);

    static int smem_set = 0;
    if (!smem_set) {
        cudaFuncSetAttribute(hmma_gemm, cudaFuncAttributeMaxDynamicSharedMemorySize,
                             2 * STAGEB);
        smem_set = 1;
    }
    hmma_gemm<<<dim3(HW / 128, 1, NB), 256, 2 * STAGEB>>>(colsbf, wbf, bias, out);
}

// round 5
// speedup vs baseline: 1.5650x; 1.5650x over previous
#include <cuda_runtime.h>
#include <cuda_bf16.h>
#include <cstdint>
#include <math.h>

#define NB 4
#define HH 64
#define WW 64
#define HW 4096
#define CIN 256
#define DC 64
#define COUT 256
#define KPA 4608               /* A cols: [hi | lo], 2*2304 */
#define KPW 6912               /* W cols: [hi | hi | lo], 3*2304 */
#define KROWA (KPA * 2)        /* A row bytes: 9216 */
#define KROWW (KPW * 2)        /* W row bytes: 13824 */
#define KCHUNKS 108            /* KPW / 64 */

// ---------------- device scratch ----------------
__device__ float g_cols[(size_t)NB * 576 * HW];            // stage-2 f32 cols
__device__ float g_offsets[(size_t)NB * 18 * HW];
__device__ float g_mask[(size_t)NB * 9 * HW];
__device__ float g_xT[(size_t)NB * HW * CIN];              // x transposed [n][p][c]
__device__ __nv_bfloat16 g_colsbf[(size_t)NB * HW * KPA];  // 151 MB
__device__ __nv_bfloat16 g_wbf[(size_t)COUT * KPW];

// ---------------- PTX helpers ----------------
__device__ __forceinline__ uint32_t smem_u32(const void* p) {
    uint32_t a;
    asm("{ .reg .u64 t; cvta.to.shared.u64 t, %1; cvt.u32.u64 %0, t; }"
        : "=r"(a) : "l"(p));
    return a;
}

__device__ __forceinline__ void cp_async16(uint32_t dst, const void* src) {
    asm volatile("cp.async.cg.shared.global [%0], [%1], 16;"
                 :: "r"(dst), "l"(src) : "memory");
}
__device__ __forceinline__ void cp_commit() {
    asm volatile("cp.async.commit_group;" ::: "memory");
}
template <int N>
__device__ __forceinline__ void cp_wait() {
    asm volatile("cp.async.wait_group %0;" :: "n"(N) : "memory");
}

__device__ __forceinline__ void ldsm_x4(uint32_t (&r)[4], uint32_t addr) {
    asm volatile("ldmatrix.sync.aligned.m8n8.x4.shared.b16 {%0,%1,%2,%3}, [%4];"
                 : "=r"(r[0]), "=r"(r[1]), "=r"(r[2]), "=r"(r[3]) : "r"(addr));
}

__device__ __forceinline__ void mma16816(float (&d)[4], const uint32_t (&a)[4],
                                         uint32_t b0, uint32_t b1) {
    asm volatile(
        "mma.sync.aligned.m16n8k16.row.col.f32.bf16.bf16.f32 "
        "{%0,%1,%2,%3}, {%4,%5,%6,%7}, {%8,%9}, {%0,%1,%2,%3};"
        : "+f"(d[0]), "+f"(d[1]), "+f"(d[2]), "+f"(d[3])
        : "r"(a[0]), "r"(a[1]), "r"(a[2]), "r"(a[3]), "r"(b0), "r"(b1));
}

// ---------------------------------------------------------------------------
// x transpose: x[n][c][p] -> xT[n][p][c]
// ---------------------------------------------------------------------------
__global__ void transpose_x(const float* __restrict__ x, float* __restrict__ xT) {
    __shared__ float t[32][33];
    int n = blockIdx.z;
    int p0 = blockIdx.x * 32, c0 = blockIdx.y * 32;
    int tx = threadIdx.x, ty = threadIdx.y;
#pragma unroll
    for (int j = 0; j < 32; j += 8)
        t[ty + j][tx] = x[((size_t)n * CIN + c0 + ty + j) * HW + p0 + tx];
    __syncthreads();
#pragma unroll
    for (int j = 0; j < 32; j += 8)
        xT[((size_t)n * HW + p0 + ty + j) * CIN + c0 + tx] = t[tx][ty + j];
}

// ---------------------------------------------------------------------------
// Weight prep: W[cout][c][k] f32 -> wbf[cout][pass*2304 + k*256 + c]
// pass0=hi, pass1=hi, pass2=lo
// ---------------------------------------------------------------------------
__global__ void prep_w_kernel(const float* __restrict__ w,
                              __nv_bfloat16* __restrict__ wbf) {
    int cout = blockIdx.x;
    int c = threadIdx.x;
#pragma unroll
    for (int k = 0; k < 9; k++) {
        float v = w[((size_t)cout * 256 + c) * 9 + k];
        __nv_bfloat16 hb = __float2bfloat16(v);
        __nv_bfloat16 lb = __float2bfloat16(v - __bfloat162float(hb));
        size_t b = (size_t)cout * KPW + k * 256 + c;
        wbf[b] = hb;
        wbf[b + 2304] = hb;
        wbf[b + 4608] = lb;
    }
}

// ---------------------------------------------------------------------------
// Stage-1 GEMM with IMPLICIT im2col of cat(x, depth). M=18, K=2880.
// Incremental (c,kk) indexing -- no divides in the hot loop.
// ---------------------------------------------------------------------------
__global__ void __launch_bounds__(256, 2)
sgemm_s1(const float* __restrict__ x, const float* __restrict__ depth,
         const float* __restrict__ A, const float* __restrict__ bias,
         float* __restrict__ C) {
    const int M = 18, K = 2880;
    __shared__ float As[16][36];
    __shared__ float Bs[16][128];
    const int tid = threadIdx.x;
    const int n0 = blockIdx.x * 128;
    const int n = blockIdx.z;
    const int tx = tid % 16, ty = tid / 16;
    const float* xn = x + (size_t)n * CIN * HW;
    const float* dn = depth + (size_t)n * DC * HW;

    float acc[2][8];
#pragma unroll
    for (int i = 0; i < 2; i++)
#pragma unroll
        for (int j = 0; j < 8; j++) acc[i][j] = 0.f;

    float4 ra;
    float rbv[8];

    // Per-slot incremental K-decomposition state (gk = c*9 + kk)
    int cS[8], kkS[8], hS[8], wS[8];
#pragma unroll
    for (int t = 0; t < 8; t++) {
        int idx = tid + t * 256;
        int row = idx >> 7, col = idx & 127;
        cS[t] = row / 9;
        kkS[t] = row - 9 * cS[t];
        int p = n0 + col;
        hS[t] = p >> 6;
        wS[t] = p & 63;
    }

    auto loadA = [&](int k0) {
        if (tid < 128) {
            int row = tid / 4, kq = tid % 4;
            ra = (row < M) ? *reinterpret_cast<const float4*>(&A[(size_t)row * K + k0 + kq * 4])
                           : make_float4(0.f, 0.f, 0.f, 0.f);
        }
    };
    auto loadB = [&]() {
#pragma unroll
        for (int t = 0; t < 8; t++) {
            int c = cS[t], kk = kkS[t];
            int kh = kk / 3, kw = kk - 3 * kh;          // kk in [0,8]: cheap
            int iy = hS[t] + kh - 1, ix = wS[t] + kw - 1;
            const float* s = (c < CIN) ? xn + (size_t)c * HW
                                       : dn + (size_t)(c - CIN) * HW;
            rbv[t] = (iy >= 0 && iy < HH && ix >= 0 && ix < WW) ? s[iy * WW + ix] : 0.f;
            // advance gk by 16
            kk += 16;
            if (kk >= 9) { kk -= 9; c++; }
            if (kk >= 9) { kk -= 9; c++; }
            cS[t] = c; kkS[t] = kk;
        }
    };
    auto storeA = [&]() {
        if (tid < 128) {
            int row = tid / 4, kq = tid % 4;
            As[kq * 4 + 0][row] = ra.x;
            As[kq * 4 + 1][row] = ra.y;
            As[kq * 4 + 2][row] = ra.z;
            As[kq * 4 + 3][row] = ra.w;
        }
    };
    auto storeB = [&]() {
#pragma unroll
        for (int t = 0; t < 8; t++) {
            int idx = tid + t * 256;
            Bs[idx >> 7][idx & 127] = rbv[t];
        }
    };

    loadA(0); loadB();
    storeA(); storeB();
    __syncthreads();

    const int ktiles = K / 16;
    for (int t = 0; t < ktiles; t++) {
        if (t + 1 < ktiles) { loadA((t + 1) * 16); loadB(); }
#pragma unroll
        for (int kk = 0; kk < 16; kk++) {
            float a0 = As[kk][ty * 2], a1 = As[kk][ty * 2 + 1];
            float b[8];
#pragma unroll
            for (int j = 0; j < 8; j++) b[j] = Bs[kk][tx * 8 + j];
#pragma unroll
            for (int j = 0; j < 8; j++) { acc[0][j] += a0 * b[j]; acc[1][j] += a1 * b[j]; }
        }
        __syncthreads();
        if (t + 1 < ktiles) { storeA(); storeB(); __syncthreads(); }
    }

#pragma unroll
    for (int i = 0; i < 2; i++) {
        int gm = ty * 2 + i;
        if (gm < M) {
            float bi = bias[gm];
            float* cp = &C[((size_t)n * M + gm) * HW + n0 + tx * 8];
#pragma unroll
            for (int j = 0; j < 8; j += 4)
                *reinterpret_cast<float4*>(cp + j) =
                    make_float4(acc[i][j] + bi, acc[i][j + 1] + bi,
                                acc[i][j + 2] + bi, acc[i][j + 3] + bi);
        }
    }
}

// ---------------------------------------------------------------------------
// Stage-2 deformable im2col (f32, depth, no mask): cols[n][(c*9+k)][p]
// ---------------------------------------------------------------------------
__global__ void deform_im2col_f32(const float* __restrict__ xin,
                                  const float* __restrict__ offs,
                                  float* __restrict__ cols) {
    int p = blockIdx.x * blockDim.x + threadIdx.x;
    int c = blockIdx.y;
    int n = blockIdx.z;
    int h = p >> 6, w = p & 63;
    const float* src = xin + ((size_t)n * DC + c) * HW;
    const float* offn = offs + (size_t)n * 18 * HW;
    float* dst = cols + ((size_t)n * DC * 9 + (size_t)c * 9) * HW + p;
#pragma unroll
    for (int k = 0; k < 9; k++) {
        int kh = k / 3, kw = k % 3;
        float dy = offn[(size_t)(2 * k + 0) * HW + p];
        float dx = offn[(size_t)(2 * k + 1) * HW + p];
        float y = (float)(h - 1 + kh) + dy;
        float xx = (float)(w - 1 + kw) + dx;
        float y0f = floorf(y), x0f = floorf(xx);
        float ly = y - y0f, lx = xx - x0f;
        int y0 = (int)y0f, x0 = (int)x0f;
        int y1 = y0 + 1, x1 = x0 + 1;
        bool vy0 = (y0 >= 0) & (y0 < HH);
        bool vy1 = (y1 >= 0) & (y1 < HH);
        bool vx0 = (x0 >= 0) & (x0 < WW);
        bool vx1 = (x1 >= 0) & (x1 < WW);
        float v00 = (vy0 & vx0) ? src[y0 * WW + x0] : 0.f;
        float v01 = (vy0 & vx1) ? src[y0 * WW + x1] : 0.f;
        float v10 = (vy1 & vx0) ? src[y1 * WW + x0] : 0.f;
        float v11 = (vy1 & vx1) ? src[y1 * WW + x1] : 0.f;
        float v = v00 * (1.f - ly) * (1.f - lx) + v01 * (1.f - ly) * lx
                + v10 * ly * (1.f - lx) + v11 * ly * lx;
        dst[(size_t)k * HW] = v;
    }
}

// ---------------------------------------------------------------------------
// Small SGEMM for stage-2 mask (M=9, K=576), sigmoid epilogue.
// ---------------------------------------------------------------------------
__global__ void __launch_bounds__(256, 2)
sgemm_mask(const float* __restrict__ A, const float* __restrict__ B,
           const float* __restrict__ bias, float* __restrict__ C) {
    const int M = 9, K = 576;
    __shared__ float As[16][36];
    __shared__ float Bs[16][128];
    const int tid = threadIdx.x;
    const int n0 = blockIdx.x * 128;
    const int n = blockIdx.z;
    const float* Bb = B + (size_t)n * K * HW;
    const int tx = tid % 16, ty = tid / 16;

    float acc[2][8];
#pragma unroll
    for (int i = 0; i < 2; i++)
#pragma unroll
        for (int j = 0; j < 8; j++) acc[i][j] = 0.f;

    float4 ra, rb[2];
    auto loadA = [&](int k0) {
        if (tid < 128) {
            int row = tid / 4, kq = tid % 4;
            ra = (row < M) ? *reinterpret_cast<const float4*>(&A[(size_t)row * K + k0 + kq * 4])
                           : make_float4(0.f, 0.f, 0.f, 0.f);
        }
    };
    auto loadB = [&](int k0) {
#pragma unroll
        for (int t = 0; t < 2; t++) {
            int idx = tid + t * 256;
            int row = idx / 32, c4 = idx % 32;
            rb[t] = *reinterpret_cast<const float4*>(
                &Bb[(size_t)(k0 + row) * HW + n0 + c4 * 4]);
        }
    };
    auto storeAB = [&]() {
        if (tid < 128) {
            int row = tid / 4, kq = tid % 4;
            As[kq * 4 + 0][row] = ra.x;
            As[kq * 4 + 1][row] = ra.y;
            As[kq * 4 + 2][row] = ra.z;
            As[kq * 4 + 3][row] = ra.w;
        }
#pragma unroll
        for (int t = 0; t < 2; t++) {
            int idx = tid + t * 256;
            int row = idx / 32, c4 = idx % 32;
            *reinterpret_cast<float4*>(&Bs[row][c4 * 4]) = rb[t];
        }
    };

    loadA(0); loadB(0); storeAB();
    __syncthreads();
    const int ktiles = K / 16;
    for (int t = 0; t < ktiles; t++) {
        if (t + 1 < ktiles) { loadA((t + 1) * 16); loadB((t + 1) * 16); }
#pragma unroll
        for (int kk = 0; kk < 16; kk++) {
            float a0 = As[kk][ty * 2], a1 = As[kk][ty * 2 + 1];
            float b[8];
#pragma unroll
            for (int j = 0; j < 8; j++) b[j] = Bs[kk][tx * 8 + j];
#pragma unroll
            for (int j = 0; j < 8; j++) { acc[0][j] += a0 * b[j]; acc[1][j] += a1 * b[j]; }
        }
        __syncthreads();
        if (t + 1 < ktiles) { storeAB(); __syncthreads(); }
    }
#pragma unroll
    for (int i = 0; i < 2; i++) {
        int gm = ty * 2 + i;
        if (gm < M) {
            float bi = bias[gm];
            float* cp = &C[((size_t)n * M + gm) * HW + n0 + tx * 8];
#pragma unroll
            for (int j = 0; j < 8; j++) {
                float v = acc[i][j] + bi;
                cp[j] = 1.f / (1.f + expf(-v));
            }
        }
    }
}

// ---------------------------------------------------------------------------
// Stage-3 deformable im2col v2: xT gathers (vectorized) + coalesced stores.
// Output: colsT[n][p][half*2304 + k*256 + c], half0=hi, half1=lo.
// Block: 32 pixels x 1 tap; warp w handles channels [32w, 32w+32).
// grid (HW/32, 9, NB), 256 threads.
// ---------------------------------------------------------------------------
__global__ void __launch_bounds__(256)
deform_im2col_bf16_v2(const float* __restrict__ xT, const float* __restrict__ offs,
                      const float* __restrict__ mask,
                      __nv_bfloat16* __restrict__ colsT) {
    __shared__ float s_w[4][32];
    __shared__ int s_i[4][32];
    __shared__ __align__(16) __nv_bfloat16 s_hi[32][264];  // 528B rows (16B-mult)
    __shared__ __align__(16) __nv_bfloat16 s_lo[32][264];

    const int k = blockIdx.y;
    const int n = blockIdx.z;
    const int p0 = blockIdx.x * 32;
    const int tid = threadIdx.x;
    const int lane = tid & 31, wrp = tid >> 5;

    if (tid < 32) {
        int p = p0 + tid;
        int h = p >> 6, w = p & 63;
        const float* offn = offs + (size_t)n * 18 * HW;
        float dy = offn[(size_t)(2 * k) * HW + p];
        float dx = offn[(size_t)(2 * k + 1) * HW + p];
        float mk = mask[((size_t)n * 9 + k) * HW + p];
        float y = (float)(h - 1 + k / 3) + dy;
        float xx = (float)(w - 1 + k % 3) + dx;
        float y0f = floorf(y), x0f = floorf(xx);
        float ly = y - y0f, lx = xx - x0f;
        int y0 = (int)y0f, x0 = (int)x0f;
        int y1 = y0 + 1, x1 = x0 + 1;
        bool vy0 = (y0 >= 0) & (y0 < HH);
        bool vy1 = (y1 >= 0) & (y1 < HH);
        bool vx0 = (x0 >= 0) & (x0 < WW);
        bool vx1 = (x1 >= 0) & (x1 < WW);
        s_w[0][tid] = (vy0 & vx0) ? (1.f - ly) * (1.f - lx) * mk : 0.f;
        s_w[1][tid] = (vy0 & vx1) ? (1.f - ly) * lx * mk : 0.f;
        s_w[2][tid] = (vy1 & vx0) ? ly * (1.f - lx) * mk : 0.f;
        s_w[3][tid] = (vy1 & vx1) ? ly * lx * mk : 0.f;
        s_i[0][tid] = (vy0 & vx0) ? y0 * WW + x0 : 0;
        s_i[1][tid] = (vy0 & vx1) ? y0 * WW + x1 : 0;
        s_i[2][tid] = (vy1 & vx0) ? y1 * WW + x0 : 0;
        s_i[3][tid] = (vy1 & vx1) ? y1 * WW + x1 : 0;
    }
    __syncthreads();

    {
        const int pl = lane;
        const float w00 = s_w[0][pl], w01 = s_w[1][pl], w10 = s_w[2][pl], w11 = s_w[3][pl];
        const float* src = xT + (size_t)n * HW * CIN;
        const float* r00 = src + (size_t)s_i[0][pl] * CIN;
        const float* r01 = src + (size_t)s_i[1][pl] * CIN;
        const float* r10 = src + (size_t)s_i[2][pl] * CIN;
        const float* r11 = src + (size_t)s_i[3][pl] * CIN;
#pragma unroll
        for (int j8 = 0; j8 < 4; j8++) {
            int c8 = wrp * 32 + j8 * 8;
            float a[8], b[8], c[8], d[8];
            *reinterpret_cast<float4*>(a) = *reinterpret_cast<const float4*>(r00 + c8);
            *reinterpret_cast<float4*>(a + 4) = *reinterpret_cast<const float4*>(r00 + c8 + 4);
            *reinterpret_cast<float4*>(b) = *reinterpret_cast<const float4*>(r01 + c8);
            *reinterpret_cast<float4*>(b + 4) = *reinterpret_cast<const float4*>(r01 + c8 + 4);
            *reinterpret_cast<float4*>(c) = *reinterpret_cast<const float4*>(r10 + c8);
            *reinterpret_cast<float4*>(c + 4) = *reinterpret_cast<const float4*>(r10 + c8 + 4);
            *reinterpret_cast<float4*>(d) = *reinterpret_cast<const float4*>(r11 + c8);
            *reinterpret_cast<float4*>(d + 4) = *reinterpret_cast<const float4*>(r11 + c8 + 4);
            __align__(16) __nv_bfloat16 hi[8];
            __align__(16) __nv_bfloat16 lo[8];
#pragma unroll
            for (int j = 0; j < 8; j++) {
                float v = w00 * a[j] + w01 * b[j] + w10 * c[j] + w11 * d[j];
                __nv_bfloat16 hb = __float2bfloat16(v);
                hi[j] = hb;
                lo[j] = __float2bfloat16(v - __bfloat162float(hb));
            }
            *reinterpret_cast<uint4*>(&s_hi[pl][c8]) = *reinterpret_cast<uint4*>(hi);
            *reinterpret_cast<uint4*>(&s_lo[pl][c8]) = *reinterpret_cast<uint4*>(lo);
        }
    }
    __syncthreads();

    // Writeout: 32 px x (hi 512B + lo 512B) = 2048 x 16B chunks, 8 per thread.
    __nv_bfloat16* base = colsT + (size_t)(n * HW + p0) * KPA + k * 256;
#pragma unroll
    for (int pass = 0; pass < 8; pass++) {
        int id = tid + pass * 256;
        int px = id >> 6;
        int rem = id & 63;
        int half = rem >> 5;
        int q = rem & 31;
        uint4 v = half ? *reinterpret_cast<uint4*>(&s_lo[px][q * 8])
                       : *reinterpret_cast<uint4*>(&s_hi[px][q * 8]);
        *reinterpret_cast<uint4*>(base + (size_t)px * KPA + half * 2304 + q * 8) = v;
    }
}

// ---------------------------------------------------------------------------
// Stage-3 HMMA GEMM: out[p 128][cout 256] = colsT[p][*] . wbf[cout][*]
// A chunks: kt<72 read directly; kt>=72 re-read hi chunks (kt-72).
// ---------------------------------------------------------------------------
#define ABYTES 16384            /* 128 rows * 128B */
#define BBYTES 32768            /* 256 rows * 128B */
#define STAGEB (ABYTES + BBYTES)

__global__ void __launch_bounds__(256, 1)
hmma_gemm(const __nv_bfloat16* __restrict__ colsT,
          const __nv_bfloat16* __restrict__ wbf,
          const float* __restrict__ bias, float* __restrict__ out) {
    extern __shared__ char smem[];
    const uint32_t sb = smem_u32(smem);
    const int tid = threadIdx.x;
    const int wid = tid >> 5, lane = tid & 31;
    const int wm = wid >> 2, wn = wid & 3;      // 2 x 4 warp grid
    const int p0 = blockIdx.x * 128;
    const int n = blockIdx.z;

    const char* Ag = (const char*)(colsT + (size_t)(n * HW + p0) * KPA);
    const char* Bg = (const char*)wbf;

    float acc[4][8][4];
#pragma unroll
    for (int i = 0; i < 4; i++)
#pragma unroll
        for (int j = 0; j < 8; j++)
#pragma unroll
            for (int r = 0; r < 4; r++) acc[i][j][r] = 0.f;

    auto load_chunk = [&](int kt, int buf) {
        int ktA = (kt < 72) ? kt : kt - 72;
        uint32_t dA = sb + buf * STAGEB;
        uint32_t dB = dA + ABYTES;
#pragma unroll
        for (int u = 0; u < 4; u++) {
            int idx = tid + u * 256;
            int row = idx >> 3, c = idx & 7;
            cp_async16(dA + row * 128 + ((c ^ (row & 7)) << 4),
                       Ag + (size_t)row * KROWA + ktA * 128 + c * 16);
        }
#pragma unroll
        for (int u = 0; u < 8; u++) {
            int idx = tid + u * 256;
            int row = idx >> 3, c = idx & 7;
            cp_async16(dB + row * 128 + ((c ^ (row & 7)) << 4),
                       Bg + (size_t)row * KROWW + kt * 128 + c * 16);
        }
        cp_commit();
    };

    auto compute_chunk = [&](int buf) {
        uint32_t Ab = sb + buf * STAGEB;
        uint32_t Bb = Ab + ABYTES;
        const int rbase = ((lane >> 3) & 1) * 8 + (lane & 7);
        const int chi = (lane >> 4);            // 0 or 1 (k-half select)
#pragma unroll
        for (int ks = 0; ks < 4; ks++) {
            int c = ks * 2 + chi;
            uint32_t af[4][4], bf[4][4];
#pragma unroll
            for (int i = 0; i < 4; i++) {
                int row = wm * 64 + i * 16 + rbase;
                ldsm_x4(af[i], Ab + row * 128 + ((c ^ (row & 7)) << 4));
            }
#pragma unroll
            for (int j = 0; j < 4; j++) {
                int row = wn * 64 + j * 16 + rbase;
                ldsm_x4(bf[j], Bb + row * 128 + ((c ^ (row & 7)) << 4));
            }
#pragma unroll
            for (int i = 0; i < 4; i++)
#pragma unroll
                for (int j = 0; j < 4; j++)
#pragma unroll
                    for (int s = 0; s < 2; s++)
                        mma16816(acc[i][j * 2 + s], af[i], bf[j][s], bf[j][s + 2]);
        }
    };

    load_chunk(0, 0);
    for (int kt = 0; kt < KCHUNKS; kt++) {
        int buf = kt & 1;
        if (kt + 1 < KCHUNKS) {
            load_chunk(kt + 1, buf ^ 1);
            cp_wait<1>();
        } else {
            cp_wait<0>();
        }
        __syncthreads();
        compute_chunk(buf);
        __syncthreads();
    }

    // Epilogue: bias + f32 stores (out is [n][cout][HW]; 32B sectors full)
#pragma unroll
    for (int i = 0; i < 4; i++) {
        int m = wm * 64 + i * 16 + (lane >> 2);
#pragma unroll
        for (int j = 0; j < 4; j++)
#pragma unroll
            for (int s = 0; s < 2; s++) {
                int cout = wn * 64 + j * 16 + s * 8 + (lane & 3) * 2;
                float b0 = bias[cout], b1 = bias[cout + 1];
                float* o = out + ((size_t)n * COUT + cout) * HW + p0;
                const float* a = acc[i][j * 2 + s];
                o[m]          = a[0] + b0;
                o[HW + m]     = a[1] + b1;
                o[m + 8]      = a[2] + b0;
                o[HW + m + 8] = a[3] + b1;
            }
    }
}

// ---------------------------------------------------------------------------
extern "C" void kernel_launch(void* const* d_in, const int* in_sizes, int n_in,
                              void* d_out, int out_size) {
    const float* x      = (const float*)d_in[0];
    const float* depth  = (const float*)d_in[1];
    const float* weight = (const float*)d_in[2];
    const float* bias   = (const float*)d_in[3];
    const float* off_w  = (const float*)d_in[4];
    const float* off_b  = (const float*)d_in[5];
    const float* mask_w = (const float*)d_in[6];
    const float* mask_b = (const float*)d_in[7];
    float* out = (float*)d_out;

    void *pc, *po, *pm, *pcb, *pwb, *pxt;
    cudaGetSymbolAddress(&pc, g_cols);
    cudaGetSymbolAddress(&po, g_offsets);
    cudaGetSymbolAddress(&pm, g_mask);
    cudaGetSymbolAddress(&pcb, g_colsbf);
    cudaGetSymbolAddress(&pwb, g_wbf);
    cudaGetSymbolAddress(&pxt, g_xT);
    float* cols = (float*)pc;
    float* offsets = (float*)po;
    float* maskbuf = (float*)pm;
    __nv_bfloat16* colsbf = (__nv_bfloat16*)pcb;
    __nv_bfloat16* wbf = (__nv_bfloat16*)pwb;
    float* xT = (float*)pxt;

    // Prep: weight split + x transpose (small)
    prep_w_kernel<<<COUT, 256>>>(weight, wbf);
    transpose_x<<<dim3(HW / 32, CIN / 32, NB), dim3(32, 8)>>>(x, xT);

    // Stage 1: offset conv via implicit-im2col SGEMM
    sgemm_s1<<<dim3(HW / 128, 1, NB), 256>>>(x, depth, off_w, off_b, offsets);

    // Stage 2: mask = sigmoid(deform_conv(depth, offset))
    deform_im2col_f32<<<dim3(HW / 256, DC, NB), 256>>>(depth, offsets, cols);
    sgemm_mask<<<dim3(HW / 128, 1, NB), 256>>>(mask_w, cols, mask_b, maskbuf);

    // Stage 3: modulated deformable conv via HMMA bf16 split-K GEMM
    deform_im2col_bf16_v2<<<dim3(HW / 32, 9, NB), 256>>>(xT, offsets, maskbuf, colsbf);

    static int smem_set = 0;
    if (!smem_set) {
        cudaFuncSetAttribute(hmma_gemm, cudaFuncAttributeMaxDynamicSharedMemorySize,
                             2 * STAGEB);
        smem_set = 1;
    }
    hmma_gemm<<<dim3(HW / 128, 1, NB), 256, 2 * STAGEB>>>(colsbf, wbf, bias, out);
}

// round 6
// speedup vs baseline: 1.5971x; 1.0205x over previous
#include <cuda_runtime.h>
#include <cuda_bf16.h>
#include <cstdint>
#include <math.h>

#define NB 4
#define HH 64
#define WW 64
#define HW 4096
#define CIN 256
#define DC 64
#define COUT 256
#define KPA 4608               /* A cols: [hi | lo], 2*2304 */
#define KPW 6912               /* W cols: [hi | hi | lo], 3*2304 */
#define KROWA (KPA * 2)        /* A row bytes: 9216 */
#define KROWW (KPW * 2)        /* W row bytes: 13824 */
#define KCHUNKS 108            /* KPW / 64 */

// ---------------- device scratch ----------------
__device__ float g_offsets[(size_t)NB * 18 * HW];
__device__ float g_mask[(size_t)NB * 9 * HW];
__device__ float g_xT[(size_t)NB * HW * CIN];              // x transposed [n][p][c]
__device__ __nv_bfloat16 g_colsbf[(size_t)NB * HW * KPA];  // 151 MB
__device__ __nv_bfloat16 g_wbf[(size_t)COUT * KPW];

// ---------------- PTX helpers ----------------
__device__ __forceinline__ uint32_t smem_u32(const void* p) {
    uint32_t a;
    asm("{ .reg .u64 t; cvta.to.shared.u64 t, %1; cvt.u32.u64 %0, t; }"
        : "=r"(a) : "l"(p));
    return a;
}

__device__ __forceinline__ void cp_async16(uint32_t dst, const void* src) {
    asm volatile("cp.async.cg.shared.global [%0], [%1], 16;"
                 :: "r"(dst), "l"(src) : "memory");
}
__device__ __forceinline__ void cp_commit() {
    asm volatile("cp.async.commit_group;" ::: "memory");
}
template <int N>
__device__ __forceinline__ void cp_wait() {
    asm volatile("cp.async.wait_group %0;" :: "n"(N) : "memory");
}

__device__ __forceinline__ void ldsm_x4(uint32_t (&r)[4], uint32_t addr) {
    asm volatile("ldmatrix.sync.aligned.m8n8.x4.shared.b16 {%0,%1,%2,%3}, [%4];"
                 : "=r"(r[0]), "=r"(r[1]), "=r"(r[2]), "=r"(r[3]) : "r"(addr));
}

__device__ __forceinline__ void mma16816(float (&d)[4], const uint32_t (&a)[4],
                                         uint32_t b0, uint32_t b1) {
    asm volatile(
        "mma.sync.aligned.m16n8k16.row.col.f32.bf16.bf16.f32 "
        "{%0,%1,%2,%3}, {%4,%5,%6,%7}, {%8,%9}, {%0,%1,%2,%3};"
        : "+f"(d[0]), "+f"(d[1]), "+f"(d[2]), "+f"(d[3])
        : "r"(a[0]), "r"(a[1]), "r"(a[2]), "r"(a[3]), "r"(b0), "r"(b1));
}

// ---------------------------------------------------------------------------
// x transpose: x[n][c][p] -> xT[n][p][c]
// ---------------------------------------------------------------------------
__global__ void transpose_x(const float* __restrict__ x, float* __restrict__ xT) {
    __shared__ float t[32][33];
    int n = blockIdx.z;
    int p0 = blockIdx.x * 32, c0 = blockIdx.y * 32;
    int tx = threadIdx.x, ty = threadIdx.y;
#pragma unroll
    for (int j = 0; j < 32; j += 8)
        t[ty + j][tx] = x[((size_t)n * CIN + c0 + ty + j) * HW + p0 + tx];
    __syncthreads();
#pragma unroll
    for (int j = 0; j < 32; j += 8)
        xT[((size_t)n * HW + p0 + ty + j) * CIN + c0 + tx] = t[tx][ty + j];
}

// ---------------------------------------------------------------------------
// Weight prep: W[cout][c][k] f32 -> wbf[cout][pass*2304 + k*256 + c]
// pass0=hi, pass1=hi, pass2=lo
// ---------------------------------------------------------------------------
__global__ void prep_w_kernel(const float* __restrict__ w,
                              __nv_bfloat16* __restrict__ wbf) {
    int cout = blockIdx.x;
    int c = threadIdx.x;
#pragma unroll
    for (int k = 0; k < 9; k++) {
        float v = w[((size_t)cout * 256 + c) * 9 + k];
        __nv_bfloat16 hb = __float2bfloat16(v);
        __nv_bfloat16 lb = __float2bfloat16(v - __bfloat162float(hb));
        size_t b = (size_t)cout * KPW + k * 256 + c;
        wbf[b] = hb;
        wbf[b + 2304] = hb;
        wbf[b + 4608] = lb;
    }
}

// ---------------------------------------------------------------------------
// Stage-1 GEMM, IMPLICIT im2col of cat(x, depth). M=18, K=2880, split-K x4.
// Each slice covers 720 K (= 80 channels). atomicAdd epilogue into C.
// grid (HW/128, 4 slices, NB), 256 threads.
// ---------------------------------------------------------------------------
__global__ void __launch_bounds__(256, 2)
sgemm_s1(const float* __restrict__ x, const float* __restrict__ depth,
         const float* __restrict__ A, const float* __restrict__ bias,
         float* __restrict__ C) {
    const int M = 18, K = 2880, KSLICE = 720;
    __shared__ float As[16][36];
    __shared__ float Bs[16][128];
    const int tid = threadIdx.x;
    const int n0 = blockIdx.x * 128;
    const int slice = blockIdx.y;
    const int n = blockIdx.z;
    const int tx = tid % 16, ty = tid / 16;
    const float* xn = x + (size_t)n * CIN * HW;
    const float* dn = depth + (size_t)n * DC * HW;

    float acc[2][8];
#pragma unroll
    for (int i = 0; i < 2; i++)
#pragma unroll
        for (int j = 0; j < 8; j++) acc[i][j] = 0.f;

    float4 ra;
    float rbv[8];

    // Per-slot incremental K-decomposition state (gk = c*9 + kk)
    int cS[8], kkS[8], hS[8], wS[8];
#pragma unroll
    for (int t = 0; t < 8; t++) {
        int idx = tid + t * 256;
        int row = idx >> 7, col = idx & 127;
        cS[t] = slice * 80 + row / 9;
        kkS[t] = row % 9;
        int p = n0 + col;
        hS[t] = p >> 6;
        wS[t] = p & 63;
    }

    auto loadA = [&](int k0) {
        if (tid < 128) {
            int row = tid / 4, kq = tid % 4;
            ra = (row < M) ? *reinterpret_cast<const float4*>(
                                 &A[(size_t)row * K + slice * KSLICE + k0 + kq * 4])
                           : make_float4(0.f, 0.f, 0.f, 0.f);
        }
    };
    auto loadB = [&]() {
#pragma unroll
        for (int t = 0; t < 8; t++) {
            int c = cS[t], kk = kkS[t];
            int kh = kk / 3, kw = kk - 3 * kh;
            int iy = hS[t] + kh - 1, ix = wS[t] + kw - 1;
            const float* s = (c < CIN) ? xn + (size_t)c * HW
                                       : dn + (size_t)(c - CIN) * HW;
            rbv[t] = (iy >= 0 && iy < HH && ix >= 0 && ix < WW) ? s[iy * WW + ix] : 0.f;
            kk += 16;
            if (kk >= 9) { kk -= 9; c++; }
            if (kk >= 9) { kk -= 9; c++; }
            cS[t] = c; kkS[t] = kk;
        }
    };
    auto storeA = [&]() {
        if (tid < 128) {
            int row = tid / 4, kq = tid % 4;
            As[kq * 4 + 0][row] = ra.x;
            As[kq * 4 + 1][row] = ra.y;
            As[kq * 4 + 2][row] = ra.z;
            As[kq * 4 + 3][row] = ra.w;
        }
    };
    auto storeB = [&]() {
#pragma unroll
        for (int t = 0; t < 8; t++) {
            int idx = tid + t * 256;
            Bs[idx >> 7][idx & 127] = rbv[t];
        }
    };

    loadA(0); loadB();
    storeA(); storeB();
    __syncthreads();

    const int ktiles = KSLICE / 16;   // 45
    for (int t = 0; t < ktiles; t++) {
        if (t + 1 < ktiles) { loadA((t + 1) * 16); loadB(); }
#pragma unroll
        for (int kk = 0; kk < 16; kk++) {
            float a0 = As[kk][ty * 2], a1 = As[kk][ty * 2 + 1];
            float b[8];
#pragma unroll
            for (int j = 0; j < 8; j++) b[j] = Bs[kk][tx * 8 + j];
#pragma unroll
            for (int j = 0; j < 8; j++) { acc[0][j] += a0 * b[j]; acc[1][j] += a1 * b[j]; }
        }
        __syncthreads();
        if (t + 1 < ktiles) { storeA(); storeB(); __syncthreads(); }
    }

#pragma unroll
    for (int i = 0; i < 2; i++) {
        int gm = ty * 2 + i;
        if (gm < M) {
            float bi = (slice == 0) ? bias[gm] : 0.f;
            float* cp = &C[((size_t)n * M + gm) * HW + n0 + tx * 8];
#pragma unroll
            for (int j = 0; j < 8; j++)
                atomicAdd(cp + j, acc[i][j] + bi);
        }
    }
}

// ---------------------------------------------------------------------------
// Stage-2 FUSED: mask = sigmoid(deform_conv(depth, offset, mask_w) + mask_b)
// One warp per pixel; lanes split the 576 (c,k) pairs (18 each).
// Weights staged in smem as ws[pair][m] (stride 9 -> conflict-free).
// grid (HW/8, NB), 256 threads (8 warps = 8 pixels).
// ---------------------------------------------------------------------------
__global__ void __launch_bounds__(256)
fused_mask(const float* __restrict__ depth, const float* __restrict__ offs,
           const float* __restrict__ mw, const float* __restrict__ mb,
           float* __restrict__ maskbuf) {
    __shared__ float ws[576][9];
    __shared__ float sbias[9];
    const int tid = threadIdx.x;
    const int n = blockIdx.y;

    for (int i = tid; i < 5184; i += 256) {
        int m = i / 576, pair = i - m * 576;
        ws[pair][m] = mw[i];
    }
    if (tid < 9) sbias[tid] = mb[tid];
    __syncthreads();

    const int wid = tid >> 5, lane = tid & 31;
    const int p = blockIdx.x * 8 + wid;
    const int h = p >> 6, w = p & 63;
    const float* dn = depth + (size_t)n * DC * HW;
    const float* offn = offs + (size_t)n * 18 * HW;

    float acc[9];
#pragma unroll
    for (int m = 0; m < 9; m++) acc[m] = 0.f;

#pragma unroll
    for (int j = 0; j < 18; j++) {
        int pair = j * 32 + lane;
        int c = pair / 9;
        int k = pair - 9 * c;
        float dy = offn[(size_t)(2 * k) * HW + p];
        float dx = offn[(size_t)(2 * k + 1) * HW + p];
        float y = (float)(h - 1 + k / 3) + dy;
        float xx = (float)(w - 1 + k % 3) + dx;
        float y0f = floorf(y), x0f = floorf(xx);
        float ly = y - y0f, lx = xx - x0f;
        int y0 = (int)y0f, x0 = (int)x0f;
        int y1 = y0 + 1, x1 = x0 + 1;
        bool vy0 = (y0 >= 0) & (y0 < HH);
        bool vy1 = (y1 >= 0) & (y1 < HH);
        bool vx0 = (x0 >= 0) & (x0 < WW);
        bool vx1 = (x1 >= 0) & (x1 < WW);
        const float* src = dn + (size_t)c * HW;
        float v00 = (vy0 & vx0) ? src[y0 * WW + x0] : 0.f;
        float v01 = (vy0 & vx1) ? src[y0 * WW + x1] : 0.f;
        float v10 = (vy1 & vx0) ? src[y1 * WW + x0] : 0.f;
        float v11 = (vy1 & vx1) ? src[y1 * WW + x1] : 0.f;
        float val = v00 * (1.f - ly) * (1.f - lx) + v01 * (1.f - ly) * lx
                  + v10 * ly * (1.f - lx) + v11 * ly * lx;
#pragma unroll
        for (int m = 0; m < 9; m++) acc[m] += ws[pair][m] * val;
    }

#pragma unroll
    for (int m = 0; m < 9; m++) {
#pragma unroll
        for (int off = 16; off > 0; off >>= 1)
            acc[m] += __shfl_xor_sync(0xFFFFFFFFu, acc[m], off);
    }
    if (lane == 0) {
        float* mp = maskbuf + (size_t)n * 9 * HW + p;
#pragma unroll
        for (int m = 0; m < 9; m++) {
            float v = acc[m] + sbias[m];
            mp[(size_t)m * HW] = 1.f / (1.f + expf(-v));
        }
    }
}

// ---------------------------------------------------------------------------
// Stage-3 deformable im2col v2: xT gathers (vectorized) + coalesced stores.
// Output: colsT[n][p][half*2304 + k*256 + c], half0=hi, half1=lo.
// grid (HW/32, 9, NB), 256 threads.
// ---------------------------------------------------------------------------
__global__ void __launch_bounds__(256)
deform_im2col_bf16_v2(const float* __restrict__ xT, const float* __restrict__ offs,
                      const float* __restrict__ mask,
                      __nv_bfloat16* __restrict__ colsT) {
    __shared__ float s_w[4][32];
    __shared__ int s_i[4][32];
    __shared__ __align__(16) __nv_bfloat16 s_hi[32][264];
    __shared__ __align__(16) __nv_bfloat16 s_lo[32][264];

    const int k = blockIdx.y;
    const int n = blockIdx.z;
    const int p0 = blockIdx.x * 32;
    const int tid = threadIdx.x;
    const int lane = tid & 31, wrp = tid >> 5;

    if (tid < 32) {
        int p = p0 + tid;
        int h = p >> 6, w = p & 63;
        const float* offn = offs + (size_t)n * 18 * HW;
        float dy = offn[(size_t)(2 * k) * HW + p];
        float dx = offn[(size_t)(2 * k + 1) * HW + p];
        float mk = mask[((size_t)n * 9 + k) * HW + p];
        float y = (float)(h - 1 + k / 3) + dy;
        float xx = (float)(w - 1 + k % 3) + dx;
        float y0f = floorf(y), x0f = floorf(xx);
        float ly = y - y0f, lx = xx - x0f;
        int y0 = (int)y0f, x0 = (int)x0f;
        int y1 = y0 + 1, x1 = x0 + 1;
        bool vy0 = (y0 >= 0) & (y0 < HH);
        bool vy1 = (y1 >= 0) & (y1 < HH);
        bool vx0 = (x0 >= 0) & (x0 < WW);
        bool vx1 = (x1 >= 0) & (x1 < WW);
        s_w[0][tid] = (vy0 & vx0) ? (1.f - ly) * (1.f - lx) * mk : 0.f;
        s_w[1][tid] = (vy0 & vx1) ? (1.f - ly) * lx * mk : 0.f;
        s_w[2][tid] = (vy1 & vx0) ? ly * (1.f - lx) * mk : 0.f;
        s_w[3][tid] = (vy1 & vx1) ? ly * lx * mk : 0.f;
        s_i[0][tid] = (vy0 & vx0) ? y0 * WW + x0 : 0;
        s_i[1][tid] = (vy0 & vx1) ? y0 * WW + x1 : 0;
        s_i[2][tid] = (vy1 & vx0) ? y1 * WW + x0 : 0;
        s_i[3][tid] = (vy1 & vx1) ? y1 * WW + x1 : 0;
    }
    __syncthreads();

    {
        const int pl = lane;
        const float w00 = s_w[0][pl], w01 = s_w[1][pl], w10 = s_w[2][pl], w11 = s_w[3][pl];
        const float* src = xT + (size_t)n * HW * CIN;
        const float* r00 = src + (size_t)s_i[0][pl] * CIN;
        const float* r01 = src + (size_t)s_i[1][pl] * CIN;
        const float* r10 = src + (size_t)s_i[2][pl] * CIN;
        const float* r11 = src + (size_t)s_i[3][pl] * CIN;
#pragma unroll
        for (int j8 = 0; j8 < 4; j8++) {
            int c8 = wrp * 32 + j8 * 8;
            float a[8], b[8], c[8], d[8];
            *reinterpret_cast<float4*>(a) = *reinterpret_cast<const float4*>(r00 + c8);
            *reinterpret_cast<float4*>(a + 4) = *reinterpret_cast<const float4*>(r00 + c8 + 4);
            *reinterpret_cast<float4*>(b) = *reinterpret_cast<const float4*>(r01 + c8);
            *reinterpret_cast<float4*>(b + 4) = *reinterpret_cast<const float4*>(r01 + c8 + 4);
            *reinterpret_cast<float4*>(c) = *reinterpret_cast<const float4*>(r10 + c8);
            *reinterpret_cast<float4*>(c + 4) = *reinterpret_cast<const float4*>(r10 + c8 + 4);
            *reinterpret_cast<float4*>(d) = *reinterpret_cast<const float4*>(r11 + c8);
            *reinterpret_cast<float4*>(d + 4) = *reinterpret_cast<const float4*>(r11 + c8 + 4);
            __align__(16) __nv_bfloat16 hi[8];
            __align__(16) __nv_bfloat16 lo[8];
#pragma unroll
            for (int j = 0; j < 8; j++) {
                float v = w00 * a[j] + w01 * b[j] + w10 * c[j] + w11 * d[j];
                __nv_bfloat16 hb = __float2bfloat16(v);
                hi[j] = hb;
                lo[j] = __float2bfloat16(v - __bfloat162float(hb));
            }
            *reinterpret_cast<uint4*>(&s_hi[pl][c8]) = *reinterpret_cast<uint4*>(hi);
            *reinterpret_cast<uint4*>(&s_lo[pl][c8]) = *reinterpret_cast<uint4*>(lo);
        }
    }
    __syncthreads();

    __nv_bfloat16* base = colsT + (size_t)(n * HW + p0) * KPA + k * 256;
#pragma unroll
    for (int pass = 0; pass < 8; pass++) {
        int id = tid + pass * 256;
        int px = id >> 6;
        int rem = id & 63;
        int half = rem >> 5;
        int q = rem & 31;
        uint4 v = half ? *reinterpret_cast<uint4*>(&s_lo[px][q * 8])
                       : *reinterpret_cast<uint4*>(&s_hi[px][q * 8]);
        *reinterpret_cast<uint4*>(base + (size_t)px * KPA + half * 2304 + q * 8) = v;
    }
}

// ---------------------------------------------------------------------------
// Stage-3 HMMA GEMM: out[p 128][cout 256] = colsT[p][*] . wbf[cout][*]
// 3-stage cp.async pipeline, single __syncthreads per chunk.
// A chunks: kt<72 read directly; kt>=72 re-read hi chunks (kt-72).
// ---------------------------------------------------------------------------
#define ABYTES 16384            /* 128 rows * 128B */
#define BBYTES 32768            /* 256 rows * 128B */
#define STAGEB (ABYTES + BBYTES)
#define NSTG 3

__global__ void __launch_bounds__(256, 1)
hmma_gemm(const __nv_bfloat16* __restrict__ colsT,
          const __nv_bfloat16* __restrict__ wbf,
          const float* __restrict__ bias, float* __restrict__ out) {
    extern __shared__ char smem[];
    const uint32_t sb = smem_u32(smem);
    const int tid = threadIdx.x;
    const int wid = tid >> 5, lane = tid & 31;
    const int wm = wid >> 2, wn = wid & 3;      // 2 x 4 warp grid
    const int p0 = blockIdx.x * 128;
    const int n = blockIdx.z;

    const char* Ag = (const char*)(colsT + (size_t)(n * HW + p0) * KPA);
    const char* Bg = (const char*)wbf;

    float acc[4][8][4];
#pragma unroll
    for (int i = 0; i < 4; i++)
#pragma unroll
        for (int j = 0; j < 8; j++)
#pragma unroll
            for (int r = 0; r < 4; r++) acc[i][j][r] = 0.f;

    auto load_chunk = [&](int kt, int buf) {
        int ktA = (kt < 72) ? kt : kt - 72;
        uint32_t dA = sb + buf * STAGEB;
        uint32_t dB = dA + ABYTES;
#pragma unroll
        for (int u = 0; u < 4; u++) {
            int idx = tid + u * 256;
            int row = idx >> 3, c = idx & 7;
            cp_async16(dA + row * 128 + ((c ^ (row & 7)) << 4),
                       Ag + (size_t)row * KROWA + ktA * 128 + c * 16);
        }
#pragma unroll
        for (int u = 0; u < 8; u++) {
            int idx = tid + u * 256;
            int row = idx >> 3, c = idx & 7;
            cp_async16(dB + row * 128 + ((c ^ (row & 7)) << 4),
                       Bg + (size_t)row * KROWW + kt * 128 + c * 16);
        }
        cp_commit();
    };

    auto compute_chunk = [&](int buf) {
        uint32_t Ab = sb + buf * STAGEB;
        uint32_t Bb = Ab + ABYTES;
        const int rbase = ((lane >> 3) & 1) * 8 + (lane & 7);
        const int chi = (lane >> 4);
#pragma unroll
        for (int ks = 0; ks < 4; ks++) {
            int c = ks * 2 + chi;
            uint32_t af[4][4], bf[4][4];
#pragma unroll
            for (int i = 0; i < 4; i++) {
                int row = wm * 64 + i * 16 + rbase;
                ldsm_x4(af[i], Ab + row * 128 + ((c ^ (row & 7)) << 4));
            }
#pragma unroll
            for (int j = 0; j < 4; j++) {
                int row = wn * 64 + j * 16 + rbase;
                ldsm_x4(bf[j], Bb + row * 128 + ((c ^ (row & 7)) << 4));
            }
#pragma unroll
            for (int i = 0; i < 4; i++)
#pragma unroll
                for (int j = 0; j < 4; j++)
#pragma unroll
                    for (int s = 0; s < 2; s++)
                        mma16816(acc[i][j * 2 + s], af[i], bf[j][s], bf[j][s + 2]);
        }
    };

    load_chunk(0, 0);
    load_chunk(1, 1);
    for (int kt = 0; kt < KCHUNKS; kt++) {
        int buf = kt % NSTG;
        if (kt + 1 < KCHUNKS) cp_wait<1>(); else cp_wait<0>();
        __syncthreads();
        if (kt + 2 < KCHUNKS) load_chunk(kt + 2, (kt + 2) % NSTG);
        compute_chunk(buf);
    }

    // Epilogue: bias + f32 stores (out is [n][cout][HW])
#pragma unroll
    for (int i = 0; i < 4; i++) {
        int m = wm * 64 + i * 16 + (lane >> 2);
#pragma unroll
        for (int j = 0; j < 4; j++)
#pragma unroll
            for (int s = 0; s < 2; s++) {
                int cout = wn * 64 + j * 16 + s * 8 + (lane & 3) * 2;
                float b0 = bias[cout], b1 = bias[cout + 1];
                float* o = out + ((size_t)n * COUT + cout) * HW + p0;
                const float* a = acc[i][j * 2 + s];
                o[m]          = a[0] + b0;
                o[HW + m]     = a[1] + b1;
                o[m + 8]      = a[2] + b0;
                o[HW + m + 8] = a[3] + b1;
            }
    }
}

// ---------------------------------------------------------------------------
extern "C" void kernel_launch(void* const* d_in, const int* in_sizes, int n_in,
                              void* d_out, int out_size) {
    const float* x      = (const float*)d_in[0];
    const float* depth  = (const float*)d_in[1];
    const float* weight = (const float*)d_in[2];
    const float* bias   = (const float*)d_in[3];
    const float* off_w  = (const float*)d_in[4];
    const float* off_b  = (const float*)d_in[5];
    const float* mask_w = (const float*)d_in[6];
    const float* mask_b = (const float*)d_in[7];
    float* out = (float*)d_out;

    void *po, *pm, *pcb, *pwb, *pxt;
    cudaGetSymbolAddress(&po, g_offsets);
    cudaGetSymbolAddress(&pm, g_mask);
    cudaGetSymbolAddress(&pcb, g_colsbf);
    cudaGetSymbolAddress(&pwb, g_wbf);
    cudaGetSymbolAddress(&pxt, g_xT);
    float* offsets = (float*)po;
    float* maskbuf = (float*)pm;
    __nv_bfloat16* colsbf = (__nv_bfloat16*)pcb;
    __nv_bfloat16* wbf = (__nv_bfloat16*)pwb;
    float* xT = (float*)pxt;

    // Prep: zero split-K accumulator, weight split, x transpose
    cudaMemsetAsync(offsets, 0, (size_t)NB * 18 * HW * sizeof(float), 0);
    prep_w_kernel<<<COUT, 256>>>(weight, wbf);
    transpose_x<<<dim3(HW / 32, CIN / 32, NB), dim3(32, 8)>>>(x, xT);

    // Stage 1: offset conv via implicit-im2col split-K SGEMM
    sgemm_s1<<<dim3(HW / 128, 4, NB), 256>>>(x, depth, off_w, off_b, offsets);

    // Stage 2: fused mask = sigmoid(deform_conv(depth, offset))
    fused_mask<<<dim3(HW / 8, NB), 256>>>(depth, offsets, mask_w, mask_b, maskbuf);

    // Stage 3: modulated deformable conv via HMMA bf16 split-K GEMM
    deform_im2col_bf16_v2<<<dim3(HW / 32, 9, NB), 256>>>(xT, offsets, maskbuf, colsbf);

    static int smem_set = 0;
    if (!smem_set) {
        cudaFuncSetAttribute(hmma_gemm, cudaFuncAttributeMaxDynamicSharedMemorySize,
                             NSTG * STAGEB);
        smem_set = 1;
    }
    hmma_gemm<<<dim3(HW / 128, 1, NB), 256, NSTG * STAGEB>>>(colsbf, wbf, bias, out);
}

// round 7
// speedup vs baseline: 1.7184x; 1.0760x over previous
#include <cuda_runtime.h>
#include <cuda_bf16.h>
#include <cstdint>
#include <math.h>

#define NB 4
#define HH 64
#define WW 64
#define HW 4096
#define CIN 256
#define DC 64
#define COUT 256
#define KPA 4608               /* A cols: [hi | lo], 2*2304 */
#define KPW 6912               /* W cols: [hi | hi | lo], 3*2304 */
#define KROWA (KPA * 2)        /* A row bytes: 9216 */
#define KROWW (KPW * 2)        /* W row bytes: 13824 */
#define KCHUNKS 108            /* KPW / 64 */

// ---------------- device scratch ----------------
__device__ float g_offsets[(size_t)NB * 18 * HW];
__device__ float g_mask[(size_t)NB * 9 * HW];
__device__ float g_xT[(size_t)NB * HW * CIN];              // x transposed [n][p][c]
__device__ float g_dT[(size_t)NB * HW * DC];               // depth transposed [n][p][c]
__device__ __nv_bfloat16 g_colsbf[(size_t)NB * HW * KPA];  // 151 MB
__device__ __nv_bfloat16 g_wbf[(size_t)COUT * KPW];

// ---------------- PTX helpers ----------------
__device__ __forceinline__ uint32_t smem_u32(const void* p) {
    uint32_t a;
    asm("{ .reg .u64 t; cvta.to.shared.u64 t, %1; cvt.u32.u64 %0, t; }"
        : "=r"(a) : "l"(p));
    return a;
}

__device__ __forceinline__ void cp_async16(uint32_t dst, const void* src) {
    asm volatile("cp.async.cg.shared.global [%0], [%1], 16;"
                 :: "r"(dst), "l"(src) : "memory");
}
__device__ __forceinline__ void cp_commit() {
    asm volatile("cp.async.commit_group;" ::: "memory");
}
template <int N>
__device__ __forceinline__ void cp_wait() {
    asm volatile("cp.async.wait_group %0;" :: "n"(N) : "memory");
}

__device__ __forceinline__ void ldsm_x4(uint32_t (&r)[4], uint32_t addr) {
    asm volatile("ldmatrix.sync.aligned.m8n8.x4.shared.b16 {%0,%1,%2,%3}, [%4];"
                 : "=r"(r[0]), "=r"(r[1]), "=r"(r[2]), "=r"(r[3]) : "r"(addr));
}

__device__ __forceinline__ void mma16816(float (&d)[4], const uint32_t (&a)[4],
                                         uint32_t b0, uint32_t b1) {
    asm volatile(
        "mma.sync.aligned.m16n8k16.row.col.f32.bf16.bf16.f32 "
        "{%0,%1,%2,%3}, {%4,%5,%6,%7}, {%8,%9}, {%0,%1,%2,%3};"
        : "+f"(d[0]), "+f"(d[1]), "+f"(d[2]), "+f"(d[3])
        : "r"(a[0]), "r"(a[1]), "r"(a[2]), "r"(a[3]), "r"(b0), "r"(b1));
}

// ---------------------------------------------------------------------------
// Generic transpose: src[n][c][p] -> dst[n][p][c]   (C = #channels)
// grid (HW/32, C/32, NB), block (32, 8)
// ---------------------------------------------------------------------------
__global__ void transpose_cp(const float* __restrict__ src, float* __restrict__ dst,
                             int C) {
    __shared__ float t[32][33];
    int n = blockIdx.z;
    int p0 = blockIdx.x * 32, c0 = blockIdx.y * 32;
    int tx = threadIdx.x, ty = threadIdx.y;
#pragma unroll
    for (int j = 0; j < 32; j += 8)
        t[ty + j][tx] = src[((size_t)n * C + c0 + ty + j) * HW + p0 + tx];
    __syncthreads();
#pragma unroll
    for (int j = 0; j < 32; j += 8)
        dst[((size_t)n * HW + p0 + ty + j) * C + c0 + tx] = t[tx][ty + j];
}

// ---------------------------------------------------------------------------
// Weight prep: W[cout][c][k] f32 -> wbf[cout][pass*2304 + k*256 + c]
// pass0=hi, pass1=hi, pass2=lo
// ---------------------------------------------------------------------------
__global__ void prep_w_kernel(const float* __restrict__ w,
                              __nv_bfloat16* __restrict__ wbf) {
    int cout = blockIdx.x;
    int c = threadIdx.x;
#pragma unroll
    for (int k = 0; k < 9; k++) {
        float v = w[((size_t)cout * 256 + c) * 9 + k];
        __nv_bfloat16 hb = __float2bfloat16(v);
        __nv_bfloat16 lb = __float2bfloat16(v - __bfloat162float(hb));
        size_t b = (size_t)cout * KPW + k * 256 + c;
        wbf[b] = hb;
        wbf[b + 2304] = hb;
        wbf[b + 4608] = lb;
    }
}

// ---------------------------------------------------------------------------
// Stage-1 GEMM, IMPLICIT im2col of cat(x, depth). M=18, K=2880, split-K x4.
// ---------------------------------------------------------------------------
__global__ void __launch_bounds__(256, 2)
sgemm_s1(const float* __restrict__ x, const float* __restrict__ depth,
         const float* __restrict__ A, const float* __restrict__ bias,
         float* __restrict__ C) {
    const int M = 18, K = 2880, KSLICE = 720;
    __shared__ float As[16][36];
    __shared__ float Bs[16][128];
    const int tid = threadIdx.x;
    const int n0 = blockIdx.x * 128;
    const int slice = blockIdx.y;
    const int n = blockIdx.z;
    const int tx = tid % 16, ty = tid / 16;
    const float* xn = x + (size_t)n * CIN * HW;
    const float* dn = depth + (size_t)n * DC * HW;

    float acc[2][8];
#pragma unroll
    for (int i = 0; i < 2; i++)
#pragma unroll
        for (int j = 0; j < 8; j++) acc[i][j] = 0.f;

    float4 ra;
    float rbv[8];

    int cS[8], kkS[8], hS[8], wS[8];
#pragma unroll
    for (int t = 0; t < 8; t++) {
        int idx = tid + t * 256;
        int row = idx >> 7, col = idx & 127;
        cS[t] = slice * 80 + row / 9;
        kkS[t] = row % 9;
        int p = n0 + col;
        hS[t] = p >> 6;
        wS[t] = p & 63;
    }

    auto loadA = [&](int k0) {
        if (tid < 128) {
            int row = tid / 4, kq = tid % 4;
            ra = (row < M) ? *reinterpret_cast<const float4*>(
                                 &A[(size_t)row * K + slice * KSLICE + k0 + kq * 4])
                           : make_float4(0.f, 0.f, 0.f, 0.f);
        }
    };
    auto loadB = [&]() {
#pragma unroll
        for (int t = 0; t < 8; t++) {
            int c = cS[t], kk = kkS[t];
            int kh = kk / 3, kw = kk - 3 * kh;
            int iy = hS[t] + kh - 1, ix = wS[t] + kw - 1;
            const float* s = (c < CIN) ? xn + (size_t)c * HW
                                       : dn + (size_t)(c - CIN) * HW;
            rbv[t] = (iy >= 0 && iy < HH && ix >= 0 && ix < WW) ? s[iy * WW + ix] : 0.f;
            kk += 16;
            if (kk >= 9) { kk -= 9; c++; }
            if (kk >= 9) { kk -= 9; c++; }
            cS[t] = c; kkS[t] = kk;
        }
    };
    auto storeA = [&]() {
        if (tid < 128) {
            int row = tid / 4, kq = tid % 4;
            As[kq * 4 + 0][row] = ra.x;
            As[kq * 4 + 1][row] = ra.y;
            As[kq * 4 + 2][row] = ra.z;
            As[kq * 4 + 3][row] = ra.w;
        }
    };
    auto storeB = [&]() {
#pragma unroll
        for (int t = 0; t < 8; t++) {
            int idx = tid + t * 256;
            Bs[idx >> 7][idx & 127] = rbv[t];
        }
    };

    loadA(0); loadB();
    storeA(); storeB();
    __syncthreads();

    const int ktiles = KSLICE / 16;
    for (int t = 0; t < ktiles; t++) {
        if (t + 1 < ktiles) { loadA((t + 1) * 16); loadB(); }
#pragma unroll
        for (int kk = 0; kk < 16; kk++) {
            float a0 = As[kk][ty * 2], a1 = As[kk][ty * 2 + 1];
            float b[8];
#pragma unroll
            for (int j = 0; j < 8; j++) b[j] = Bs[kk][tx * 8 + j];
#pragma unroll
            for (int j = 0; j < 8; j++) { acc[0][j] += a0 * b[j]; acc[1][j] += a1 * b[j]; }
        }
        __syncthreads();
        if (t + 1 < ktiles) { storeA(); storeB(); __syncthreads(); }
    }

#pragma unroll
    for (int i = 0; i < 2; i++) {
        int gm = ty * 2 + i;
        if (gm < M) {
            float bi = (slice == 0) ? bias[gm] : 0.f;
            float* cp = &C[((size_t)n * M + gm) * HW + n0 + tx * 8];
#pragma unroll
            for (int j = 0; j < 8; j++)
                atomicAdd(cp + j, acc[i][j] + bi);
        }
    }
}

// ---------------------------------------------------------------------------
// Stage-2 FUSED v2: mask = sigmoid(deform_conv(depthT, offset) + mb)
// Warp = pixel. Loop k (9 taps): offsets broadcast; lanes = channels,
// coalesced float2 gathers from depthT[p][64]. Weights smem ws[k][m][c].
// grid (HW/8, NB), 256 threads.
// ---------------------------------------------------------------------------
__global__ void __launch_bounds__(256)
fused_mask(const float* __restrict__ depthT, const float* __restrict__ offs,
           const float* __restrict__ mw, const float* __restrict__ mb,
           float* __restrict__ maskbuf) {
    __shared__ float ws[9][9][64];     // [k][m][c]
    __shared__ float sbias[9];
    const int tid = threadIdx.x;
    const int n = blockIdx.y;

    // mw layout: [m][c][kh][kw] -> ws[k][m][c]
    for (int i = tid; i < 5184; i += 256) {
        int m = i / 576;
        int rem = i - m * 576;
        int c = rem / 9;
        int k = rem - 9 * c;
        ws[k][m][c] = mw[i];
    }
    if (tid < 9) sbias[tid] = mb[tid];
    __syncthreads();

    const int wid = tid >> 5, lane = tid & 31;
    const int p = blockIdx.x * 8 + wid;
    const int h = p >> 6, w = p & 63;
    const float* dn = depthT + (size_t)n * HW * DC;
    const float* offn = offs + (size_t)n * 18 * HW;

    float acc[9];
#pragma unroll
    for (int m = 0; m < 9; m++) acc[m] = 0.f;

#pragma unroll
    for (int k = 0; k < 9; k++) {
        float dy = offn[(size_t)(2 * k) * HW + p];
        float dx = offn[(size_t)(2 * k + 1) * HW + p];
        float y = (float)(h - 1 + k / 3) + dy;
        float xx = (float)(w - 1 + k % 3) + dx;
        float y0f = floorf(y), x0f = floorf(xx);
        float ly = y - y0f, lx = xx - x0f;
        int y0 = (int)y0f, x0 = (int)x0f;
        int y1 = y0 + 1, x1 = x0 + 1;
        bool vy0 = (y0 >= 0) & (y0 < HH);
        bool vy1 = (y1 >= 0) & (y1 < HH);
        bool vx0 = (x0 >= 0) & (x0 < WW);
        bool vx1 = (x1 >= 0) & (x1 < WW);
        float w00 = (vy0 & vx0) ? (1.f - ly) * (1.f - lx) : 0.f;
        float w01 = (vy0 & vx1) ? (1.f - ly) * lx : 0.f;
        float w10 = (vy1 & vx0) ? ly * (1.f - lx) : 0.f;
        float w11 = (vy1 & vx1) ? ly * lx : 0.f;
        int i00 = (vy0 & vx0) ? y0 * WW + x0 : 0;
        int i01 = (vy0 & vx1) ? y0 * WW + x1 : 0;
        int i10 = (vy1 & vx0) ? y1 * WW + x0 : 0;
        int i11 = (vy1 & vx1) ? y1 * WW + x1 : 0;
        int cc = lane * 2;
        float2 a = *reinterpret_cast<const float2*>(dn + (size_t)i00 * DC + cc);
        float2 b = *reinterpret_cast<const float2*>(dn + (size_t)i01 * DC + cc);
        float2 cv = *reinterpret_cast<const float2*>(dn + (size_t)i10 * DC + cc);
        float2 d = *reinterpret_cast<const float2*>(dn + (size_t)i11 * DC + cc);
        float v0 = w00 * a.x + w01 * b.x + w10 * cv.x + w11 * d.x;
        float v1 = w00 * a.y + w01 * b.y + w10 * cv.y + w11 * d.y;
#pragma unroll
        for (int m = 0; m < 9; m++) {
            float2 wv = *reinterpret_cast<const float2*>(&ws[k][m][cc]);
            acc[m] += wv.x * v0 + wv.y * v1;
        }
    }

#pragma unroll
    for (int m = 0; m < 9; m++) {
#pragma unroll
        for (int off = 16; off > 0; off >>= 1)
            acc[m] += __shfl_xor_sync(0xFFFFFFFFu, acc[m], off);
    }
    if (lane == 0) {
        float* mp = maskbuf + (size_t)n * 9 * HW + p;
#pragma unroll
        for (int m = 0; m < 9; m++) {
            float v = acc[m] + sbias[m];
            mp[(size_t)m * HW] = 1.f / (1.f + expf(-v));
        }
    }
}

// ---------------------------------------------------------------------------
// Stage-3 deformable im2col v2: xT gathers (vectorized) + coalesced stores.
// Output: colsT[n][p][half*2304 + k*256 + c], half0=hi, half1=lo.
// grid (HW/32, 9, NB), 256 threads.
// ---------------------------------------------------------------------------
__global__ void __launch_bounds__(256)
deform_im2col_bf16_v2(const float* __restrict__ xT, const float* __restrict__ offs,
                      const float* __restrict__ mask,
                      __nv_bfloat16* __restrict__ colsT) {
    __shared__ float s_w[4][32];
    __shared__ int s_i[4][32];
    __shared__ __align__(16) __nv_bfloat16 s_hi[32][264];
    __shared__ __align__(16) __nv_bfloat16 s_lo[32][264];

    const int k = blockIdx.y;
    const int n = blockIdx.z;
    const int p0 = blockIdx.x * 32;
    const int tid = threadIdx.x;
    const int lane = tid & 31, wrp = tid >> 5;

    if (tid < 32) {
        int p = p0 + tid;
        int h = p >> 6, w = p & 63;
        const float* offn = offs + (size_t)n * 18 * HW;
        float dy = offn[(size_t)(2 * k) * HW + p];
        float dx = offn[(size_t)(2 * k + 1) * HW + p];
        float mk = mask[((size_t)n * 9 + k) * HW + p];
        float y = (float)(h - 1 + k / 3) + dy;
        float xx = (float)(w - 1 + k % 3) + dx;
        float y0f = floorf(y), x0f = floorf(xx);
        float ly = y - y0f, lx = xx - x0f;
        int y0 = (int)y0f, x0 = (int)x0f;
        int y1 = y0 + 1, x1 = x0 + 1;
        bool vy0 = (y0 >= 0) & (y0 < HH);
        bool vy1 = (y1 >= 0) & (y1 < HH);
        bool vx0 = (x0 >= 0) & (x0 < WW);
        bool vx1 = (x1 >= 0) & (x1 < WW);
        s_w[0][tid] = (vy0 & vx0) ? (1.f - ly) * (1.f - lx) * mk : 0.f;
        s_w[1][tid] = (vy0 & vx1) ? (1.f - ly) * lx * mk : 0.f;
        s_w[2][tid] = (vy1 & vx0) ? ly * (1.f - lx) * mk : 0.f;
        s_w[3][tid] = (vy1 & vx1) ? ly * lx * mk : 0.f;
        s_i[0][tid] = (vy0 & vx0) ? y0 * WW + x0 : 0;
        s_i[1][tid] = (vy0 & vx1) ? y0 * WW + x1 : 0;
        s_i[2][tid] = (vy1 & vx0) ? y1 * WW + x0 : 0;
        s_i[3][tid] = (vy1 & vx1) ? y1 * WW + x1 : 0;
    }
    __syncthreads();

    {
        const int pl = lane;
        const float w00 = s_w[0][pl], w01 = s_w[1][pl], w10 = s_w[2][pl], w11 = s_w[3][pl];
        const float* src = xT + (size_t)n * HW * CIN;
        const float* r00 = src + (size_t)s_i[0][pl] * CIN;
        const float* r01 = src + (size_t)s_i[1][pl] * CIN;
        const float* r10 = src + (size_t)s_i[2][pl] * CIN;
        const float* r11 = src + (size_t)s_i[3][pl] * CIN;
#pragma unroll
        for (int j8 = 0; j8 < 4; j8++) {
            int c8 = wrp * 32 + j8 * 8;
            float a[8], b[8], c[8], d[8];
            *reinterpret_cast<float4*>(a) = *reinterpret_cast<const float4*>(r00 + c8);
            *reinterpret_cast<float4*>(a + 4) = *reinterpret_cast<const float4*>(r00 + c8 + 4);
            *reinterpret_cast<float4*>(b) = *reinterpret_cast<const float4*>(r01 + c8);
            *reinterpret_cast<float4*>(b + 4) = *reinterpret_cast<const float4*>(r01 + c8 + 4);
            *reinterpret_cast<float4*>(c) = *reinterpret_cast<const float4*>(r10 + c8);
            *reinterpret_cast<float4*>(c + 4) = *reinterpret_cast<const float4*>(r10 + c8 + 4);
            *reinterpret_cast<float4*>(d) = *reinterpret_cast<const float4*>(r11 + c8);
            *reinterpret_cast<float4*>(d + 4) = *reinterpret_cast<const float4*>(r11 + c8 + 4);
            __align__(16) __nv_bfloat16 hi[8];
            __align__(16) __nv_bfloat16 lo[8];
#pragma unroll
            for (int j = 0; j < 8; j++) {
                float v = w00 * a[j] + w01 * b[j] + w10 * c[j] + w11 * d[j];
                __nv_bfloat16 hb = __float2bfloat16(v);
                hi[j] = hb;
                lo[j] = __float2bfloat16(v - __bfloat162float(hb));
            }
            *reinterpret_cast<uint4*>(&s_hi[pl][c8]) = *reinterpret_cast<uint4*>(hi);
            *reinterpret_cast<uint4*>(&s_lo[pl][c8]) = *reinterpret_cast<uint4*>(lo);
        }
    }
    __syncthreads();

    __nv_bfloat16* base = colsT + (size_t)(n * HW + p0) * KPA + k * 256;
#pragma unroll
    for (int pass = 0; pass < 8; pass++) {
        int id = tid + pass * 256;
        int px = id >> 6;
        int rem = id & 63;
        int half = rem >> 5;
        int q = rem & 31;
        uint4 v = half ? *reinterpret_cast<uint4*>(&s_lo[px][q * 8])
                       : *reinterpret_cast<uint4*>(&s_hi[px][q * 8]);
        *reinterpret_cast<uint4*>(base + (size_t)px * KPA + half * 2304 + q * 8) = v;
    }
}

// ---------------------------------------------------------------------------
// Stage-3 HMMA GEMM: out[p 128][cout 256] = colsT[p][*] . wbf[cout][*]
// 3-stage cp.async pipeline, single __syncthreads per chunk.
// ---------------------------------------------------------------------------
#define ABYTES 16384            /* 128 rows * 128B */
#define BBYTES 32768            /* 256 rows * 128B */
#define STAGEB (ABYTES + BBYTES)
#define NSTG 3

__global__ void __launch_bounds__(256, 1)
hmma_gemm(const __nv_bfloat16* __restrict__ colsT,
          const __nv_bfloat16* __restrict__ wbf,
          const float* __restrict__ bias, float* __restrict__ out) {
    extern __shared__ char smem[];
    const uint32_t sb = smem_u32(smem);
    const int tid = threadIdx.x;
    const int wid = tid >> 5, lane = tid & 31;
    const int wm = wid >> 2, wn = wid & 3;
    const int p0 = blockIdx.x * 128;
    const int n = blockIdx.z;

    const char* Ag = (const char*)(colsT + (size_t)(n * HW + p0) * KPA);
    const char* Bg = (const char*)wbf;

    float acc[4][8][4];
#pragma unroll
    for (int i = 0; i < 4; i++)
#pragma unroll
        for (int j = 0; j < 8; j++)
#pragma unroll
            for (int r = 0; r < 4; r++) acc[i][j][r] = 0.f;

    auto load_chunk = [&](int kt, int buf) {
        int ktA = (kt < 72) ? kt : kt - 72;
        uint32_t dA = sb + buf * STAGEB;
        uint32_t dB = dA + ABYTES;
#pragma unroll
        for (int u = 0; u < 4; u++) {
            int idx = tid + u * 256;
            int row = idx >> 3, c = idx & 7;
            cp_async16(dA + row * 128 + ((c ^ (row & 7)) << 4),
                       Ag + (size_t)row * KROWA + ktA * 128 + c * 16);
        }
#pragma unroll
        for (int u = 0; u < 8; u++) {
            int idx = tid + u * 256;
            int row = idx >> 3, c = idx & 7;
            cp_async16(dB + row * 128 + ((c ^ (row & 7)) << 4),
                       Bg + (size_t)row * KROWW + kt * 128 + c * 16);
        }
        cp_commit();
    };

    auto compute_chunk = [&](int buf) {
        uint32_t Ab = sb + buf * STAGEB;
        uint32_t Bb = Ab + ABYTES;
        const int rbase = ((lane >> 3) & 1) * 8 + (lane & 7);
        const int chi = (lane >> 4);
#pragma unroll
        for (int ks = 0; ks < 4; ks++) {
            int c = ks * 2 + chi;
            uint32_t af[4][4], bf[4][4];
#pragma unroll
            for (int i = 0; i < 4; i++) {
                int row = wm * 64 + i * 16 + rbase;
                ldsm_x4(af[i], Ab + row * 128 + ((c ^ (row & 7)) << 4));
            }
#pragma unroll
            for (int j = 0; j < 4; j++) {
                int row = wn * 64 + j * 16 + rbase;
                ldsm_x4(bf[j], Bb + row * 128 + ((c ^ (row & 7)) << 4));
            }
#pragma unroll
            for (int i = 0; i < 4; i++)
#pragma unroll
                for (int j = 0; j < 4; j++)
#pragma unroll
                    for (int s = 0; s < 2; s++)
                        mma16816(acc[i][j * 2 + s], af[i], bf[j][s], bf[j][s + 2]);
        }
    };

    load_chunk(0, 0);
    load_chunk(1, 1);
    for (int kt = 0; kt < KCHUNKS; kt++) {
        int buf = kt % NSTG;
        if (kt + 1 < KCHUNKS) cp_wait<1>(); else cp_wait<0>();
        __syncthreads();
        if (kt + 2 < KCHUNKS) load_chunk(kt + 2, (kt + 2) % NSTG);
        compute_chunk(buf);
    }

#pragma unroll
    for (int i = 0; i < 4; i++) {
        int m = wm * 64 + i * 16 + (lane >> 2);
#pragma unroll
        for (int j = 0; j < 4; j++)
#pragma unroll
            for (int s = 0; s < 2; s++) {
                int cout = wn * 64 + j * 16 + s * 8 + (lane & 3) * 2;
                float b0 = bias[cout], b1 = bias[cout + 1];
                float* o = out + ((size_t)n * COUT + cout) * HW + p0;
                const float* a = acc[i][j * 2 + s];
                o[m]          = a[0] + b0;
                o[HW + m]     = a[1] + b1;
                o[m + 8]      = a[2] + b0;
                o[HW + m + 8] = a[3] + b1;
            }
    }
}

// ---------------------------------------------------------------------------
extern "C" void kernel_launch(void* const* d_in, const int* in_sizes, int n_in,
                              void* d_out, int out_size) {
    const float* x      = (const float*)d_in[0];
    const float* depth  = (const float*)d_in[1];
    const float* weight = (const float*)d_in[2];
    const float* bias   = (const float*)d_in[3];
    const float* off_w  = (const float*)d_in[4];
    const float* off_b  = (const float*)d_in[5];
    const float* mask_w = (const float*)d_in[6];
    const float* mask_b = (const float*)d_in[7];
    float* out = (float*)d_out;

    void *po, *pm, *pcb, *pwb, *pxt, *pdt;
    cudaGetSymbolAddress(&po, g_offsets);
    cudaGetSymbolAddress(&pm, g_mask);
    cudaGetSymbolAddress(&pcb, g_colsbf);
    cudaGetSymbolAddress(&pwb, g_wbf);
    cudaGetSymbolAddress(&pxt, g_xT);
    cudaGetSymbolAddress(&pdt, g_dT);
    float* offsets = (float*)po;
    float* maskbuf = (float*)pm;
    __nv_bfloat16* colsbf = (__nv_bfloat16*)pcb;
    __nv_bfloat16* wbf = (__nv_bfloat16*)pwb;
    float* xT = (float*)pxt;
    float* dT = (float*)pdt;

    // Prep: zero split-K accumulator, weight split, transposes
    cudaMemsetAsync(offsets, 0, (size_t)NB * 18 * HW * sizeof(float), 0);
    prep_w_kernel<<<COUT, 256>>>(weight, wbf);
    transpose_cp<<<dim3(HW / 32, CIN / 32, NB), dim3(32, 8)>>>(x, xT, CIN);
    transpose_cp<<<dim3(HW / 32, DC / 32, NB), dim3(32, 8)>>>(depth, dT, DC);

    // Stage 1: offset conv via implicit-im2col split-K SGEMM
    sgemm_s1<<<dim3(HW / 128, 4, NB), 256>>>(x, depth, off_w, off_b, offsets);

    // Stage 2: fused mask = sigmoid(deform_conv(depth, offset))
    fused_mask<<<dim3(HW / 8, NB), 256>>>(dT, offsets, mask_w, mask_b, maskbuf);

    // Stage 3: modulated deformable conv via HMMA bf16 split-K GEMM
    deform_im2col_bf16_v2<<<dim3(HW / 32, 9, NB), 256>>>(xT, offsets, maskbuf, colsbf);

    static int smem_set = 0;
    if (!smem_set) {
        cudaFuncSetAttribute(hmma_gemm, cudaFuncAttributeMaxDynamicSharedMemorySize,
                             NSTG * STAGEB);
        smem_set = 1;
    }
    hmma_gemm<<<dim3(HW / 128, 1, NB), 256, NSTG * STAGEB>>>(colsbf, wbf, bias, out);
}

// round 8
// speedup vs baseline: 1.7249x; 1.0038x over previous
#include <cuda_runtime.h>
#include <cuda_bf16.h>
#include <cstdint>
#include <math.h>

#define NB 4
#define HH 64
#define WW 64
#define HW 4096
#define CIN 256
#define DC 64
#define COUT 256
#define KPA 4608               /* A cols: [hi | lo], 2*2304 */
#define KPW 6912               /* W cols: [hi | hi | lo], 3*2304 */
#define KROWA (KPA * 2)        /* A row bytes: 9216 */
#define KROWW (KPW * 2)        /* W row bytes: 13824 */
#define KCHUNKS 108            /* KPW / 64 */

// ---------------- device scratch ----------------
__device__ float g_offsets[(size_t)NB * 18 * HW];
__device__ float g_mask[(size_t)NB * 9 * HW];
__device__ float g_xT[(size_t)NB * HW * CIN];              // x transposed [n][p][c]
__device__ float g_dT[(size_t)NB * HW * DC];               // depth transposed [n][p][c]
__device__ float g_wpoff[18 * 2880];                       // off_w repacked tap-major
__device__ __nv_bfloat16 g_colsbf[(size_t)NB * HW * KPA];  // 151 MB
__device__ __nv_bfloat16 g_wbf[(size_t)COUT * KPW];

// ---------------- PTX helpers ----------------
__device__ __forceinline__ uint32_t smem_u32(const void* p) {
    uint32_t a;
    asm("{ .reg .u64 t; cvta.to.shared.u64 t, %1; cvt.u32.u64 %0, t; }"
        : "=r"(a) : "l"(p));
    return a;
}

__device__ __forceinline__ void cp_async16(uint32_t dst, const void* src) {
    asm volatile("cp.async.cg.shared.global [%0], [%1], 16;"
                 :: "r"(dst), "l"(src) : "memory");
}
__device__ __forceinline__ void cp_commit() {
    asm volatile("cp.async.commit_group;" ::: "memory");
}
template <int N>
__device__ __forceinline__ void cp_wait() {
    asm volatile("cp.async.wait_group %0;" :: "n"(N) : "memory");
}

__device__ __forceinline__ void ldsm_x4(uint32_t (&r)[4], uint32_t addr) {
    asm volatile("ldmatrix.sync.aligned.m8n8.x4.shared.b16 {%0,%1,%2,%3}, [%4];"
                 : "=r"(r[0]), "=r"(r[1]), "=r"(r[2]), "=r"(r[3]) : "r"(addr));
}

__device__ __forceinline__ void mma16816(float (&d)[4], const uint32_t (&a)[4],
                                         uint32_t b0, uint32_t b1) {
    asm volatile(
        "mma.sync.aligned.m16n8k16.row.col.f32.bf16.bf16.f32 "
        "{%0,%1,%2,%3}, {%4,%5,%6,%7}, {%8,%9}, {%0,%1,%2,%3};"
        : "+f"(d[0]), "+f"(d[1]), "+f"(d[2]), "+f"(d[3])
        : "r"(a[0]), "r"(a[1]), "r"(a[2]), "r"(a[3]), "r"(b0), "r"(b1));
}

// ---------------------------------------------------------------------------
// Generic transpose: src[n][c][p] -> dst[n][p][c]
// ---------------------------------------------------------------------------
__global__ void transpose_cp(const float* __restrict__ src, float* __restrict__ dst,
                             int C) {
    __shared__ float t[32][33];
    int n = blockIdx.z;
    int p0 = blockIdx.x * 32, c0 = blockIdx.y * 32;
    int tx = threadIdx.x, ty = threadIdx.y;
#pragma unroll
    for (int j = 0; j < 32; j += 8)
        t[ty + j][tx] = src[((size_t)n * C + c0 + ty + j) * HW + p0 + tx];
    __syncthreads();
#pragma unroll
    for (int j = 0; j < 32; j += 8)
        dst[((size_t)n * HW + p0 + ty + j) * C + c0 + tx] = t[tx][ty + j];
}

// ---------------------------------------------------------------------------
// Weight preps
// ---------------------------------------------------------------------------
__global__ void prep_w_kernel(const float* __restrict__ w,
                              __nv_bfloat16* __restrict__ wbf) {
    int cout = blockIdx.x;
    int c = threadIdx.x;
#pragma unroll
    for (int k = 0; k < 9; k++) {
        float v = w[((size_t)cout * 256 + c) * 9 + k];
        __nv_bfloat16 hb = __float2bfloat16(v);
        __nv_bfloat16 lb = __float2bfloat16(v - __bfloat162float(hb));
        size_t b = (size_t)cout * KPW + k * 256 + c;
        wbf[b] = hb;
        wbf[b + 2304] = hb;
        wbf[b + 4608] = lb;
    }
}

// off_w[m][c][kh][kw] -> wp[m][tap*320 + c]
__global__ void prep_off_w(const float* __restrict__ ow, float* __restrict__ wp) {
    int m = blockIdx.x;       // 18
    int c = threadIdx.x;      // 320
#pragma unroll
    for (int kk = 0; kk < 9; kk++)
        wp[m * 2880 + kk * 320 + c] = ow[m * 2880 + c * 9 + kk];
}

// ---------------------------------------------------------------------------
// Stage-1 GEMM v2: implicit im2col from NHWC xT/dT, tap-major K.
// M=18 (BM=32 padded), BN=128, BK=16. Split-K x2 (1440 each), atomic merge.
// grid (HW/128, 2, NB), 256 threads.
// ---------------------------------------------------------------------------
__global__ void __launch_bounds__(256, 3)
sgemm_s1(const float* __restrict__ xT, const float* __restrict__ dT,
         const float* __restrict__ A, const float* __restrict__ bias,
         float* __restrict__ C) {
    const int M = 18;
    __shared__ float As[16][36];
    __shared__ float Bs[16][128];
    const int tid = threadIdx.x;
    const int n0 = blockIdx.x * 128;
    const int slice = blockIdx.y;
    const int n = blockIdx.z;
    const int tx = tid % 16, ty = tid / 16;
    const float* xTn = xT + (size_t)n * HW * CIN;
    const float* dTn = dT + (size_t)n * HW * DC;

    float acc[2][8];
#pragma unroll
    for (int i = 0; i < 2; i++)
#pragma unroll
        for (int j = 0; j < 8; j++) acc[i][j] = 0.f;

    float4 ra;
    float4 rbq[2];

    // loadB tap/ctile state (global ktile = slice*90 + kt)
    int tap = (slice == 0) ? 0 : 4;    // 90/20 = 4
    int ct  = (slice == 0) ? 0 : 10;   // 90%20 = 10

    auto loadA = [&](int kt) {
        if (tid < 128) {
            int row = tid / 4, kq = tid % 4;
            ra = (row < M) ? *reinterpret_cast<const float4*>(
                                 &A[(size_t)row * 2880 + slice * 1440 + kt * 16 + kq * 4])
                           : make_float4(0.f, 0.f, 0.f, 0.f);
        }
    };
    auto loadB = [&]() {
        int c0 = ct * 16;
        int dr = tap / 3 - 1, dc = tap % 3 - 1;
#pragma unroll
        for (int u = 0; u < 2; u++) {
            int slot = tid + u * 256;
            int px = slot >> 2, q = slot & 3;
            int p = n0 + px;
            int h = p >> 6, w = p & 63;
            int iy = h + dr, ix = w + dc;
            bool v = (iy >= 0) & (iy < HH) & (ix >= 0) & (ix < WW);
            int pn = iy * WW + ix;
            const float* src = (c0 < CIN)
                ? xTn + (size_t)pn * CIN + c0 + q * 4
                : dTn + (size_t)pn * DC + (c0 - CIN) + q * 4;
            rbq[u] = v ? *reinterpret_cast<const float4*>(src)
                       : make_float4(0.f, 0.f, 0.f, 0.f);
        }
        if (++ct == 20) { ct = 0; tap++; }
    };
    auto storeA = [&]() {
        if (tid < 128) {
            int row = tid / 4, kq = tid % 4;
            As[kq * 4 + 0][row] = ra.x;
            As[kq * 4 + 1][row] = ra.y;
            As[kq * 4 + 2][row] = ra.z;
            As[kq * 4 + 3][row] = ra.w;
        }
    };
    auto storeB = [&]() {
#pragma unroll
        for (int u = 0; u < 2; u++) {
            int slot = tid + u * 256;
            int px = slot >> 2, q = slot & 3;
            Bs[q * 4 + 0][px] = rbq[u].x;
            Bs[q * 4 + 1][px] = rbq[u].y;
            Bs[q * 4 + 2][px] = rbq[u].z;
            Bs[q * 4 + 3][px] = rbq[u].w;
        }
    };

    loadA(0); loadB();
    storeA(); storeB();
    __syncthreads();

    const int ktiles = 90;
    for (int t = 0; t < ktiles; t++) {
        if (t + 1 < ktiles) { loadA(t + 1); loadB(); }
#pragma unroll
        for (int kk = 0; kk < 16; kk++) {
            float a0 = As[kk][ty * 2], a1 = As[kk][ty * 2 + 1];
            float b[8];
#pragma unroll
            for (int j = 0; j < 8; j++) b[j] = Bs[kk][tx * 8 + j];
#pragma unroll
            for (int j = 0; j < 8; j++) { acc[0][j] += a0 * b[j]; acc[1][j] += a1 * b[j]; }
        }
        __syncthreads();
        if (t + 1 < ktiles) { storeA(); storeB(); __syncthreads(); }
    }

#pragma unroll
    for (int i = 0; i < 2; i++) {
        int gm = ty * 2 + i;
        if (gm < M) {
            float bi = (slice == 0) ? bias[gm] : 0.f;
            float* cp = &C[((size_t)n * M + gm) * HW + n0 + tx * 8];
#pragma unroll
            for (int j = 0; j < 8; j++)
                atomicAdd(cp + j, acc[i][j] + bi);
        }
    }
}

// ---------------------------------------------------------------------------
// Stage-2 FUSED: mask = sigmoid(deform_conv(depthT, offset) + mb)
// ---------------------------------------------------------------------------
__global__ void __launch_bounds__(256)
fused_mask(const float* __restrict__ depthT, const float* __restrict__ offs,
           const float* __restrict__ mw, const float* __restrict__ mb,
           float* __restrict__ maskbuf) {
    __shared__ float ws[9][9][64];     // [k][m][c]
    __shared__ float sbias[9];
    const int tid = threadIdx.x;
    const int n = blockIdx.y;

    for (int i = tid; i < 5184; i += 256) {
        int m = i / 576;
        int rem = i - m * 576;
        int c = rem / 9;
        int k = rem - 9 * c;
        ws[k][m][c] = mw[i];
    }
    if (tid < 9) sbias[tid] = mb[tid];
    __syncthreads();

    const int wid = tid >> 5, lane = tid & 31;
    const int p = blockIdx.x * 8 + wid;
    const int h = p >> 6, w = p & 63;
    const float* dn = depthT + (size_t)n * HW * DC;
    const float* offn = offs + (size_t)n * 18 * HW;

    float acc[9];
#pragma unroll
    for (int m = 0; m < 9; m++) acc[m] = 0.f;

#pragma unroll
    for (int k = 0; k < 9; k++) {
        float dy = offn[(size_t)(2 * k) * HW + p];
        float dx = offn[(size_t)(2 * k + 1) * HW + p];
        float y = (float)(h - 1 + k / 3) + dy;
        float xx = (float)(w - 1 + k % 3) + dx;
        float y0f = floorf(y), x0f = floorf(xx);
        float ly = y - y0f, lx = xx - x0f;
        int y0 = (int)y0f, x0 = (int)x0f;
        int y1 = y0 + 1, x1 = x0 + 1;
        bool vy0 = (y0 >= 0) & (y0 < HH);
        bool vy1 = (y1 >= 0) & (y1 < HH);
        bool vx0 = (x0 >= 0) & (x0 < WW);
        bool vx1 = (x1 >= 0) & (x1 < WW);
        float w00 = (vy0 & vx0) ? (1.f - ly) * (1.f - lx) : 0.f;
        float w01 = (vy0 & vx1) ? (1.f - ly) * lx : 0.f;
        float w10 = (vy1 & vx0) ? ly * (1.f - lx) : 0.f;
        float w11 = (vy1 & vx1) ? ly * lx : 0.f;
        int i00 = (vy0 & vx0) ? y0 * WW + x0 : 0;
        int i01 = (vy0 & vx1) ? y0 * WW + x1 : 0;
        int i10 = (vy1 & vx0) ? y1 * WW + x0 : 0;
        int i11 = (vy1 & vx1) ? y1 * WW + x1 : 0;
        int cc = lane * 2;
        float2 a = *reinterpret_cast<const float2*>(dn + (size_t)i00 * DC + cc);
        float2 b = *reinterpret_cast<const float2*>(dn + (size_t)i01 * DC + cc);
        float2 cv = *reinterpret_cast<const float2*>(dn + (size_t)i10 * DC + cc);
        float2 d = *reinterpret_cast<const float2*>(dn + (size_t)i11 * DC + cc);
        float v0 = w00 * a.x + w01 * b.x + w10 * cv.x + w11 * d.x;
        float v1 = w00 * a.y + w01 * b.y + w10 * cv.y + w11 * d.y;
#pragma unroll
        for (int m = 0; m < 9; m++) {
            float2 wv = *reinterpret_cast<const float2*>(&ws[k][m][cc]);
            acc[m] += wv.x * v0 + wv.y * v1;
        }
    }

#pragma unroll
    for (int m = 0; m < 9; m++) {
#pragma unroll
        for (int off = 16; off > 0; off >>= 1)
            acc[m] += __shfl_xor_sync(0xFFFFFFFFu, acc[m], off);
    }
    if (lane == 0) {
        float* mp = maskbuf + (size_t)n * 9 * HW + p;
#pragma unroll
        for (int m = 0; m < 9; m++) {
            float v = acc[m] + sbias[m];
            mp[(size_t)m * HW] = 1.f / (1.f + expf(-v));
        }
    }
}

// ---------------------------------------------------------------------------
// Stage-3 deformable im2col: xT gathers + coalesced bf16 split stores.
// ---------------------------------------------------------------------------
__global__ void __launch_bounds__(256)
deform_im2col_bf16_v2(const float* __restrict__ xT, const float* __restrict__ offs,
                      const float* __restrict__ mask,
                      __nv_bfloat16* __restrict__ colsT) {
    __shared__ float s_w[4][32];
    __shared__ int s_i[4][32];
    __shared__ __align__(16) __nv_bfloat16 s_hi[32][264];
    __shared__ __align__(16) __nv_bfloat16 s_lo[32][264];

    const int k = blockIdx.y;
    const int n = blockIdx.z;
    const int p0 = blockIdx.x * 32;
    const int tid = threadIdx.x;
    const int lane = tid & 31, wrp = tid >> 5;

    if (tid < 32) {
        int p = p0 + tid;
        int h = p >> 6, w = p & 63;
        const float* offn = offs + (size_t)n * 18 * HW;
        float dy = offn[(size_t)(2 * k) * HW + p];
        float dx = offn[(size_t)(2 * k + 1) * HW + p];
        float mk = mask[((size_t)n * 9 + k) * HW + p];
        float y = (float)(h - 1 + k / 3) + dy;
        float xx = (float)(w - 1 + k % 3) + dx;
        float y0f = floorf(y), x0f = floorf(xx);
        float ly = y - y0f, lx = xx - x0f;
        int y0 = (int)y0f, x0 = (int)x0f;
        int y1 = y0 + 1, x1 = x0 + 1;
        bool vy0 = (y0 >= 0) & (y0 < HH);
        bool vy1 = (y1 >= 0) & (y1 < HH);
        bool vx0 = (x0 >= 0) & (x0 < WW);
        bool vx1 = (x1 >= 0) & (x1 < WW);
        s_w[0][tid] = (vy0 & vx0) ? (1.f - ly) * (1.f - lx) * mk : 0.f;
        s_w[1][tid] = (vy0 & vx1) ? (1.f - ly) * lx * mk : 0.f;
        s_w[2][tid] = (vy1 & vx0) ? ly * (1.f - lx) * mk : 0.f;
        s_w[3][tid] = (vy1 & vx1) ? ly * lx * mk : 0.f;
        s_i[0][tid] = (vy0 & vx0) ? y0 * WW + x0 : 0;
        s_i[1][tid] = (vy0 & vx1) ? y0 * WW + x1 : 0;
        s_i[2][tid] = (vy1 & vx0) ? y1 * WW + x0 : 0;
        s_i[3][tid] = (vy1 & vx1) ? y1 * WW + x1 : 0;
    }
    __syncthreads();

    {
        const int pl = lane;
        const float w00 = s_w[0][pl], w01 = s_w[1][pl], w10 = s_w[2][pl], w11 = s_w[3][pl];
        const float* src = xT + (size_t)n * HW * CIN;
        const float* r00 = src + (size_t)s_i[0][pl] * CIN;
        const float* r01 = src + (size_t)s_i[1][pl] * CIN;
        const float* r10 = src + (size_t)s_i[2][pl] * CIN;
        const float* r11 = src + (size_t)s_i[3][pl] * CIN;
#pragma unroll
        for (int j8 = 0; j8 < 4; j8++) {
            int c8 = wrp * 32 + j8 * 8;
            float a[8], b[8], c[8], d[8];
            *reinterpret_cast<float4*>(a) = *reinterpret_cast<const float4*>(r00 + c8);
            *reinterpret_cast<float4*>(a + 4) = *reinterpret_cast<const float4*>(r00 + c8 + 4);
            *reinterpret_cast<float4*>(b) = *reinterpret_cast<const float4*>(r01 + c8);
            *reinterpret_cast<float4*>(b + 4) = *reinterpret_cast<const float4*>(r01 + c8 + 4);
            *reinterpret_cast<float4*>(c) = *reinterpret_cast<const float4*>(r10 + c8);
            *reinterpret_cast<float4*>(c + 4) = *reinterpret_cast<const float4*>(r10 + c8 + 4);
            *reinterpret_cast<float4*>(d) = *reinterpret_cast<const float4*>(r11 + c8);
            *reinterpret_cast<float4*>(d + 4) = *reinterpret_cast<const float4*>(r11 + c8 + 4);
            __align__(16) __nv_bfloat16 hi[8];
            __align__(16) __nv_bfloat16 lo[8];
#pragma unroll
            for (int j = 0; j < 8; j++) {
                float v = w00 * a[j] + w01 * b[j] + w10 * c[j] + w11 * d[j];
                __nv_bfloat16 hb = __float2bfloat16(v);
                hi[j] = hb;
                lo[j] = __float2bfloat16(v - __bfloat162float(hb));
            }
            *reinterpret_cast<uint4*>(&s_hi[pl][c8]) = *reinterpret_cast<uint4*>(hi);
            *reinterpret_cast<uint4*>(&s_lo[pl][c8]) = *reinterpret_cast<uint4*>(lo);
        }
    }
    __syncthreads();

    __nv_bfloat16* base = colsT + (size_t)(n * HW + p0) * KPA + k * 256;
#pragma unroll
    for (int pass = 0; pass < 8; pass++) {
        int id = tid + pass * 256;
        int px = id >> 6;
        int rem = id & 63;
        int half = rem >> 5;
        int q = rem & 31;
        uint4 v = half ? *reinterpret_cast<uint4*>(&s_lo[px][q * 8])
                       : *reinterpret_cast<uint4*>(&s_hi[px][q * 8]);
        *reinterpret_cast<uint4*>(base + (size_t)px * KPA + half * 2304 + q * 8) = v;
    }
}

// ---------------------------------------------------------------------------
// Stage-3 HMMA GEMM (3-stage cp.async pipeline)
// ---------------------------------------------------------------------------
#define ABYTES 16384
#define BBYTES 32768
#define STAGEB (ABYTES + BBYTES)
#define NSTG 3

__global__ void __launch_bounds__(256, 1)
hmma_gemm(const __nv_bfloat16* __restrict__ colsT,
          const __nv_bfloat16* __restrict__ wbf,
          const float* __restrict__ bias, float* __restrict__ out) {
    extern __shared__ char smem[];
    const uint32_t sb = smem_u32(smem);
    const int tid = threadIdx.x;
    const int wid = tid >> 5, lane = tid & 31;
    const int wm = wid >> 2, wn = wid & 3;
    const int p0 = blockIdx.x * 128;
    const int n = blockIdx.z;

    const char* Ag = (const char*)(colsT + (size_t)(n * HW + p0) * KPA);
    const char* Bg = (const char*)wbf;

    float acc[4][8][4];
#pragma unroll
    for (int i = 0; i < 4; i++)
#pragma unroll
        for (int j = 0; j < 8; j++)
#pragma unroll
            for (int r = 0; r < 4; r++) acc[i][j][r] = 0.f;

    auto load_chunk = [&](int kt, int buf) {
        int ktA = (kt < 72) ? kt : kt - 72;
        uint32_t dA = sb + buf * STAGEB;
        uint32_t dB = dA + ABYTES;
#pragma unroll
        for (int u = 0; u < 4; u++) {
            int idx = tid + u * 256;
            int row = idx >> 3, c = idx & 7;
            cp_async16(dA + row * 128 + ((c ^ (row & 7)) << 4),
                       Ag + (size_t)row * KROWA + ktA * 128 + c * 16);
        }
#pragma unroll
        for (int u = 0; u < 8; u++) {
            int idx = tid + u * 256;
            int row = idx >> 3, c = idx & 7;
            cp_async16(dB + row * 128 + ((c ^ (row & 7)) << 4),
                       Bg + (size_t)row * KROWW + kt * 128 + c * 16);
        }
        cp_commit();
    };

    auto compute_chunk = [&](int buf) {
        uint32_t Ab = sb + buf * STAGEB;
        uint32_t Bb = Ab + ABYTES;
        const int rbase = ((lane >> 3) & 1) * 8 + (lane & 7);
        const int chi = (lane >> 4);
#pragma unroll
        for (int ks = 0; ks < 4; ks++) {
            int c = ks * 2 + chi;
            uint32_t af[4][4], bf[4][4];
#pragma unroll
            for (int i = 0; i < 4; i++) {
                int row = wm * 64 + i * 16 + rbase;
                ldsm_x4(af[i], Ab + row * 128 + ((c ^ (row & 7)) << 4));
            }
#pragma unroll
            for (int j = 0; j < 4; j++) {
                int row = wn * 64 + j * 16 + rbase;
                ldsm_x4(bf[j], Bb + row * 128 + ((c ^ (row & 7)) << 4));
            }
#pragma unroll
            for (int i = 0; i < 4; i++)
#pragma unroll
                for (int j = 0; j < 4; j++)
#pragma unroll
                    for (int s = 0; s < 2; s++)
                        mma16816(acc[i][j * 2 + s], af[i], bf[j][s], bf[j][s + 2]);
        }
    };

    load_chunk(0, 0);
    load_chunk(1, 1);
    for (int kt = 0; kt < KCHUNKS; kt++) {
        int buf = kt % NSTG;
        if (kt + 1 < KCHUNKS) cp_wait<1>(); else cp_wait<0>();
        __syncthreads();
        if (kt + 2 < KCHUNKS) load_chunk(kt + 2, (kt + 2) % NSTG);
        compute_chunk(buf);
    }

#pragma unroll
    for (int i = 0; i < 4; i++) {
        int m = wm * 64 + i * 16 + (lane >> 2);
#pragma unroll
        for (int j = 0; j < 4; j++)
#pragma unroll
            for (int s = 0; s < 2; s++) {
                int cout = wn * 64 + j * 16 + s * 8 + (lane & 3) * 2;
                float b0 = bias[cout], b1 = bias[cout + 1];
                float* o = out + ((size_t)n * COUT + cout) * HW + p0;
                const float* a = acc[i][j * 2 + s];
                o[m]          = a[0] + b0;
                o[HW + m]     = a[1] + b1;
                o[m + 8]      = a[2] + b0;
                o[HW + m + 8] = a[3] + b1;
            }
    }
}

// ---------------------------------------------------------------------------
extern "C" void kernel_launch(void* const* d_in, const int* in_sizes, int n_in,
                              void* d_out, int out_size) {
    const float* x      = (const float*)d_in[0];
    const float* depth  = (const float*)d_in[1];
    const float* weight = (const float*)d_in[2];
    const float* bias   = (const float*)d_in[3];
    const float* off_w  = (const float*)d_in[4];
    const float* off_b  = (const float*)d_in[5];
    const float* mask_w = (const float*)d_in[6];
    const float* mask_b = (const float*)d_in[7];
    float* out = (float*)d_out;

    void *po, *pm, *pcb, *pwb, *pxt, *pdt, *pwp;
    cudaGetSymbolAddress(&po, g_offsets);
    cudaGetSymbolAddress(&pm, g_mask);
    cudaGetSymbolAddress(&pcb, g_colsbf);
    cudaGetSymbolAddress(&pwb, g_wbf);
    cudaGetSymbolAddress(&pxt, g_xT);
    cudaGetSymbolAddress(&pdt, g_dT);
    cudaGetSymbolAddress(&pwp, g_wpoff);
    float* offsets = (float*)po;
    float* maskbuf = (float*)pm;
    __nv_bfloat16* colsbf = (__nv_bfloat16*)pcb;
    __nv_bfloat16* wbf = (__nv_bfloat16*)pwb;
    float* xT = (float*)pxt;
    float* dT = (float*)pdt;
    float* wpoff = (float*)pwp;

    // Prep: zero split-K accumulator, weight packs, transposes
    cudaMemsetAsync(offsets, 0, (size_t)NB * 18 * HW * sizeof(float), 0);
    prep_w_kernel<<<COUT, 256>>>(weight, wbf);
    prep_off_w<<<18, 320>>>(off_w, wpoff);
    transpose_cp<<<dim3(HW / 32, CIN / 32, NB), dim3(32, 8)>>>(x, xT, CIN);
    transpose_cp<<<dim3(HW / 32, DC / 32, NB), dim3(32, 8)>>>(depth, dT, DC);

    // Stage 1: offset conv via implicit-im2col (NHWC) split-K SGEMM
    sgemm_s1<<<dim3(HW / 128, 2, NB), 256>>>(xT, dT, wpoff, off_b, offsets);

    // Stage 2: fused mask = sigmoid(deform_conv(depth, offset))
    fused_mask<<<dim3(HW / 8, NB), 256>>>(dT, offsets, mask_w, mask_b, maskbuf);

    // Stage 3: modulated deformable conv via HMMA bf16 split-K GEMM
    deform_im2col_bf16_v2<<<dim3(HW / 32, 9, NB), 256>>>(xT, offsets, maskbuf, colsbf);

    static int smem_set = 0;
    if (!smem_set) {
        cudaFuncSetAttribute(hmma_gemm, cudaFuncAttributeMaxDynamicSharedMemorySize,
                             NSTG * STAGEB);
        smem_set = 1;
    }
    hmma_gemm<<<dim3(HW / 128, 1, NB), 256, NSTG * STAGEB>>>(colsbf, wbf, bias, out);
}

// round 9
// speedup vs baseline: 2.2635x; 1.3122x over previous
#include <cuda_runtime.h>
#include <cuda_bf16.h>
#include <cstdint>
#include <math.h>

#define NB 4
#define HH 64
#define WW 64
#define HW 4096
#define CIN 256
#define DC 64
#define COUT 256
#define KPA 4608               /* stage-3 A cols: [hi | lo] */
#define KPW 6912               /* stage-3 W cols: [hi | hi | lo] */
#define KROWA (KPA * 2)
#define KROWW (KPW * 2)
#define KCHUNKS 108            /* stage-3: KPW / 64 */
#define S1K 8640               /* stage-1 W cols: 3 * 2880 */
#define S1CHUNKS 135           /* S1K / 64 */

// ---------------- device scratch ----------------
__device__ float g_offsets[(size_t)NB * 18 * HW];
__device__ float g_mask[(size_t)NB * 9 * HW];
__device__ float g_xT[(size_t)NB * HW * CIN];              // x NHWC f32
__device__ float g_dT[(size_t)NB * HW * DC];               // depth NHWC f32
__device__ __nv_bfloat16 g_xdbf[(size_t)NB * HW * 640];    // cat(x,d) [hi320|lo320]
__device__ __nv_bfloat16 g_ws1[(size_t)32 * S1K];          // off_w split, 32 rows
__device__ __nv_bfloat16 g_colsbf[(size_t)NB * HW * KPA];
__device__ __nv_bfloat16 g_wbf[(size_t)COUT * KPW];

// ---------------- PTX helpers ----------------
__device__ __forceinline__ uint32_t smem_u32(const void* p) {
    uint32_t a;
    asm("{ .reg .u64 t; cvta.to.shared.u64 t, %1; cvt.u32.u64 %0, t; }"
        : "=r"(a) : "l"(p));
    return a;
}
__device__ __forceinline__ void cp_async16(uint32_t dst, const void* src) {
    asm volatile("cp.async.cg.shared.global [%0], [%1], 16;"
                 :: "r"(dst), "l"(src) : "memory");
}
// zero-fill variant: src-size 0 -> smem gets zeros
__device__ __forceinline__ void cp_async16_z(uint32_t dst, const void* src, bool pred) {
    int sz = pred ? 16 : 0;
    asm volatile("cp.async.cg.shared.global [%0], [%1], 16, %2;"
                 :: "r"(dst), "l"(src), "r"(sz) : "memory");
}
__device__ __forceinline__ void cp_commit() {
    asm volatile("cp.async.commit_group;" ::: "memory");
}
template <int N>
__device__ __forceinline__ void cp_wait() {
    asm volatile("cp.async.wait_group %0;" :: "n"(N) : "memory");
}
__device__ __forceinline__ void ldsm_x4(uint32_t (&r)[4], uint32_t addr) {
    asm volatile("ldmatrix.sync.aligned.m8n8.x4.shared.b16 {%0,%1,%2,%3}, [%4];"
                 : "=r"(r[0]), "=r"(r[1]), "=r"(r[2]), "=r"(r[3]) : "r"(addr));
}
__device__ __forceinline__ void mma16816(float (&d)[4], const uint32_t (&a)[4],
                                         uint32_t b0, uint32_t b1) {
    asm volatile(
        "mma.sync.aligned.m16n8k16.row.col.f32.bf16.bf16.f32 "
        "{%0,%1,%2,%3}, {%4,%5,%6,%7}, {%8,%9}, {%0,%1,%2,%3};"
        : "+f"(d[0]), "+f"(d[1]), "+f"(d[2]), "+f"(d[3])
        : "r"(a[0]), "r"(a[1]), "r"(a[2]), "r"(a[3]), "r"(b0), "r"(b1));
}

// ---------------------------------------------------------------------------
// Transpose: src[n][c][p] -> dst[n][p][c]
// ---------------------------------------------------------------------------
__global__ void transpose_cp(const float* __restrict__ src, float* __restrict__ dst,
                             int C) {
    __shared__ float t[32][33];
    int n = blockIdx.z;
    int p0 = blockIdx.x * 32, c0 = blockIdx.y * 32;
    int tx = threadIdx.x, ty = threadIdx.y;
#pragma unroll
    for (int j = 0; j < 32; j += 8)
        t[ty + j][tx] = src[((size_t)n * C + c0 + ty + j) * HW + p0 + tx];
    __syncthreads();
#pragma unroll
    for (int j = 0; j < 32; j += 8)
        dst[((size_t)n * HW + p0 + ty + j) * C + c0 + tx] = t[tx][ty + j];
}

// ---------------------------------------------------------------------------
// Build xdbf[n][p][hi 0..320 | lo 320..640] from xT/dT
// grid (HW/32, NB), 256 threads; 1280 slots of 8 channels per block
// ---------------------------------------------------------------------------
__global__ void __launch_bounds__(256)
build_xdbf(const float* __restrict__ xT, const float* __restrict__ dT,
           __nv_bfloat16* __restrict__ xd) {
    int n = blockIdx.y;
    int p0 = blockIdx.x * 32;
    int tid = threadIdx.x;
#pragma unroll
    for (int pass = 0; pass < 5; pass++) {
        int id = tid + pass * 256;      // 0..1279
        int px = id / 40;
        int c8 = (id - px * 40) * 8;    // 0..312
        size_t prow = (size_t)n * HW + p0 + px;
        const float* src = (c8 < CIN) ? xT + prow * CIN + c8
                                      : dT + prow * DC + (c8 - CIN);
        float v[8];
        *reinterpret_cast<float4*>(v) = *reinterpret_cast<const float4*>(src);
        *reinterpret_cast<float4*>(v + 4) = *reinterpret_cast<const float4*>(src + 4);
        __align__(16) __nv_bfloat16 hi[8];
        __align__(16) __nv_bfloat16 lo[8];
#pragma unroll
        for (int j = 0; j < 8; j++) {
            __nv_bfloat16 hb = __float2bfloat16(v[j]);
            hi[j] = hb;
            lo[j] = __float2bfloat16(v[j] - __bfloat162float(hb));
        }
        __nv_bfloat16* dst = xd + prow * 640;
        *reinterpret_cast<uint4*>(dst + c8) = *reinterpret_cast<uint4*>(hi);
        *reinterpret_cast<uint4*>(dst + 320 + c8) = *reinterpret_cast<uint4*>(lo);
    }
}

// ---------------------------------------------------------------------------
// Weight preps
// ---------------------------------------------------------------------------
__global__ void prep_w_kernel(const float* __restrict__ w,
                              __nv_bfloat16* __restrict__ wbf) {
    int cout = blockIdx.x;
    int c = threadIdx.x;
#pragma unroll
    for (int k = 0; k < 9; k++) {
        float v = w[((size_t)cout * 256 + c) * 9 + k];
        __nv_bfloat16 hb = __float2bfloat16(v);
        __nv_bfloat16 lb = __float2bfloat16(v - __bfloat162float(hb));
        size_t b = (size_t)cout * KPW + k * 256 + c;
        wbf[b] = hb;
        wbf[b + 2304] = hb;
        wbf[b + 4608] = lb;
    }
}

// off_w[m][c][kh][kw] -> ws1[m][pass*2880 + tap*320 + c], rows 18..31 zero
__global__ void prep_s1w(const float* __restrict__ ow, __nv_bfloat16* __restrict__ ws) {
    int m = blockIdx.x;       // 0..31
    int c = threadIdx.x;      // 0..319
#pragma unroll
    for (int kk = 0; kk < 9; kk++) {
        float v = (m < 18) ? ow[((size_t)m * 320 + c) * 9 + kk] : 0.f;
        __nv_bfloat16 hb = __float2bfloat16(v);
        __nv_bfloat16 lb = __float2bfloat16(v - __bfloat162float(hb));
        size_t b = (size_t)m * S1K + kk * 320 + c;
        ws[b] = hb;
        ws[b + 2880] = hb;
        ws[b + 5760] = lb;
    }
}

// ---------------------------------------------------------------------------
// Stage-1 HMMA GEMM (implicit im2col): offsets[p][m18] = xdcols . ws1^T
// A: 128 px x 64 bf16 (chunk in one tap; uniform shift, zfill borders)
// B: 32 m-rows x 64. 8 warps = 8 m16 pixel tiles. 3-stage cp.async.
// grid (HW/128, 1, NB), 256 threads.
// ---------------------------------------------------------------------------
#define S1_AB 16384            /* A tile bytes */
#define S1_BB 4096             /* B tile bytes (32 x 128B) */
#define S1_STG (S1_AB + S1_BB)

__global__ void __launch_bounds__(256, 1)
s1_hmma(const __nv_bfloat16* __restrict__ xd, const __nv_bfloat16* __restrict__ ws,
        const float* __restrict__ offb, float* __restrict__ offsets) {
    extern __shared__ char smem[];
    const uint32_t sb = smem_u32(smem);
    const int tid = threadIdx.x;
    const int wid = tid >> 5, lane = tid & 31;
    const int p0 = blockIdx.x * 128;
    const int n = blockIdx.z;
    const __nv_bfloat16* xdn = xd + (size_t)n * HW * 640;

    float acc[4][4];
#pragma unroll
    for (int i = 0; i < 4; i++)
#pragma unroll
        for (int r = 0; r < 4; r++) acc[i][r] = 0.f;

    auto load_chunk = [&](int kc, int buf) {
        int pass = kc / 45;
        int r = kc - pass * 45;
        int tap = r / 5;
        int c0 = (r - tap * 5) * 64;
        int ah = (pass == 1) ? 320 : 0;     // A half: pass1 = lo
        int dr = tap / 3 - 1, dc = tap % 3 - 1;
        uint32_t dA = sb + buf * S1_STG;
        uint32_t dB = dA + S1_AB;
#pragma unroll
        for (int u = 0; u < 4; u++) {
            int idx = tid + u * 256;
            int row = idx >> 3, q = idx & 7;
            int gp = p0 + row;
            int h = gp >> 6, w = gp & 63;
            int iy = h + dr, ix = w + dc;
            bool v = (iy >= 0) & (iy < HH) & (ix >= 0) & (ix < WW);
            int pn = v ? iy * WW + ix : 0;
            cp_async16_z(dA + row * 128 + ((q ^ (row & 7)) << 4),
                         xdn + (size_t)pn * 640 + ah + c0 + q * 8, v);
        }
        {
            int row = tid >> 3, q = tid & 7;
            cp_async16(dB + row * 128 + ((q ^ (row & 7)) << 4),
                       ws + (size_t)row * S1K + kc * 64 + q * 8);
        }
        cp_commit();
    };

    auto compute_chunk = [&](int buf) {
        uint32_t Ab = sb + buf * S1_STG;
        uint32_t Bb = Ab + S1_AB;
        const int rbase = ((lane >> 3) & 1) * 8 + (lane & 7);
        const int chi = (lane >> 4);
#pragma unroll
        for (int ks = 0; ks < 4; ks++) {
            int c = ks * 2 + chi;
            uint32_t af[4], bf[2][4];
            {
                int row = wid * 16 + rbase;
                ldsm_x4(af, Ab + row * 128 + ((c ^ (row & 7)) << 4));
            }
#pragma unroll
            for (int j = 0; j < 2; j++) {
                int row = j * 16 + rbase;
                ldsm_x4(bf[j], Bb + row * 128 + ((c ^ (row & 7)) << 4));
            }
#pragma unroll
            for (int j = 0; j < 2; j++)
#pragma unroll
                for (int s = 0; s < 2; s++)
                    mma16816(acc[j * 2 + s], af, bf[j][s], bf[j][s + 2]);
        }
    };

    load_chunk(0, 0);
    load_chunk(1, 1);
    for (int kc = 0; kc < S1CHUNKS; kc++) {
        int buf = kc % 3;
        if (kc + 1 < S1CHUNKS) cp_wait<1>(); else cp_wait<0>();
        __syncthreads();
        if (kc + 2 < S1CHUNKS) load_chunk(kc + 2, (kc + 2) % 3);
        compute_chunk(buf);
    }

    // Epilogue: m = j*16 + s*8 + (lane&3)*2 (even); keep m<18
#pragma unroll
    for (int j = 0; j < 2; j++)
#pragma unroll
        for (int s = 0; s < 2; s++) {
            int m = j * 16 + s * 8 + (lane & 3) * 2;
            if (m < 18) {
                float b0 = offb[m], b1 = offb[m + 1];
                int row = wid * 16 + (lane >> 2);
                float* o = offsets + ((size_t)n * 18 + m) * HW + p0;
                const float* a = acc[j * 2 + s];
                o[row]          = a[0] + b0;
                o[HW + row]     = a[1] + b1;
                o[row + 8]      = a[2] + b0;
                o[HW + row + 8] = a[3] + b1;
            }
        }
}

// ---------------------------------------------------------------------------
// Stage-2 FUSED: mask = sigmoid(deform_conv(depthT, offset) + mb)
// ---------------------------------------------------------------------------
__global__ void __launch_bounds__(256)
fused_mask(const float* __restrict__ depthT, const float* __restrict__ offs,
           const float* __restrict__ mw, const float* __restrict__ mb,
           float* __restrict__ maskbuf) {
    __shared__ float ws[9][9][64];
    __shared__ float sbias[9];
    const int tid = threadIdx.x;
    const int n = blockIdx.y;

    for (int i = tid; i < 5184; i += 256) {
        int m = i / 576;
        int rem = i - m * 576;
        int c = rem / 9;
        int k = rem - 9 * c;
        ws[k][m][c] = mw[i];
    }
    if (tid < 9) sbias[tid] = mb[tid];
    __syncthreads();

    const int wid = tid >> 5, lane = tid & 31;
    const int p = blockIdx.x * 8 + wid;
    const int h = p >> 6, w = p & 63;
    const float* dn = depthT + (size_t)n * HW * DC;
    const float* offn = offs + (size_t)n * 18 * HW;

    float acc[9];
#pragma unroll
    for (int m = 0; m < 9; m++) acc[m] = 0.f;

#pragma unroll
    for (int k = 0; k < 9; k++) {
        float dy = offn[(size_t)(2 * k) * HW + p];
        float dx = offn[(size_t)(2 * k + 1) * HW + p];
        float y = (float)(h - 1 + k / 3) + dy;
        float xx = (float)(w - 1 + k % 3) + dx;
        float y0f = floorf(y), x0f = floorf(xx);
        float ly = y - y0f, lx = xx - x0f;
        int y0 = (int)y0f, x0 = (int)x0f;
        int y1 = y0 + 1, x1 = x0 + 1;
        bool vy0 = (y0 >= 0) & (y0 < HH);
        bool vy1 = (y1 >= 0) & (y1 < HH);
        bool vx0 = (x0 >= 0) & (x0 < WW);
        bool vx1 = (x1 >= 0) & (x1 < WW);
        float w00 = (vy0 & vx0) ? (1.f - ly) * (1.f - lx) : 0.f;
        float w01 = (vy0 & vx1) ? (1.f - ly) * lx : 0.f;
        float w10 = (vy1 & vx0) ? ly * (1.f - lx) : 0.f;
        float w11 = (vy1 & vx1) ? ly * lx : 0.f;
        int i00 = (vy0 & vx0) ? y0 * WW + x0 : 0;
        int i01 = (vy0 & vx1) ? y0 * WW + x1 : 0;
        int i10 = (vy1 & vx0) ? y1 * WW + x0 : 0;
        int i11 = (vy1 & vx1) ? y1 * WW + x1 : 0;
        int cc = lane * 2;
        float2 a = *reinterpret_cast<const float2*>(dn + (size_t)i00 * DC + cc);
        float2 b = *reinterpret_cast<const float2*>(dn + (size_t)i01 * DC + cc);
        float2 cv = *reinterpret_cast<const float2*>(dn + (size_t)i10 * DC + cc);
        float2 d = *reinterpret_cast<const float2*>(dn + (size_t)i11 * DC + cc);
        float v0 = w00 * a.x + w01 * b.x + w10 * cv.x + w11 * d.x;
        float v1 = w00 * a.y + w01 * b.y + w10 * cv.y + w11 * d.y;
#pragma unroll
        for (int m = 0; m < 9; m++) {
            float2 wv = *reinterpret_cast<const float2*>(&ws[k][m][cc]);
            acc[m] += wv.x * v0 + wv.y * v1;
        }
    }

#pragma unroll
    for (int m = 0; m < 9; m++) {
#pragma unroll
        for (int off = 16; off > 0; off >>= 1)
            acc[m] += __shfl_xor_sync(0xFFFFFFFFu, acc[m], off);
    }
    if (lane == 0) {
        float* mp = maskbuf + (size_t)n * 9 * HW + p;
#pragma unroll
        for (int m = 0; m < 9; m++) {
            float v = acc[m] + sbias[m];
            mp[(size_t)m * HW] = 1.f / (1.f + expf(-v));
        }
    }
}

// ---------------------------------------------------------------------------
// Stage-3 deformable im2col: xT gathers + coalesced bf16 split stores.
// ---------------------------------------------------------------------------
__global__ void __launch_bounds__(256)
deform_im2col_bf16_v2(const float* __restrict__ xT, const float* __restrict__ offs,
                      const float* __restrict__ mask,
                      __nv_bfloat16* __restrict__ colsT) {
    __shared__ float s_w[4][32];
    __shared__ int s_i[4][32];
    __shared__ __align__(16) __nv_bfloat16 s_hi[32][264];
    __shared__ __align__(16) __nv_bfloat16 s_lo[32][264];

    const int k = blockIdx.y;
    const int n = blockIdx.z;
    const int p0 = blockIdx.x * 32;
    const int tid = threadIdx.x;
    const int lane = tid & 31, wrp = tid >> 5;

    if (tid < 32) {
        int p = p0 + tid;
        int h = p >> 6, w = p & 63;
        const float* offn = offs + (size_t)n * 18 * HW;
        float dy = offn[(size_t)(2 * k) * HW + p];
        float dx = offn[(size_t)(2 * k + 1) * HW + p];
        float mk = mask[((size_t)n * 9 + k) * HW + p];
        float y = (float)(h - 1 + k / 3) + dy;
        float xx = (float)(w - 1 + k % 3) + dx;
        float y0f = floorf(y), x0f = floorf(xx);
        float ly = y - y0f, lx = xx - x0f;
        int y0 = (int)y0f, x0 = (int)x0f;
        int y1 = y0 + 1, x1 = x0 + 1;
        bool vy0 = (y0 >= 0) & (y0 < HH);
        bool vy1 = (y1 >= 0) & (y1 < HH);
        bool vx0 = (x0 >= 0) & (x0 < WW);
        bool vx1 = (x1 >= 0) & (x1 < WW);
        s_w[0][tid] = (vy0 & vx0) ? (1.f - ly) * (1.f - lx) * mk : 0.f;
        s_w[1][tid] = (vy0 & vx1) ? (1.f - ly) * lx * mk : 0.f;
        s_w[2][tid] = (vy1 & vx0) ? ly * (1.f - lx) * mk : 0.f;
        s_w[3][tid] = (vy1 & vx1) ? ly * lx * mk : 0.f;
        s_i[0][tid] = (vy0 & vx0) ? y0 * WW + x0 : 0;
        s_i[1][tid] = (vy0 & vx1) ? y0 * WW + x1 : 0;
        s_i[2][tid] = (vy1 & vx0) ? y1 * WW + x0 : 0;
        s_i[3][tid] = (vy1 & vx1) ? y1 * WW + x1 : 0;
    }
    __syncthreads();

    {
        const int pl = lane;
        const float w00 = s_w[0][pl], w01 = s_w[1][pl], w10 = s_w[2][pl], w11 = s_w[3][pl];
        const float* src = xT + (size_t)n * HW * CIN;
        const float* r00 = src + (size_t)s_i[0][pl] * CIN;
        const float* r01 = src + (size_t)s_i[1][pl] * CIN;
        const float* r10 = src + (size_t)s_i[2][pl] * CIN;
        const float* r11 = src + (size_t)s_i[3][pl] * CIN;
#pragma unroll
        for (int j8 = 0; j8 < 4; j8++) {
            int c8 = wrp * 32 + j8 * 8;
            float a[8], b[8], c[8], d[8];
            *reinterpret_cast<float4*>(a) = *reinterpret_cast<const float4*>(r00 + c8);
            *reinterpret_cast<float4*>(a + 4) = *reinterpret_cast<const float4*>(r00 + c8 + 4);
            *reinterpret_cast<float4*>(b) = *reinterpret_cast<const float4*>(r01 + c8);
            *reinterpret_cast<float4*>(b + 4) = *reinterpret_cast<const float4*>(r01 + c8 + 4);
            *reinterpret_cast<float4*>(c) = *reinterpret_cast<const float4*>(r10 + c8);
            *reinterpret_cast<float4*>(c + 4) = *reinterpret_cast<const float4*>(r10 + c8 + 4);
            *reinterpret_cast<float4*>(d) = *reinterpret_cast<const float4*>(r11 + c8);
            *reinterpret_cast<float4*>(d + 4) = *reinterpret_cast<const float4*>(r11 + c8 + 4);
            __align__(16) __nv_bfloat16 hi[8];
            __align__(16) __nv_bfloat16 lo[8];
#pragma unroll
            for (int j = 0; j < 8; j++) {
                float v = w00 * a[j] + w01 * b[j] + w10 * c[j] + w11 * d[j];
                __nv_bfloat16 hb = __float2bfloat16(v);
                hi[j] = hb;
                lo[j] = __float2bfloat16(v - __bfloat162float(hb));
            }
            *reinterpret_cast<uint4*>(&s_hi[pl][c8]) = *reinterpret_cast<uint4*>(hi);
            *reinterpret_cast<uint4*>(&s_lo[pl][c8]) = *reinterpret_cast<uint4*>(lo);
        }
    }
    __syncthreads();

    __nv_bfloat16* base = colsT + (size_t)(n * HW + p0) * KPA + k * 256;
#pragma unroll
    for (int pass = 0; pass < 8; pass++) {
        int id = tid + pass * 256;
        int px = id >> 6;
        int rem = id & 63;
        int half = rem >> 5;
        int q = rem & 31;
        uint4 v = half ? *reinterpret_cast<uint4*>(&s_lo[px][q * 8])
                       : *reinterpret_cast<uint4*>(&s_hi[px][q * 8]);
        *reinterpret_cast<uint4*>(base + (size_t)px * KPA + half * 2304 + q * 8) = v;
    }
}

// ---------------------------------------------------------------------------
// Stage-3 HMMA GEMM (3-stage cp.async pipeline)
// ---------------------------------------------------------------------------
#define ABYTES 16384
#define BBYTES 32768
#define STAGEB (ABYTES + BBYTES)
#define NSTG 3

__global__ void __launch_bounds__(256, 1)
hmma_gemm(const __nv_bfloat16* __restrict__ colsT,
          const __nv_bfloat16* __restrict__ wbf,
          const float* __restrict__ bias, float* __restrict__ out) {
    extern __shared__ char smem[];
    const uint32_t sb = smem_u32(smem);
    const int tid = threadIdx.x;
    const int wid = tid >> 5, lane = tid & 31;
    const int wm = wid >> 2, wn = wid & 3;
    const int p0 = blockIdx.x * 128;
    const int n = blockIdx.z;

    const char* Ag = (const char*)(colsT + (size_t)(n * HW + p0) * KPA);
    const char* Bg = (const char*)wbf;

    float acc[4][8][4];
#pragma unroll
    for (int i = 0; i < 4; i++)
#pragma unroll
        for (int j = 0; j < 8; j++)
#pragma unroll
            for (int r = 0; r < 4; r++) acc[i][j][r] = 0.f;

    auto load_chunk = [&](int kt, int buf) {
        int ktA = (kt < 72) ? kt : kt - 72;
        uint32_t dA = sb + buf * STAGEB;
        uint32_t dB = dA + ABYTES;
#pragma unroll
        for (int u = 0; u < 4; u++) {
            int idx = tid + u * 256;
            int row = idx >> 3, c = idx & 7;
            cp_async16(dA + row * 128 + ((c ^ (row & 7)) << 4),
                       Ag + (size_t)row * KROWA + ktA * 128 + c * 16);
        }
#pragma unroll
        for (int u = 0; u < 8; u++) {
            int idx = tid + u * 256;
            int row = idx >> 3, c = idx & 7;
            cp_async16(dB + row * 128 + ((c ^ (row & 7)) << 4),
                       Bg + (size_t)row * KROWW + kt * 128 + c * 16);
        }
        cp_commit();
    };

    auto compute_chunk = [&](int buf) {
        uint32_t Ab = sb + buf * STAGEB;
        uint32_t Bb = Ab + ABYTES;
        const int rbase = ((lane >> 3) & 1) * 8 + (lane & 7);
        const int chi = (lane >> 4);
#pragma unroll
        for (int ks = 0; ks < 4; ks++) {
            int c = ks * 2 + chi;
            uint32_t af[4][4], bf[4][4];
#pragma unroll
            for (int i = 0; i < 4; i++) {
                int row = wm * 64 + i * 16 + rbase;
                ldsm_x4(af[i], Ab + row * 128 + ((c ^ (row & 7)) << 4));
            }
#pragma unroll
            for (int j = 0; j < 4; j++) {
                int row = wn * 64 + j * 16 + rbase;
                ldsm_x4(bf[j], Bb + row * 128 + ((c ^ (row & 7)) << 4));
            }
#pragma unroll
            for (int i = 0; i < 4; i++)
#pragma unroll
                for (int j = 0; j < 4; j++)
#pragma unroll
                    for (int s = 0; s < 2; s++)
                        mma16816(acc[i][j * 2 + s], af[i], bf[j][s], bf[j][s + 2]);
        }
    };

    load_chunk(0, 0);
    load_chunk(1, 1);
    for (int kt = 0; kt < KCHUNKS; kt++) {
        int buf = kt % NSTG;
        if (kt + 1 < KCHUNKS) cp_wait<1>(); else cp_wait<0>();
        __syncthreads();
        if (kt + 2 < KCHUNKS) load_chunk(kt + 2, (kt + 2) % NSTG);
        compute_chunk(buf);
    }

#pragma unroll
    for (int i = 0; i < 4; i++) {
        int m = wm * 64 + i * 16 + (lane >> 2);
#pragma unroll
        for (int j = 0; j < 4; j++)
#pragma unroll
            for (int s = 0; s < 2; s++) {
                int cout = wn * 64 + j * 16 + s * 8 + (lane & 3) * 2;
                float b0 = bias[cout], b1 = bias[cout + 1];
                float* o = out + ((size_t)n * COUT + cout) * HW + p0;
                const float* a = acc[i][j * 2 + s];
                o[m]          = a[0] + b0;
                o[HW + m]     = a[1] + b1;
                o[m + 8]      = a[2] + b0;
                o[HW + m + 8] = a[3] + b1;
            }
    }
}

// ---------------------------------------------------------------------------
extern "C" void kernel_launch(void* const* d_in, const int* in_sizes, int n_in,
                              void* d_out, int out_size) {
    const float* x      = (const float*)d_in[0];
    const float* depth  = (const float*)d_in[1];
    const float* weight = (const float*)d_in[2];
    const float* bias   = (const float*)d_in[3];
    const float* off_w  = (const float*)d_in[4];
    const float* off_b  = (const float*)d_in[5];
    const float* mask_w = (const float*)d_in[6];
    const float* mask_b = (const float*)d_in[7];
    float* out = (float*)d_out;

    void *po, *pm, *pcb, *pwb, *pxt, *pdt, *pxd, *pw1;
    cudaGetSymbolAddress(&po, g_offsets);
    cudaGetSymbolAddress(&pm, g_mask);
    cudaGetSymbolAddress(&pcb, g_colsbf);
    cudaGetSymbolAddress(&pwb, g_wbf);
    cudaGetSymbolAddress(&pxt, g_xT);
    cudaGetSymbolAddress(&pdt, g_dT);
    cudaGetSymbolAddress(&pxd, g_xdbf);
    cudaGetSymbolAddress(&pw1, g_ws1);
    float* offsets = (float*)po;
    float* maskbuf = (float*)pm;
    __nv_bfloat16* colsbf = (__nv_bfloat16*)pcb;
    __nv_bfloat16* wbf = (__nv_bfloat16*)pwb;
    float* xT = (float*)pxt;
    float* dT = (float*)pdt;
    __nv_bfloat16* xdbf = (__nv_bfloat16*)pxd;
    __nv_bfloat16* ws1 = (__nv_bfloat16*)pw1;

    // Prep
    prep_w_kernel<<<COUT, 256>>>(weight, wbf);
    prep_s1w<<<32, 320>>>(off_w, ws1);
    transpose_cp<<<dim3(HW / 32, CIN / 32, NB), dim3(32, 8)>>>(x, xT, CIN);
    transpose_cp<<<dim3(HW / 32, DC / 32, NB), dim3(32, 8)>>>(depth, dT, DC);
    build_xdbf<<<dim3(HW / 32, NB), 256>>>(xT, dT, xdbf);

    static int smem_set = 0;
    if (!smem_set) {
        cudaFuncSetAttribute(s1_hmma, cudaFuncAttributeMaxDynamicSharedMemorySize,
                             3 * S1_STG);
        cudaFuncSetAttribute(hmma_gemm, cudaFuncAttributeMaxDynamicSharedMemorySize,
                             NSTG * STAGEB);
        smem_set = 1;
    }

    // Stage 1: offset conv via implicit-im2col HMMA GEMM
    s1_hmma<<<dim3(HW / 128, 1, NB), 256, 3 * S1_STG>>>(xdbf, ws1, off_b, offsets);

    // Stage 2: fused mask = sigmoid(deform_conv(depth, offset))
    fused_mask<<<dim3(HW / 8, NB), 256>>>(dT, offsets, mask_w, mask_b, maskbuf);

    // Stage 3: modulated deformable conv via HMMA bf16 split-K GEMM
    deform_im2col_bf16_v2<<<dim3(HW / 32, 9, NB), 256>>>(xT, offsets, maskbuf, colsbf);
    hmma_gemm<<<dim3(HW / 128, 1, NB), 256, NSTG * STAGEB>>>(colsbf, wbf, bias, out);
}

// round 10
// speedup vs baseline: 3.4889x; 1.5414x over previous
#include <cuda_runtime.h>
#include <cuda_bf16.h>
#include <cstdint>
#include <math.h>

#define NB 4
#define HH 64
#define WW 64
#define HW 4096
#define CIN 256
#define DC 64
#define COUT 256
#define KPA 4608               /* stage-3 A cols: [hi | lo] */
#define KPW 6912               /* stage-3 W cols: [hi | hi | lo] */
#define KROWA (KPA * 2)
#define KROWW (KPW * 2)
#define KCHUNKS 108            /* stage-3: KPW / 64 */
#define KPAIRS 54
#define S1K 8640               /* stage-1 W cols: 3 * 2880 */
#define S1CHUNKS 135           /* S1K / 64 */

// ---------------- device scratch ----------------
__device__ float g_offsets[(size_t)NB * 18 * HW];
__device__ float g_mask[(size_t)NB * 9 * HW];
__device__ float g_xT[(size_t)NB * HW * CIN];              // x NHWC f32
__device__ float g_dT[(size_t)NB * HW * DC];               // depth NHWC f32
__device__ __nv_bfloat16 g_xdbf[(size_t)NB * HW * 640];    // cat(x,d) [hi320|lo320]
__device__ __nv_bfloat16 g_ws1[(size_t)32 * S1K];          // off_w split, 32 rows
__device__ __nv_bfloat16 g_colsbf[(size_t)NB * HW * KPA];
__device__ __nv_bfloat16 g_wbf[(size_t)COUT * KPW];

// ---------------- PTX helpers ----------------
__device__ __forceinline__ uint32_t smem_u32(const void* p) {
    uint32_t a;
    asm("{ .reg .u64 t; cvta.to.shared.u64 t, %1; cvt.u32.u64 %0, t; }"
        : "=r"(a) : "l"(p));
    return a;
}
__device__ __forceinline__ void cp_async16(uint32_t dst, const void* src) {
    asm volatile("cp.async.cg.shared.global [%0], [%1], 16;"
                 :: "r"(dst), "l"(src) : "memory");
}
__device__ __forceinline__ void cp_async16_z(uint32_t dst, const void* src, bool pred) {
    int sz = pred ? 16 : 0;
    asm volatile("cp.async.cg.shared.global [%0], [%1], 16, %2;"
                 :: "r"(dst), "l"(src), "r"(sz) : "memory");
}
__device__ __forceinline__ void cp_commit() {
    asm volatile("cp.async.commit_group;" ::: "memory");
}
template <int N>
__device__ __forceinline__ void cp_wait() {
    asm volatile("cp.async.wait_group %0;" :: "n"(N) : "memory");
}
__device__ __forceinline__ void ldsm_x4(uint32_t (&r)[4], uint32_t addr) {
    asm volatile("ldmatrix.sync.aligned.m8n8.x4.shared.b16 {%0,%1,%2,%3}, [%4];"
                 : "=r"(r[0]), "=r"(r[1]), "=r"(r[2]), "=r"(r[3]) : "r"(addr));
}
__device__ __forceinline__ void mma16816(float (&d)[4], const uint32_t (&a)[4],
                                         uint32_t b0, uint32_t b1) {
    asm volatile(
        "mma.sync.aligned.m16n8k16.row.col.f32.bf16.bf16.f32 "
        "{%0,%1,%2,%3}, {%4,%5,%6,%7}, {%8,%9}, {%0,%1,%2,%3};"
        : "+f"(d[0]), "+f"(d[1]), "+f"(d[2]), "+f"(d[3])
        : "r"(a[0]), "r"(a[1]), "r"(a[2]), "r"(a[3]), "r"(b0), "r"(b1));
}

// ---------------------------------------------------------------------------
// Transpose: src[n][c][p] -> dst[n][p][c]
// ---------------------------------------------------------------------------
__global__ void transpose_cp(const float* __restrict__ src, float* __restrict__ dst,
                             int C) {
    __shared__ float t[32][33];
    int n = blockIdx.z;
    int p0 = blockIdx.x * 32, c0 = blockIdx.y * 32;
    int tx = threadIdx.x, ty = threadIdx.y;
#pragma unroll
    for (int j = 0; j < 32; j += 8)
        t[ty + j][tx] = src[((size_t)n * C + c0 + ty + j) * HW + p0 + tx];
    __syncthreads();
#pragma unroll
    for (int j = 0; j < 32; j += 8)
        dst[((size_t)n * HW + p0 + ty + j) * C + c0 + tx] = t[tx][ty + j];
}

// ---------------------------------------------------------------------------
// Build xdbf[n][p][hi 0..320 | lo 320..640] from xT/dT
// ---------------------------------------------------------------------------
__global__ void __launch_bounds__(256)
build_xdbf(const float* __restrict__ xT, const float* __restrict__ dT,
           __nv_bfloat16* __restrict__ xd) {
    int n = blockIdx.y;
    int p0 = blockIdx.x * 32;
    int tid = threadIdx.x;
#pragma unroll
    for (int pass = 0; pass < 5; pass++) {
        int id = tid + pass * 256;
        int px = id / 40;
        int c8 = (id - px * 40) * 8;
        size_t prow = (size_t)n * HW + p0 + px;
        const float* src = (c8 < CIN) ? xT + prow * CIN + c8
                                      : dT + prow * DC + (c8 - CIN);
        float v[8];
        *reinterpret_cast<float4*>(v) = *reinterpret_cast<const float4*>(src);
        *reinterpret_cast<float4*>(v + 4) = *reinterpret_cast<const float4*>(src + 4);
        __align__(16) __nv_bfloat16 hi[8];
        __align__(16) __nv_bfloat16 lo[8];
#pragma unroll
        for (int j = 0; j < 8; j++) {
            __nv_bfloat16 hb = __float2bfloat16(v[j]);
            hi[j] = hb;
            lo[j] = __float2bfloat16(v[j] - __bfloat162float(hb));
        }
        __nv_bfloat16* dst = xd + prow * 640;
        *reinterpret_cast<uint4*>(dst + c8) = *reinterpret_cast<uint4*>(hi);
        *reinterpret_cast<uint4*>(dst + 320 + c8) = *reinterpret_cast<uint4*>(lo);
    }
}

// ---------------------------------------------------------------------------
// Weight preps
// ---------------------------------------------------------------------------
__global__ void prep_w_kernel(const float* __restrict__ w,
                              __nv_bfloat16* __restrict__ wbf) {
    int cout = blockIdx.x;
    int c = threadIdx.x;
#pragma unroll
    for (int k = 0; k < 9; k++) {
        float v = w[((size_t)cout * 256 + c) * 9 + k];
        __nv_bfloat16 hb = __float2bfloat16(v);
        __nv_bfloat16 lb = __float2bfloat16(v - __bfloat162float(hb));
        size_t b = (size_t)cout * KPW + k * 256 + c;
        wbf[b] = hb;
        wbf[b + 2304] = hb;
        wbf[b + 4608] = lb;
    }
}

__global__ void prep_s1w(const float* __restrict__ ow, __nv_bfloat16* __restrict__ ws) {
    int m = blockIdx.x;
    int c = threadIdx.x;
#pragma unroll
    for (int kk = 0; kk < 9; kk++) {
        float v = (m < 18) ? ow[((size_t)m * 320 + c) * 9 + kk] : 0.f;
        __nv_bfloat16 hb = __float2bfloat16(v);
        __nv_bfloat16 lb = __float2bfloat16(v - __bfloat162float(hb));
        size_t b = (size_t)m * S1K + kk * 320 + c;
        ws[b] = hb;
        ws[b + 2880] = hb;
        ws[b + 5760] = lb;
    }
}

// ---------------------------------------------------------------------------
// Stage-1 HMMA GEMM (implicit im2col)
// ---------------------------------------------------------------------------
#define S1_AB 16384
#define S1_BB 4096
#define S1_STG (S1_AB + S1_BB)

__global__ void __launch_bounds__(256, 1)
s1_hmma(const __nv_bfloat16* __restrict__ xd, const __nv_bfloat16* __restrict__ ws,
        const float* __restrict__ offb, float* __restrict__ offsets) {
    extern __shared__ char smem[];
    const uint32_t sb = smem_u32(smem);
    const int tid = threadIdx.x;
    const int wid = tid >> 5, lane = tid & 31;
    const int p0 = blockIdx.x * 128;
    const int n = blockIdx.z;
    const __nv_bfloat16* xdn = xd + (size_t)n * HW * 640;

    float acc[4][4];
#pragma unroll
    for (int i = 0; i < 4; i++)
#pragma unroll
        for (int r = 0; r < 4; r++) acc[i][r] = 0.f;

    auto load_chunk = [&](int kc, int buf) {
        int pass = kc / 45;
        int r = kc - pass * 45;
        int tap = r / 5;
        int c0 = (r - tap * 5) * 64;
        int ah = (pass == 1) ? 320 : 0;
        int dr = tap / 3 - 1, dc = tap % 3 - 1;
        uint32_t dA = sb + buf * S1_STG;
        uint32_t dB = dA + S1_AB;
#pragma unroll
        for (int u = 0; u < 4; u++) {
            int idx = tid + u * 256;
            int row = idx >> 3, q = idx & 7;
            int gp = p0 + row;
            int h = gp >> 6, w = gp & 63;
            int iy = h + dr, ix = w + dc;
            bool v = (iy >= 0) & (iy < HH) & (ix >= 0) & (ix < WW);
            int pn = v ? iy * WW + ix : 0;
            cp_async16_z(dA + row * 128 + ((q ^ (row & 7)) << 4),
                         xdn + (size_t)pn * 640 + ah + c0 + q * 8, v);
        }
        {
            int row = tid >> 3, q = tid & 7;
            cp_async16(dB + row * 128 + ((q ^ (row & 7)) << 4),
                       ws + (size_t)row * S1K + kc * 64 + q * 8);
        }
        cp_commit();
    };

    auto compute_chunk = [&](int buf) {
        uint32_t Ab = sb + buf * S1_STG;
        uint32_t Bb = Ab + S1_AB;
        const int rbase = ((lane >> 3) & 1) * 8 + (lane & 7);
        const int chi = (lane >> 4);
#pragma unroll
        for (int ks = 0; ks < 4; ks++) {
            int c = ks * 2 + chi;
            uint32_t af[4], bf[2][4];
            {
                int row = wid * 16 + rbase;
                ldsm_x4(af, Ab + row * 128 + ((c ^ (row & 7)) << 4));
            }
#pragma unroll
            for (int j = 0; j < 2; j++) {
                int row = j * 16 + rbase;
                ldsm_x4(bf[j], Bb + row * 128 + ((c ^ (row & 7)) << 4));
            }
#pragma unroll
            for (int j = 0; j < 2; j++)
#pragma unroll
                for (int s = 0; s < 2; s++)
                    mma16816(acc[j * 2 + s], af, bf[j][s], bf[j][s + 2]);
        }
    };

    load_chunk(0, 0);
    load_chunk(1, 1);
    for (int kc = 0; kc < S1CHUNKS; kc++) {
        int buf = kc % 3;
        if (kc + 1 < S1CHUNKS) cp_wait<1>(); else cp_wait<0>();
        __syncthreads();
        if (kc + 2 < S1CHUNKS) load_chunk(kc + 2, (kc + 2) % 3);
        compute_chunk(buf);
    }

#pragma unroll
    for (int j = 0; j < 2; j++)
#pragma unroll
        for (int s = 0; s < 2; s++) {
            int m = j * 16 + s * 8 + (lane & 3) * 2;
            if (m < 18) {
                float b0 = offb[m], b1 = offb[m + 1];
                int row = wid * 16 + (lane >> 2);
                float* o = offsets + ((size_t)n * 18 + m) * HW + p0;
                const float* a = acc[j * 2 + s];
                o[row]          = a[0] + b0;
                o[HW + row]     = a[1] + b1;
                o[row + 8]      = a[2] + b0;
                o[HW + row + 8] = a[3] + b1;
            }
        }
}

// ---------------------------------------------------------------------------
// Stage-2 FUSED: mask = sigmoid(deform_conv(depthT, offset) + mb)
// ---------------------------------------------------------------------------
__global__ void __launch_bounds__(256)
fused_mask(const float* __restrict__ depthT, const float* __restrict__ offs,
           const float* __restrict__ mw, const float* __restrict__ mb,
           float* __restrict__ maskbuf) {
    __shared__ float ws[9][9][64];
    __shared__ float sbias[9];
    const int tid = threadIdx.x;
    const int n = blockIdx.y;

    for (int i = tid; i < 5184; i += 256) {
        int m = i / 576;
        int rem = i - m * 576;
        int c = rem / 9;
        int k = rem - 9 * c;
        ws[k][m][c] = mw[i];
    }
    if (tid < 9) sbias[tid] = mb[tid];
    __syncthreads();

    const int wid = tid >> 5, lane = tid & 31;
    const int p = blockIdx.x * 8 + wid;
    const int h = p >> 6, w = p & 63;
    const float* dn = depthT + (size_t)n * HW * DC;
    const float* offn = offs + (size_t)n * 18 * HW;

    float acc[9];
#pragma unroll
    for (int m = 0; m < 9; m++) acc[m] = 0.f;

#pragma unroll
    for (int k = 0; k < 9; k++) {
        float dy = offn[(size_t)(2 * k) * HW + p];
        float dx = offn[(size_t)(2 * k + 1) * HW + p];
        float y = (float)(h - 1 + k / 3) + dy;
        float xx = (float)(w - 1 + k % 3) + dx;
        float y0f = floorf(y), x0f = floorf(xx);
        float ly = y - y0f, lx = xx - x0f;
        int y0 = (int)y0f, x0 = (int)x0f;
        int y1 = y0 + 1, x1 = x0 + 1;
        bool vy0 = (y0 >= 0) & (y0 < HH);
        bool vy1 = (y1 >= 0) & (y1 < HH);
        bool vx0 = (x0 >= 0) & (x0 < WW);
        bool vx1 = (x1 >= 0) & (x1 < WW);
        float w00 = (vy0 & vx0) ? (1.f - ly) * (1.f - lx) : 0.f;
        float w01 = (vy0 & vx1) ? (1.f - ly) * lx : 0.f;
        float w10 = (vy1 & vx0) ? ly * (1.f - lx) : 0.f;
        float w11 = (vy1 & vx1) ? ly * lx : 0.f;
        int i00 = (vy0 & vx0) ? y0 * WW + x0 : 0;
        int i01 = (vy0 & vx1) ? y0 * WW + x1 : 0;
        int i10 = (vy1 & vx0) ? y1 * WW + x0 : 0;
        int i11 = (vy1 & vx1) ? y1 * WW + x1 : 0;
        int cc = lane * 2;
        float2 a = *reinterpret_cast<const float2*>(dn + (size_t)i00 * DC + cc);
        float2 b = *reinterpret_cast<const float2*>(dn + (size_t)i01 * DC + cc);
        float2 cv = *reinterpret_cast<const float2*>(dn + (size_t)i10 * DC + cc);
        float2 d = *reinterpret_cast<const float2*>(dn + (size_t)i11 * DC + cc);
        float v0 = w00 * a.x + w01 * b.x + w10 * cv.x + w11 * d.x;
        float v1 = w00 * a.y + w01 * b.y + w10 * cv.y + w11 * d.y;
#pragma unroll
        for (int m = 0; m < 9; m++) {
            float2 wv = *reinterpret_cast<const float2*>(&ws[k][m][cc]);
            acc[m] += wv.x * v0 + wv.y * v1;
        }
    }

#pragma unroll
    for (int m = 0; m < 9; m++) {
#pragma unroll
        for (int off = 16; off > 0; off >>= 1)
            acc[m] += __shfl_xor_sync(0xFFFFFFFFu, acc[m], off);
    }
    if (lane == 0) {
        float* mp = maskbuf + (size_t)n * 9 * HW + p;
#pragma unroll
        for (int m = 0; m < 9; m++) {
            float v = acc[m] + sbias[m];
            mp[(size_t)m * HW] = 1.f / (1.f + expf(-v));
        }
    }
}

// ---------------------------------------------------------------------------
// Stage-3 deformable im2col v3: WARP-PER-PIXEL, fully coalesced.
// Lanes = 8-channel slices; 4 corner reads per tap are contiguous 1KB
// warp transactions; output per pixel is contiguous (no smem staging).
// grid (HW/8, NB), 256 threads (8 warps = 8 pixels).
// ---------------------------------------------------------------------------
__global__ void __launch_bounds__(256)
deform_im2col_bf16_v3(const float* __restrict__ xT, const float* __restrict__ offs,
                      const float* __restrict__ mask,
                      __nv_bfloat16* __restrict__ colsT) {
    const int tid = threadIdx.x;
    const int wid = tid >> 5, lane = tid & 31;
    const int n = blockIdx.y;
    const int p = blockIdx.x * 8 + wid;
    const int h = p >> 6, w = p & 63;
    const float* offn = offs + (size_t)n * 18 * HW;
    const float* maskn = mask + (size_t)n * 9 * HW;
    const float* src = xT + (size_t)n * HW * CIN;
    __nv_bfloat16* outp = colsT + ((size_t)n * HW + p) * KPA;
    const int cc = lane * 8;

#pragma unroll
    for (int k = 0; k < 9; k++) {
        float dy = offn[(size_t)(2 * k) * HW + p];
        float dx = offn[(size_t)(2 * k + 1) * HW + p];
        float mk = maskn[(size_t)k * HW + p];
        float y = (float)(h - 1 + k / 3) + dy;
        float xx = (float)(w - 1 + k % 3) + dx;
        float y0f = floorf(y), x0f = floorf(xx);
        float ly = y - y0f, lx = xx - x0f;
        int y0 = (int)y0f, x0 = (int)x0f;
        int y1 = y0 + 1, x1 = x0 + 1;
        bool vy0 = (y0 >= 0) & (y0 < HH);
        bool vy1 = (y1 >= 0) & (y1 < HH);
        bool vx0 = (x0 >= 0) & (x0 < WW);
        bool vx1 = (x1 >= 0) & (x1 < WW);
        float w00 = (vy0 & vx0) ? (1.f - ly) * (1.f - lx) * mk : 0.f;
        float w01 = (vy0 & vx1) ? (1.f - ly) * lx * mk : 0.f;
        float w10 = (vy1 & vx0) ? ly * (1.f - lx) * mk : 0.f;
        float w11 = (vy1 & vx1) ? ly * lx * mk : 0.f;
        int i00 = (vy0 & vx0) ? y0 * WW + x0 : 0;
        int i01 = (vy0 & vx1) ? y0 * WW + x1 : 0;
        int i10 = (vy1 & vx0) ? y1 * WW + x0 : 0;
        int i11 = (vy1 & vx1) ? y1 * WW + x1 : 0;

        const float* r00 = src + (size_t)i00 * CIN + cc;
        const float* r01 = src + (size_t)i01 * CIN + cc;
        const float* r10 = src + (size_t)i10 * CIN + cc;
        const float* r11 = src + (size_t)i11 * CIN + cc;
        float a[8], b[8], c[8], d[8];
        *reinterpret_cast<float4*>(a)     = *reinterpret_cast<const float4*>(r00);
        *reinterpret_cast<float4*>(a + 4) = *reinterpret_cast<const float4*>(r00 + 4);
        *reinterpret_cast<float4*>(b)     = *reinterpret_cast<const float4*>(r01);
        *reinterpret_cast<float4*>(b + 4) = *reinterpret_cast<const float4*>(r01 + 4);
        *reinterpret_cast<float4*>(c)     = *reinterpret_cast<const float4*>(r10);
        *reinterpret_cast<float4*>(c + 4) = *reinterpret_cast<const float4*>(r10 + 4);
        *reinterpret_cast<float4*>(d)     = *reinterpret_cast<const float4*>(r11);
        *reinterpret_cast<float4*>(d + 4) = *reinterpret_cast<const float4*>(r11 + 4);

        __align__(16) __nv_bfloat16 hi[8];
        __align__(16) __nv_bfloat16 lo[8];
#pragma unroll
        for (int j = 0; j < 8; j++) {
            float v = w00 * a[j] + w01 * b[j] + w10 * c[j] + w11 * d[j];
            __nv_bfloat16 hb = __float2bfloat16(v);
            hi[j] = hb;
            lo[j] = __float2bfloat16(v - __bfloat162float(hb));
        }
        *reinterpret_cast<uint4*>(outp + k * 256 + cc) = *reinterpret_cast<uint4*>(hi);
        *reinterpret_cast<uint4*>(outp + 2304 + k * 256 + cc) = *reinterpret_cast<uint4*>(lo);
    }
}

// ---------------------------------------------------------------------------
// Stage-3 HMMA GEMM: BK=128 (two 64-col sub-chunks per stage), 2-stage.
// ---------------------------------------------------------------------------
#define ABYTES 16384
#define BBYTES 32768
#define STAGEB (ABYTES + BBYTES)
#define STAGE2B (2 * STAGEB)   /* 96 KB per stage */

__global__ void __launch_bounds__(256, 1)
hmma_gemm(const __nv_bfloat16* __restrict__ colsT,
          const __nv_bfloat16* __restrict__ wbf,
          const float* __restrict__ bias, float* __restrict__ out) {
    extern __shared__ char smem[];
    const uint32_t sb = smem_u32(smem);
    const int tid = threadIdx.x;
    const int wid = tid >> 5, lane = tid & 31;
    const int wm = wid >> 2, wn = wid & 3;
    const int p0 = blockIdx.x * 128;
    const int n = blockIdx.z;

    const char* Ag = (const char*)(colsT + (size_t)(n * HW + p0) * KPA);
    const char* Bg = (const char*)wbf;

    float acc[4][8][4];
#pragma unroll
    for (int i = 0; i < 4; i++)
#pragma unroll
        for (int j = 0; j < 8; j++)
#pragma unroll
            for (int r = 0; r < 4; r++) acc[i][j][r] = 0.f;

    // load one stage = chunks {2t, 2t+1}; single commit
    auto load_stage = [&](int t, int s) {
#pragma unroll
        for (int half = 0; half < 2; half++) {
            int kt = 2 * t + half;
            int ktA = (kt < 72) ? kt : kt - 72;
            uint32_t dA = sb + s * STAGE2B + half * STAGEB;
            uint32_t dB = dA + ABYTES;
#pragma unroll
            for (int u = 0; u < 4; u++) {
                int idx = tid + u * 256;
                int row = idx >> 3, c = idx & 7;
                cp_async16(dA + row * 128 + ((c ^ (row & 7)) << 4),
                           Ag + (size_t)row * KROWA + ktA * 128 + c * 16);
            }
#pragma unroll
            for (int u = 0; u < 8; u++) {
                int idx = tid + u * 256;
                int row = idx >> 3, c = idx & 7;
                cp_async16(dB + row * 128 + ((c ^ (row & 7)) << 4),
                           Bg + (size_t)row * KROWW + kt * 128 + c * 16);
            }
        }
        cp_commit();
    };

    auto compute_stage = [&](int s) {
        const int rbase = ((lane >> 3) & 1) * 8 + (lane & 7);
        const int chi = (lane >> 4);
#pragma unroll
        for (int half = 0; half < 2; half++) {
            uint32_t Ab = sb + s * STAGE2B + half * STAGEB;
            uint32_t Bb = Ab + ABYTES;
#pragma unroll
            for (int ks = 0; ks < 4; ks++) {
                int c = ks * 2 + chi;
                uint32_t af[4][4], bf[4][4];
#pragma unroll
                for (int i = 0; i < 4; i++) {
                    int row = wm * 64 + i * 16 + rbase;
                    ldsm_x4(af[i], Ab + row * 128 + ((c ^ (row & 7)) << 4));
                }
#pragma unroll
                for (int j = 0; j < 4; j++) {
                    int row = wn * 64 + j * 16 + rbase;
                    ldsm_x4(bf[j], Bb + row * 128 + ((c ^ (row & 7)) << 4));
                }
#pragma unroll
                for (int i = 0; i < 4; i++)
#pragma unroll
                    for (int j = 0; j < 4; j++)
#pragma unroll
                        for (int s2 = 0; s2 < 2; s2++)
                            mma16816(acc[i][j * 2 + s2], af[i], bf[j][s2], bf[j][s2 + 2]);
            }
        }
    };

    load_stage(0, 0);
    for (int t = 0; t < KPAIRS; t++) {
        cp_wait<0>();
        __syncthreads();
        if (t + 1 < KPAIRS) load_stage(t + 1, (t + 1) & 1);
        compute_stage(t & 1);
    }

#pragma unroll
    for (int i = 0; i < 4; i++) {
        int m = wm * 64 + i * 16 + (lane >> 2);
#pragma unroll
        for (int j = 0; j < 4; j++)
#pragma unroll
            for (int s = 0; s < 2; s++) {
                int cout = wn * 64 + j * 16 + s * 8 + (lane & 3) * 2;
                float b0 = bias[cout], b1 = bias[cout + 1];
                float* o = out + ((size_t)n * COUT + cout) * HW + p0;
                const float* a = acc[i][j * 2 + s];
                o[m]          = a[0] + b0;
                o[HW + m]     = a[1] + b1;
                o[m + 8]      = a[2] + b0;
                o[HW + m + 8] = a[3] + b1;
            }
    }
}

// ---------------------------------------------------------------------------
extern "C" void kernel_launch(void* const* d_in, const int* in_sizes, int n_in,
                              void* d_out, int out_size) {
    const float* x      = (const float*)d_in[0];
    const float* depth  = (const float*)d_in[1];
    const float* weight = (const float*)d_in[2];
    const float* bias   = (const float*)d_in[3];
    const float* off_w  = (const float*)d_in[4];
    const float* off_b  = (const float*)d_in[5];
    const float* mask_w = (const float*)d_in[6];
    const float* mask_b = (const float*)d_in[7];
    float* out = (float*)d_out;

    void *po, *pm, *pcb, *pwb, *pxt, *pdt, *pxd, *pw1;
    cudaGetSymbolAddress(&po, g_offsets);
    cudaGetSymbolAddress(&pm, g_mask);
    cudaGetSymbolAddress(&pcb, g_colsbf);
    cudaGetSymbolAddress(&pwb, g_wbf);
    cudaGetSymbolAddress(&pxt, g_xT);
    cudaGetSymbolAddress(&pdt, g_dT);
    cudaGetSymbolAddress(&pxd, g_xdbf);
    cudaGetSymbolAddress(&pw1, g_ws1);
    float* offsets = (float*)po;
    float* maskbuf = (float*)pm;
    __nv_bfloat16* colsbf = (__nv_bfloat16*)pcb;
    __nv_bfloat16* wbf = (__nv_bfloat16*)pwb;
    float* xT = (float*)pxt;
    float* dT = (float*)pdt;
    __nv_bfloat16* xdbf = (__nv_bfloat16*)pxd;
    __nv_bfloat16* ws1 = (__nv_bfloat16*)pw1;

    // Prep
    prep_w_kernel<<<COUT, 256>>>(weight, wbf);
    prep_s1w<<<32, 320>>>(off_w, ws1);
    transpose_cp<<<dim3(HW / 32, CIN / 32, NB), dim3(32, 8)>>>(x, xT, CIN);
    transpose_cp<<<dim3(HW / 32, DC / 32, NB), dim3(32, 8)>>>(depth, dT, DC);
    build_xdbf<<<dim3(HW / 32, NB), 256>>>(xT, dT, xdbf);

    static int smem_set = 0;
    if (!smem_set) {
        cudaFuncSetAttribute(s1_hmma, cudaFuncAttributeMaxDynamicSharedMemorySize,
                             3 * S1_STG);
        cudaFuncSetAttribute(hmma_gemm, cudaFuncAttributeMaxDynamicSharedMemorySize,
                             2 * STAGE2B);
        smem_set = 1;
    }

    // Stage 1: offset conv via implicit-im2col HMMA GEMM
    s1_hmma<<<dim3(HW / 128, 1, NB), 256, 3 * S1_STG>>>(xdbf, ws1, off_b, offsets);

    // Stage 2: fused mask = sigmoid(deform_conv(depth, offset))
    fused_mask<<<dim3(HW / 8, NB), 256>>>(dT, offsets, mask_w, mask_b, maskbuf);

    // Stage 3: modulated deformable conv via HMMA bf16 split-K GEMM
    deform_im2col_bf16_v3<<<dim3(HW / 8, NB), 256>>>(xT, offsets, maskbuf, colsbf);
    hmma_gemm<<<dim3(HW / 128, 1, NB), 256, 2 * STAGE2B>>>(colsbf, wbf, bias, out);
}

// round 11
// speedup vs baseline: 5.2969x; 1.5182x over previous
#include <cuda_runtime.h>
#include <cuda_bf16.h>
#include <cuda_fp16.h>
#include <cstdint>
#include <math.h>

#define NB 4
#define HH 64
#define WW 64
#define HW 4096
#define CIN 256
#define DC 64
#define COUT 256
#define KP3 2304               /* stage-3 K: single-pass fp16 */
#define KROW3 (KP3 * 2)        /* 4608 bytes per row */
#define K3CHUNKS 36            /* KP3 / 64 */
#define K3PAIRS 18
#define S1K 8640               /* stage-1 W cols: 3 * 2880 (bf16 split) */
#define S1CHUNKS 135           /* S1K / 64 */

// ---------------- device scratch ----------------
__device__ float g_offsets[(size_t)NB * 18 * HW];
__device__ float g_mask[(size_t)NB * 9 * HW];
__device__ float g_xT[(size_t)NB * HW * CIN];              // x NHWC f32
__device__ float g_dT[(size_t)NB * HW * DC];               // depth NHWC f32
__device__ __nv_bfloat16 g_xdbf[(size_t)NB * HW * 640];    // cat(x,d) [hi320|lo320]
__device__ __nv_bfloat16 g_ws1[(size_t)32 * S1K];          // off_w split, 32 rows
__device__ __half g_colsh[(size_t)NB * HW * KP3];          // 75 MB fp16 cols
__device__ __half g_wh[(size_t)COUT * KP3];                // fp16 weights

// ---------------- PTX helpers ----------------
__device__ __forceinline__ uint32_t smem_u32(const void* p) {
    uint32_t a;
    asm("{ .reg .u64 t; cvta.to.shared.u64 t, %1; cvt.u32.u64 %0, t; }"
        : "=r"(a) : "l"(p));
    return a;
}
__device__ __forceinline__ void cp_async16(uint32_t dst, const void* src) {
    asm volatile("cp.async.cg.shared.global [%0], [%1], 16;"
                 :: "r"(dst), "l"(src) : "memory");
}
__device__ __forceinline__ void cp_async16_z(uint32_t dst, const void* src, bool pred) {
    int sz = pred ? 16 : 0;
    asm volatile("cp.async.cg.shared.global [%0], [%1], 16, %2;"
                 :: "r"(dst), "l"(src), "r"(sz) : "memory");
}
__device__ __forceinline__ void cp_commit() {
    asm volatile("cp.async.commit_group;" ::: "memory");
}
template <int N>
__device__ __forceinline__ void cp_wait() {
    asm volatile("cp.async.wait_group %0;" :: "n"(N) : "memory");
}
__device__ __forceinline__ void ldsm_x4(uint32_t (&r)[4], uint32_t addr) {
    asm volatile("ldmatrix.sync.aligned.m8n8.x4.shared.b16 {%0,%1,%2,%3}, [%4];"
                 : "=r"(r[0]), "=r"(r[1]), "=r"(r[2]), "=r"(r[3]) : "r"(addr));
}
// bf16 variant (stage-1)
__device__ __forceinline__ void mma16816_bf(float (&d)[4], const uint32_t (&a)[4],
                                            uint32_t b0, uint32_t b1) {
    asm volatile(
        "mma.sync.aligned.m16n8k16.row.col.f32.bf16.bf16.f32 "
        "{%0,%1,%2,%3}, {%4,%5,%6,%7}, {%8,%9}, {%0,%1,%2,%3};"
        : "+f"(d[0]), "+f"(d[1]), "+f"(d[2]), "+f"(d[3])
        : "r"(a[0]), "r"(a[1]), "r"(a[2]), "r"(a[3]), "r"(b0), "r"(b1));
}
// fp16 variant (stage-3)
__device__ __forceinline__ void mma16816_f16(float (&d)[4], const uint32_t (&a)[4],
                                             uint32_t b0, uint32_t b1) {
    asm volatile(
        "mma.sync.aligned.m16n8k16.row.col.f32.f16.f16.f32 "
        "{%0,%1,%2,%3}, {%4,%5,%6,%7}, {%8,%9}, {%0,%1,%2,%3};"
        : "+f"(d[0]), "+f"(d[1]), "+f"(d[2]), "+f"(d[3])
        : "r"(a[0]), "r"(a[1]), "r"(a[2]), "r"(a[3]), "r"(b0), "r"(b1));
}

// ---------------------------------------------------------------------------
// Transpose: src[n][c][p] -> dst[n][p][c]
// ---------------------------------------------------------------------------
__global__ void transpose_cp(const float* __restrict__ src, float* __restrict__ dst,
                             int C) {
    __shared__ float t[32][33];
    int n = blockIdx.z;
    int p0 = blockIdx.x * 32, c0 = blockIdx.y * 32;
    int tx = threadIdx.x, ty = threadIdx.y;
#pragma unroll
    for (int j = 0; j < 32; j += 8)
        t[ty + j][tx] = src[((size_t)n * C + c0 + ty + j) * HW + p0 + tx];
    __syncthreads();
#pragma unroll
    for (int j = 0; j < 32; j += 8)
        dst[((size_t)n * HW + p0 + ty + j) * C + c0 + tx] = t[tx][ty + j];
}

// ---------------------------------------------------------------------------
// Build xdbf[n][p][hi 0..320 | lo 320..640] from xT/dT (stage-1 input)
// ---------------------------------------------------------------------------
__global__ void __launch_bounds__(256)
build_xdbf(const float* __restrict__ xT, const float* __restrict__ dT,
           __nv_bfloat16* __restrict__ xd) {
    int n = blockIdx.y;
    int p0 = blockIdx.x * 32;
    int tid = threadIdx.x;
#pragma unroll
    for (int pass = 0; pass < 5; pass++) {
        int id = tid + pass * 256;
        int px = id / 40;
        int c8 = (id - px * 40) * 8;
        size_t prow = (size_t)n * HW + p0 + px;
        const float* src = (c8 < CIN) ? xT + prow * CIN + c8
                                      : dT + prow * DC + (c8 - CIN);
        float v[8];
        *reinterpret_cast<float4*>(v) = *reinterpret_cast<const float4*>(src);
        *reinterpret_cast<float4*>(v + 4) = *reinterpret_cast<const float4*>(src + 4);
        __align__(16) __nv_bfloat16 hi[8];
        __align__(16) __nv_bfloat16 lo[8];
#pragma unroll
        for (int j = 0; j < 8; j++) {
            __nv_bfloat16 hb = __float2bfloat16(v[j]);
            hi[j] = hb;
            lo[j] = __float2bfloat16(v[j] - __bfloat162float(hb));
        }
        __nv_bfloat16* dst = xd + prow * 640;
        *reinterpret_cast<uint4*>(dst + c8) = *reinterpret_cast<uint4*>(hi);
        *reinterpret_cast<uint4*>(dst + 320 + c8) = *reinterpret_cast<uint4*>(lo);
    }
}

// ---------------------------------------------------------------------------
// Weight preps
// ---------------------------------------------------------------------------
// weight[cout][c][k] f32 -> wh[cout][k*256 + c] fp16 (single pass)
__global__ void prep_w_kernel(const float* __restrict__ w,
                              __half* __restrict__ wh) {
    int cout = blockIdx.x;
    int c = threadIdx.x;
#pragma unroll
    for (int k = 0; k < 9; k++) {
        float v = w[((size_t)cout * 256 + c) * 9 + k];
        wh[(size_t)cout * KP3 + k * 256 + c] = __float2half(v);
    }
}

__global__ void prep_s1w(const float* __restrict__ ow, __nv_bfloat16* __restrict__ ws) {
    int m = blockIdx.x;
    int c = threadIdx.x;
#pragma unroll
    for (int kk = 0; kk < 9; kk++) {
        float v = (m < 18) ? ow[((size_t)m * 320 + c) * 9 + kk] : 0.f;
        __nv_bfloat16 hb = __float2bfloat16(v);
        __nv_bfloat16 lb = __float2bfloat16(v - __bfloat162float(hb));
        size_t b = (size_t)m * S1K + kk * 320 + c;
        ws[b] = hb;
        ws[b + 2880] = hb;
        ws[b + 5760] = lb;
    }
}

// ---------------------------------------------------------------------------
// Stage-1 HMMA GEMM (implicit im2col, bf16 3-pass)
// ---------------------------------------------------------------------------
#define S1_AB 16384
#define S1_BB 4096
#define S1_STG (S1_AB + S1_BB)

__global__ void __launch_bounds__(256, 1)
s1_hmma(const __nv_bfloat16* __restrict__ xd, const __nv_bfloat16* __restrict__ ws,
        const float* __restrict__ offb, float* __restrict__ offsets) {
    extern __shared__ char smem[];
    const uint32_t sb = smem_u32(smem);
    const int tid = threadIdx.x;
    const int wid = tid >> 5, lane = tid & 31;
    const int p0 = blockIdx.x * 128;
    const int n = blockIdx.z;
    const __nv_bfloat16* xdn = xd + (size_t)n * HW * 640;

    float acc[4][4];
#pragma unroll
    for (int i = 0; i < 4; i++)
#pragma unroll
        for (int r = 0; r < 4; r++) acc[i][r] = 0.f;

    auto load_chunk = [&](int kc, int buf) {
        int pass = kc / 45;
        int r = kc - pass * 45;
        int tap = r / 5;
        int c0 = (r - tap * 5) * 64;
        int ah = (pass == 1) ? 320 : 0;
        int dr = tap / 3 - 1, dc = tap % 3 - 1;
        uint32_t dA = sb + buf * S1_STG;
        uint32_t dB = dA + S1_AB;
#pragma unroll
        for (int u = 0; u < 4; u++) {
            int idx = tid + u * 256;
            int row = idx >> 3, q = idx & 7;
            int gp = p0 + row;
            int h = gp >> 6, w = gp & 63;
            int iy = h + dr, ix = w + dc;
            bool v = (iy >= 0) & (iy < HH) & (ix >= 0) & (ix < WW);
            int pn = v ? iy * WW + ix : 0;
            cp_async16_z(dA + row * 128 + ((q ^ (row & 7)) << 4),
                         xdn + (size_t)pn * 640 + ah + c0 + q * 8, v);
        }
        {
            int row = tid >> 3, q = tid & 7;
            cp_async16(dB + row * 128 + ((q ^ (row & 7)) << 4),
                       ws + (size_t)row * S1K + kc * 64 + q * 8);
        }
        cp_commit();
    };

    auto compute_chunk = [&](int buf) {
        uint32_t Ab = sb + buf * S1_STG;
        uint32_t Bb = Ab + S1_AB;
        const int rbase = ((lane >> 3) & 1) * 8 + (lane & 7);
        const int chi = (lane >> 4);
#pragma unroll
        for (int ks = 0; ks < 4; ks++) {
            int c = ks * 2 + chi;
            uint32_t af[4], bf[2][4];
            {
                int row = wid * 16 + rbase;
                ldsm_x4(af, Ab + row * 128 + ((c ^ (row & 7)) << 4));
            }
#pragma unroll
            for (int j = 0; j < 2; j++) {
                int row = j * 16 + rbase;
                ldsm_x4(bf[j], Bb + row * 128 + ((c ^ (row & 7)) << 4));
            }
#pragma unroll
            for (int j = 0; j < 2; j++)
#pragma unroll
                for (int s = 0; s < 2; s++)
                    mma16816_bf(acc[j * 2 + s], af, bf[j][s], bf[j][s + 2]);
        }
    };

    load_chunk(0, 0);
    load_chunk(1, 1);
    for (int kc = 0; kc < S1CHUNKS; kc++) {
        int buf = kc % 3;
        if (kc + 1 < S1CHUNKS) cp_wait<1>(); else cp_wait<0>();
        __syncthreads();
        if (kc + 2 < S1CHUNKS) load_chunk(kc + 2, (kc + 2) % 3);
        compute_chunk(buf);
    }

#pragma unroll
    for (int j = 0; j < 2; j++)
#pragma unroll
        for (int s = 0; s < 2; s++) {
            int m = j * 16 + s * 8 + (lane & 3) * 2;
            if (m < 18) {
                float b0 = offb[m], b1 = offb[m + 1];
                int row = wid * 16 + (lane >> 2);
                float* o = offsets + ((size_t)n * 18 + m) * HW + p0;
                const float* a = acc[j * 2 + s];
                o[row]          = a[0] + b0;
                o[HW + row]     = a[1] + b1;
                o[row + 8]      = a[2] + b0;
                o[HW + row + 8] = a[3] + b1;
            }
        }
}

// ---------------------------------------------------------------------------
// Stage-2 FUSED: mask = sigmoid(deform_conv(depthT, offset) + mb)
// ---------------------------------------------------------------------------
__global__ void __launch_bounds__(256)
fused_mask(const float* __restrict__ depthT, const float* __restrict__ offs,
           const float* __restrict__ mw, const float* __restrict__ mb,
           float* __restrict__ maskbuf) {
    __shared__ float ws[9][9][64];
    __shared__ float sbias[9];
    const int tid = threadIdx.x;
    const int n = blockIdx.y;

    for (int i = tid; i < 5184; i += 256) {
        int m = i / 576;
        int rem = i - m * 576;
        int c = rem / 9;
        int k = rem - 9 * c;
        ws[k][m][c] = mw[i];
    }
    if (tid < 9) sbias[tid] = mb[tid];
    __syncthreads();

    const int wid = tid >> 5, lane = tid & 31;
    const int p = blockIdx.x * 8 + wid;
    const int h = p >> 6, w = p & 63;
    const float* dn = depthT + (size_t)n * HW * DC;
    const float* offn = offs + (size_t)n * 18 * HW;

    float acc[9];
#pragma unroll
    for (int m = 0; m < 9; m++) acc[m] = 0.f;

#pragma unroll
    for (int k = 0; k < 9; k++) {
        float dy = offn[(size_t)(2 * k) * HW + p];
        float dx = offn[(size_t)(2 * k + 1) * HW + p];
        float y = (float)(h - 1 + k / 3) + dy;
        float xx = (float)(w - 1 + k % 3) + dx;
        float y0f = floorf(y), x0f = floorf(xx);
        float ly = y - y0f, lx = xx - x0f;
        int y0 = (int)y0f, x0 = (int)x0f;
        int y1 = y0 + 1, x1 = x0 + 1;
        bool vy0 = (y0 >= 0) & (y0 < HH);
        bool vy1 = (y1 >= 0) & (y1 < HH);
        bool vx0 = (x0 >= 0) & (x0 < WW);
        bool vx1 = (x1 >= 0) & (x1 < WW);
        float w00 = (vy0 & vx0) ? (1.f - ly) * (1.f - lx) : 0.f;
        float w01 = (vy0 & vx1) ? (1.f - ly) * lx : 0.f;
        float w10 = (vy1 & vx0) ? ly * (1.f - lx) : 0.f;
        float w11 = (vy1 & vx1) ? ly * lx : 0.f;
        int i00 = (vy0 & vx0) ? y0 * WW + x0 : 0;
        int i01 = (vy0 & vx1) ? y0 * WW + x1 : 0;
        int i10 = (vy1 & vx0) ? y1 * WW + x0 : 0;
        int i11 = (vy1 & vx1) ? y1 * WW + x1 : 0;
        int cc = lane * 2;
        float2 a = *reinterpret_cast<const float2*>(dn + (size_t)i00 * DC + cc);
        float2 b = *reinterpret_cast<const float2*>(dn + (size_t)i01 * DC + cc);
        float2 cv = *reinterpret_cast<const float2*>(dn + (size_t)i10 * DC + cc);
        float2 d = *reinterpret_cast<const float2*>(dn + (size_t)i11 * DC + cc);
        float v0 = w00 * a.x + w01 * b.x + w10 * cv.x + w11 * d.x;
        float v1 = w00 * a.y + w01 * b.y + w10 * cv.y + w11 * d.y;
#pragma unroll
        for (int m = 0; m < 9; m++) {
            float2 wv = *reinterpret_cast<const float2*>(&ws[k][m][cc]);
            acc[m] += wv.x * v0 + wv.y * v1;
        }
    }

#pragma unroll
    for (int m = 0; m < 9; m++) {
#pragma unroll
        for (int off = 16; off > 0; off >>= 1)
            acc[m] += __shfl_xor_sync(0xFFFFFFFFu, acc[m], off);
    }
    if (lane == 0) {
        float* mp = maskbuf + (size_t)n * 9 * HW + p;
#pragma unroll
        for (int m = 0; m < 9; m++) {
            float v = acc[m] + sbias[m];
            mp[(size_t)m * HW] = 1.f / (1.f + expf(-v));
        }
    }
}

// ---------------------------------------------------------------------------
// Stage-3 deformable im2col v4: warp-per-pixel, fp16 single output.
// grid (HW/8, NB), 256 threads (8 warps = 8 pixels).
// ---------------------------------------------------------------------------
__global__ void __launch_bounds__(256)
deform_im2col_f16(const float* __restrict__ xT, const float* __restrict__ offs,
                  const float* __restrict__ mask, __half* __restrict__ colsT) {
    const int tid = threadIdx.x;
    const int wid = tid >> 5, lane = tid & 31;
    const int n = blockIdx.y;
    const int p = blockIdx.x * 8 + wid;
    const int h = p >> 6, w = p & 63;
    const float* offn = offs + (size_t)n * 18 * HW;
    const float* maskn = mask + (size_t)n * 9 * HW;
    const float* src = xT + (size_t)n * HW * CIN;
    __half* outp = colsT + ((size_t)n * HW + p) * KP3;
    const int cc = lane * 8;

#pragma unroll
    for (int k = 0; k < 9; k++) {
        float dy = offn[(size_t)(2 * k) * HW + p];
        float dx = offn[(size_t)(2 * k + 1) * HW + p];
        float mk = maskn[(size_t)k * HW + p];
        float y = (float)(h - 1 + k / 3) + dy;
        float xx = (float)(w - 1 + k % 3) + dx;
        float y0f = floorf(y), x0f = floorf(xx);
        float ly = y - y0f, lx = xx - x0f;
        int y0 = (int)y0f, x0 = (int)x0f;
        int y1 = y0 + 1, x1 = x0 + 1;
        bool vy0 = (y0 >= 0) & (y0 < HH);
        bool vy1 = (y1 >= 0) & (y1 < HH);
        bool vx0 = (x0 >= 0) & (x0 < WW);
        bool vx1 = (x1 >= 0) & (x1 < WW);
        float w00 = (vy0 & vx0) ? (1.f - ly) * (1.f - lx) * mk : 0.f;
        float w01 = (vy0 & vx1) ? (1.f - ly) * lx * mk : 0.f;
        float w10 = (vy1 & vx0) ? ly * (1.f - lx) * mk : 0.f;
        float w11 = (vy1 & vx1) ? ly * lx * mk : 0.f;
        int i00 = (vy0 & vx0) ? y0 * WW + x0 : 0;
        int i01 = (vy0 & vx1) ? y0 * WW + x1 : 0;
        int i10 = (vy1 & vx0) ? y1 * WW + x0 : 0;
        int i11 = (vy1 & vx1) ? y1 * WW + x1 : 0;

        const float* r00 = src + (size_t)i00 * CIN + cc;
        const float* r01 = src + (size_t)i01 * CIN + cc;
        const float* r10 = src + (size_t)i10 * CIN + cc;
        const float* r11 = src + (size_t)i11 * CIN + cc;
        float a[8], b[8], c[8], d[8];
        *reinterpret_cast<float4*>(a)     = *reinterpret_cast<const float4*>(r00);
        *reinterpret_cast<float4*>(a + 4) = *reinterpret_cast<const float4*>(r00 + 4);
        *reinterpret_cast<float4*>(b)     = *reinterpret_cast<const float4*>(r01);
        *reinterpret_cast<float4*>(b + 4) = *reinterpret_cast<const float4*>(r01 + 4);
        *reinterpret_cast<float4*>(c)     = *reinterpret_cast<const float4*>(r10);
        *reinterpret_cast<float4*>(c + 4) = *reinterpret_cast<const float4*>(r10 + 4);
        *reinterpret_cast<float4*>(d)     = *reinterpret_cast<const float4*>(r11);
        *reinterpret_cast<float4*>(d + 4) = *reinterpret_cast<const float4*>(r11 + 4);

        __align__(16) __half hv[8];
#pragma unroll
        for (int j = 0; j < 8; j++) {
            float v = w00 * a[j] + w01 * b[j] + w10 * c[j] + w11 * d[j];
            hv[j] = __float2half(v);
        }
        *reinterpret_cast<uint4*>(outp + k * 256 + cc) = *reinterpret_cast<uint4*>(hv);
    }
}

// ---------------------------------------------------------------------------
// Stage-3 HMMA GEMM: fp16 single-pass, K=2304, BK=128 (2 sub-chunks), 2-stage.
// ---------------------------------------------------------------------------
#define ABYTES 16384
#define BBYTES 32768
#define STAGEB (ABYTES + BBYTES)
#define STAGE2B (2 * STAGEB)

__global__ void __launch_bounds__(256, 1)
hmma_gemm(const __half* __restrict__ colsT, const __half* __restrict__ wh,
          const float* __restrict__ bias, float* __restrict__ out) {
    extern __shared__ char smem[];
    const uint32_t sb = smem_u32(smem);
    const int tid = threadIdx.x;
    const int wid = tid >> 5, lane = tid & 31;
    const int wm = wid >> 2, wn = wid & 3;
    const int p0 = blockIdx.x * 128;
    const int n = blockIdx.z;

    const char* Ag = (const char*)(colsT + (size_t)(n * HW + p0) * KP3);
    const char* Bg = (const char*)wh;

    float acc[4][8][4];
#pragma unroll
    for (int i = 0; i < 4; i++)
#pragma unroll
        for (int j = 0; j < 8; j++)
#pragma unroll
            for (int r = 0; r < 4; r++) acc[i][j][r] = 0.f;

    auto load_stage = [&](int t, int s) {
#pragma unroll
        for (int half = 0; half < 2; half++) {
            int kt = 2 * t + half;
            uint32_t dA = sb + s * STAGE2B + half * STAGEB;
            uint32_t dB = dA + ABYTES;
#pragma unroll
            for (int u = 0; u < 4; u++) {
                int idx = tid + u * 256;
                int row = idx >> 3, c = idx & 7;
                cp_async16(dA + row * 128 + ((c ^ (row & 7)) << 4),
                           Ag + (size_t)row * KROW3 + kt * 128 + c * 16);
            }
#pragma unroll
            for (int u = 0; u < 8; u++) {
                int idx = tid + u * 256;
                int row = idx >> 3, c = idx & 7;
                cp_async16(dB + row * 128 + ((c ^ (row & 7)) << 4),
                           Bg + (size_t)row * KROW3 + kt * 128 + c * 16);
            }
        }
        cp_commit();
    };

    auto compute_stage = [&](int s) {
        const int rbase = ((lane >> 3) & 1) * 8 + (lane & 7);
        const int chi = (lane >> 4);
#pragma unroll
        for (int half = 0; half < 2; half++) {
            uint32_t Ab = sb + s * STAGE2B + half * STAGEB;
            uint32_t Bb = Ab + ABYTES;
#pragma unroll
            for (int ks = 0; ks < 4; ks++) {
                int c = ks * 2 + chi;
                uint32_t af[4][4], bf[4][4];
#pragma unroll
                for (int i = 0; i < 4; i++) {
                    int row = wm * 64 + i * 16 + rbase;
                    ldsm_x4(af[i], Ab + row * 128 + ((c ^ (row & 7)) << 4));
                }
#pragma unroll
                for (int j = 0; j < 4; j++) {
                    int row = wn * 64 + j * 16 + rbase;
                    ldsm_x4(bf[j], Bb + row * 128 + ((c ^ (row & 7)) << 4));
                }
#pragma unroll
                for (int i = 0; i < 4; i++)
#pragma unroll
                    for (int j = 0; j < 4; j++)
#pragma unroll
                        for (int s2 = 0; s2 < 2; s2++)
                            mma16816_f16(acc[i][j * 2 + s2], af[i], bf[j][s2], bf[j][s2 + 2]);
            }
        }
    };

    load_stage(0, 0);
    for (int t = 0; t < K3PAIRS; t++) {
        cp_wait<0>();
        __syncthreads();
        if (t + 1 < K3PAIRS) load_stage(t + 1, (t + 1) & 1);
        compute_stage(t & 1);
    }

#pragma unroll
    for (int i = 0; i < 4; i++) {
        int m = wm * 64 + i * 16 + (lane >> 2);
#pragma unroll
        for (int j = 0; j < 4; j++)
#pragma unroll
            for (int s = 0; s < 2; s++) {
                int cout = wn * 64 + j * 16 + s * 8 + (lane & 3) * 2;
                float b0 = bias[cout], b1 = bias[cout + 1];
                float* o = out + ((size_t)n * COUT + cout) * HW + p0;
                const float* a = acc[i][j * 2 + s];
                o[m]          = a[0] + b0;
                o[HW + m]     = a[1] + b1;
                o[m + 8]      = a[2] + b0;
                o[HW + m + 8] = a[3] + b1;
            }
    }
}

// ---------------------------------------------------------------------------
extern "C" void kernel_launch(void* const* d_in, const int* in_sizes, int n_in,
                              void* d_out, int out_size) {
    const float* x      = (const float*)d_in[0];
    const float* depth  = (const float*)d_in[1];
    const float* weight = (const float*)d_in[2];
    const float* bias   = (const float*)d_in[3];
    const float* off_w  = (const float*)d_in[4];
    const float* off_b  = (const float*)d_in[5];
    const float* mask_w = (const float*)d_in[6];
    const float* mask_b = (const float*)d_in[7];
    float* out = (float*)d_out;

    void *po, *pm, *pch, *pwh, *pxt, *pdt, *pxd, *pw1;
    cudaGetSymbolAddress(&po, g_offsets);
    cudaGetSymbolAddress(&pm, g_mask);
    cudaGetSymbolAddress(&pch, g_colsh);
    cudaGetSymbolAddress(&pwh, g_wh);
    cudaGetSymbolAddress(&pxt, g_xT);
    cudaGetSymbolAddress(&pdt, g_dT);
    cudaGetSymbolAddress(&pxd, g_xdbf);
    cudaGetSymbolAddress(&pw1, g_ws1);
    float* offsets = (float*)po;
    float* maskbuf = (float*)pm;
    __half* colsh = (__half*)pch;
    __half* wh = (__half*)pwh;
    float* xT = (float*)pxt;
    float* dT = (float*)pdt;
    __nv_bfloat16* xdbf = (__nv_bfloat16*)pxd;
    __nv_bfloat16* ws1 = (__nv_bfloat16*)pw1;

    // Prep
    prep_w_kernel<<<COUT, 256>>>(weight, wh);
    prep_s1w<<<32, 320>>>(off_w, ws1);
    transpose_cp<<<dim3(HW / 32, CIN / 32, NB), dim3(32, 8)>>>(x, xT, CIN);
    transpose_cp<<<dim3(HW / 32, DC / 32, NB), dim3(32, 8)>>>(depth, dT, DC);
    build_xdbf<<<dim3(HW / 32, NB), 256>>>(xT, dT, xdbf);

    static int smem_set = 0;
    if (!smem_set) {
        cudaFuncSetAttribute(s1_hmma, cudaFuncAttributeMaxDynamicSharedMemorySize,
                             3 * S1_STG);
        cudaFuncSetAttribute(hmma_gemm, cudaFuncAttributeMaxDynamicSharedMemorySize,
                             2 * STAGE2B);
        smem_set = 1;
    }

    // Stage 1: offset conv via implicit-im2col HMMA GEMM (bf16 3-pass)
    s1_hmma<<<dim3(HW / 128, 1, NB), 256, 3 * S1_STG>>>(xdbf, ws1, off_b, offsets);

    // Stage 2: fused mask = sigmoid(deform_conv(depth, offset))
    fused_mask<<<dim3(HW / 8, NB), 256>>>(dT, offsets, mask_w, mask_b, maskbuf);

    // Stage 3: modulated deformable conv, fp16 single-pass HMMA GEMM
    deform_im2col_f16<<<dim3(HW / 8, NB), 256>>>(xT, offsets, maskbuf, colsh);
    hmma_gemm<<<dim3(HW / 128, 1, NB), 256, 2 * STAGE2B>>>(colsh, wh, bias, out);
}

// round 12
// speedup vs baseline: 5.7031x; 1.0767x over previous
#include <cuda_runtime.h>
#include <cuda_bf16.h>
#include <cuda_fp16.h>
#include <cstdint>
#include <math.h>

#define NB 4
#define HH 64
#define WW 64
#define HW 4096
#define CIN 256
#define DC 64
#define COUT 256
#define KP3 2304               /* stage-3 K: single-pass fp16 */
#define KROW3 (KP3 * 2)
#define K3PAIRS 18
#define S1K 8640               /* stage-1 W cols: 3 * 2880 (bf16 split) */
#define S1CHUNKS 135

// ---------------- device scratch ----------------
__device__ float g_offsets[(size_t)NB * 18 * HW];
__device__ float g_mask[(size_t)NB * 9 * HW];
__device__ __half g_xTh[(size_t)NB * HW * CIN];            // x NHWC fp16
__device__ float g_dT[(size_t)NB * HW * DC];               // depth NHWC f32
__device__ __nv_bfloat16 g_xdbf[(size_t)NB * HW * 640];    // cat(x,d) [hi320|lo320]
__device__ __nv_bfloat16 g_ws1[(size_t)32 * S1K];          // off_w split, 32 rows
__device__ __half g_colsh[(size_t)NB * HW * KP3];          // 75 MB fp16 cols
__device__ __half g_wh[(size_t)COUT * KP3];                // fp16 weights

// ---------------- PTX helpers ----------------
__device__ __forceinline__ uint32_t smem_u32(const void* p) {
    uint32_t a;
    asm("{ .reg .u64 t; cvta.to.shared.u64 t, %1; cvt.u32.u64 %0, t; }"
        : "=r"(a) : "l"(p));
    return a;
}
__device__ __forceinline__ void cp_async16(uint32_t dst, const void* src) {
    asm volatile("cp.async.cg.shared.global [%0], [%1], 16;"
                 :: "r"(dst), "l"(src) : "memory");
}
__device__ __forceinline__ void cp_async16_z(uint32_t dst, const void* src, bool pred) {
    int sz = pred ? 16 : 0;
    asm volatile("cp.async.cg.shared.global [%0], [%1], 16, %2;"
                 :: "r"(dst), "l"(src), "r"(sz) : "memory");
}
__device__ __forceinline__ void cp_commit() {
    asm volatile("cp.async.commit_group;" ::: "memory");
}
template <int N>
__device__ __forceinline__ void cp_wait() {
    asm volatile("cp.async.wait_group %0;" :: "n"(N) : "memory");
}
__device__ __forceinline__ void ldsm_x4(uint32_t (&r)[4], uint32_t addr) {
    asm volatile("ldmatrix.sync.aligned.m8n8.x4.shared.b16 {%0,%1,%2,%3}, [%4];"
                 : "=r"(r[0]), "=r"(r[1]), "=r"(r[2]), "=r"(r[3]) : "r"(addr));
}
__device__ __forceinline__ void mma16816_bf(float (&d)[4], const uint32_t (&a)[4],
                                            uint32_t b0, uint32_t b1) {
    asm volatile(
        "mma.sync.aligned.m16n8k16.row.col.f32.bf16.bf16.f32 "
        "{%0,%1,%2,%3}, {%4,%5,%6,%7}, {%8,%9}, {%0,%1,%2,%3};"
        : "+f"(d[0]), "+f"(d[1]), "+f"(d[2]), "+f"(d[3])
        : "r"(a[0]), "r"(a[1]), "r"(a[2]), "r"(a[3]), "r"(b0), "r"(b1));
}
__device__ __forceinline__ void mma16816_f16(float (&d)[4], const uint32_t (&a)[4],
                                             uint32_t b0, uint32_t b1) {
    asm volatile(
        "mma.sync.aligned.m16n8k16.row.col.f32.f16.f16.f32 "
        "{%0,%1,%2,%3}, {%4,%5,%6,%7}, {%8,%9}, {%0,%1,%2,%3};"
        : "+f"(d[0]), "+f"(d[1]), "+f"(d[2]), "+f"(d[3])
        : "r"(a[0]), "r"(a[1]), "r"(a[2]), "r"(a[3]), "r"(b0), "r"(b1));
}

// ---------------------------------------------------------------------------
// prep_x: x[n][c][p] -> xTh[n][p][c] fp16 + xdbf hi/lo (channels 0..255)
// grid (HW/32, CIN/32, NB), block (32, 8)
// ---------------------------------------------------------------------------
__global__ void prep_x(const float* __restrict__ x, __half* __restrict__ xTh,
                       __nv_bfloat16* __restrict__ xd) {
    __shared__ float t[32][33];
    int n = blockIdx.z;
    int p0 = blockIdx.x * 32, c0 = blockIdx.y * 32;
    int tx = threadIdx.x, ty = threadIdx.y;
#pragma unroll
    for (int j = 0; j < 32; j += 8)
        t[ty + j][tx] = x[((size_t)n * CIN + c0 + ty + j) * HW + p0 + tx];
    __syncthreads();
#pragma unroll
    for (int j = 0; j < 32; j += 8) {
        float v = t[tx][ty + j];
        size_t prow = (size_t)n * HW + p0 + ty + j;
        int c = c0 + tx;
        xTh[prow * CIN + c] = __float2half(v);
        __nv_bfloat16 hb = __float2bfloat16(v);
        xd[prow * 640 + c] = hb;
        xd[prow * 640 + 320 + c] = __float2bfloat16(v - __bfloat162float(hb));
    }
}

// ---------------------------------------------------------------------------
// prep_d: depth[n][c][p] -> dT[n][p][c] f32 + xdbf hi/lo (channels 256..319)
// grid (HW/32, 2, NB), block (32, 8)
// ---------------------------------------------------------------------------
__global__ void prep_d(const float* __restrict__ depth, float* __restrict__ dT,
                       __nv_bfloat16* __restrict__ xd) {
    __shared__ float t[32][33];
    int n = blockIdx.z;
    int p0 = blockIdx.x * 32, c0 = blockIdx.y * 32;
    int tx = threadIdx.x, ty = threadIdx.y;
#pragma unroll
    for (int j = 0; j < 32; j += 8)
        t[ty + j][tx] = depth[((size_t)n * DC + c0 + ty + j) * HW + p0 + tx];
    __syncthreads();
#pragma unroll
    for (int j = 0; j < 32; j += 8) {
        float v = t[tx][ty + j];
        size_t prow = (size_t)n * HW + p0 + ty + j;
        int c = c0 + tx;
        dT[prow * DC + c] = v;
        __nv_bfloat16 hb = __float2bfloat16(v);
        xd[prow * 640 + 256 + c] = hb;
        xd[prow * 640 + 576 + c] = __float2bfloat16(v - __bfloat162float(hb));
    }
}

// ---------------------------------------------------------------------------
// Weight preps
// ---------------------------------------------------------------------------
__global__ void prep_w_kernel(const float* __restrict__ w,
                              __half* __restrict__ wh) {
    int cout = blockIdx.x;
    int c = threadIdx.x;
#pragma unroll
    for (int k = 0; k < 9; k++) {
        float v = w[((size_t)cout * 256 + c) * 9 + k];
        wh[(size_t)cout * KP3 + k * 256 + c] = __float2half(v);
    }
}

__global__ void prep_s1w(const float* __restrict__ ow, __nv_bfloat16* __restrict__ ws) {
    int m = blockIdx.x;
    int c = threadIdx.x;
#pragma unroll
    for (int kk = 0; kk < 9; kk++) {
        float v = (m < 18) ? ow[((size_t)m * 320 + c) * 9 + kk] : 0.f;
        __nv_bfloat16 hb = __float2bfloat16(v);
        __nv_bfloat16 lb = __float2bfloat16(v - __bfloat162float(hb));
        size_t b = (size_t)m * S1K + kk * 320 + c;
        ws[b] = hb;
        ws[b + 2880] = hb;
        ws[b + 5760] = lb;
    }
}

// ---------------------------------------------------------------------------
// Stage-1 HMMA GEMM (implicit im2col, bf16 3-pass)
// ---------------------------------------------------------------------------
#define S1_AB 16384
#define S1_BB 4096
#define S1_STG (S1_AB + S1_BB)

__global__ void __launch_bounds__(256, 1)
s1_hmma(const __nv_bfloat16* __restrict__ xd, const __nv_bfloat16* __restrict__ ws,
        const float* __restrict__ offb, float* __restrict__ offsets) {
    extern __shared__ char smem[];
    const uint32_t sb = smem_u32(smem);
    const int tid = threadIdx.x;
    const int wid = tid >> 5, lane = tid & 31;
    const int p0 = blockIdx.x * 128;
    const int n = blockIdx.z;
    const __nv_bfloat16* xdn = xd + (size_t)n * HW * 640;

    float acc[4][4];
#pragma unroll
    for (int i = 0; i < 4; i++)
#pragma unroll
        for (int r = 0; r < 4; r++) acc[i][r] = 0.f;

    auto load_chunk = [&](int kc, int buf) {
        int pass = kc / 45;
        int r = kc - pass * 45;
        int tap = r / 5;
        int c0 = (r - tap * 5) * 64;
        int ah = (pass == 1) ? 320 : 0;
        int dr = tap / 3 - 1, dc = tap % 3 - 1;
        uint32_t dA = sb + buf * S1_STG;
        uint32_t dB = dA + S1_AB;
#pragma unroll
        for (int u = 0; u < 4; u++) {
            int idx = tid + u * 256;
            int row = idx >> 3, q = idx & 7;
            int gp = p0 + row;
            int h = gp >> 6, w = gp & 63;
            int iy = h + dr, ix = w + dc;
            bool v = (iy >= 0) & (iy < HH) & (ix >= 0) & (ix < WW);
            int pn = v ? iy * WW + ix : 0;
            cp_async16_z(dA + row * 128 + ((q ^ (row & 7)) << 4),
                         xdn + (size_t)pn * 640 + ah + c0 + q * 8, v);
        }
        {
            int row = tid >> 3, q = tid & 7;
            cp_async16(dB + row * 128 + ((q ^ (row & 7)) << 4),
                       ws + (size_t)row * S1K + kc * 64 + q * 8);
        }
        cp_commit();
    };

    auto compute_chunk = [&](int buf) {
        uint32_t Ab = sb + buf * S1_STG;
        uint32_t Bb = Ab + S1_AB;
        const int rbase = ((lane >> 3) & 1) * 8 + (lane & 7);
        const int chi = (lane >> 4);
#pragma unroll
        for (int ks = 0; ks < 4; ks++) {
            int c = ks * 2 + chi;
            uint32_t af[4], bf[2][4];
            {
                int row = wid * 16 + rbase;
                ldsm_x4(af, Ab + row * 128 + ((c ^ (row & 7)) << 4));
            }
#pragma unroll
            for (int j = 0; j < 2; j++) {
                int row = j * 16 + rbase;
                ldsm_x4(bf[j], Bb + row * 128 + ((c ^ (row & 7)) << 4));
            }
#pragma unroll
            for (int j = 0; j < 2; j++)
#pragma unroll
                for (int s = 0; s < 2; s++)
                    mma16816_bf(acc[j * 2 + s], af, bf[j][s], bf[j][s + 2]);
        }
    };

    load_chunk(0, 0);
    load_chunk(1, 1);
    for (int kc = 0; kc < S1CHUNKS; kc++) {
        int buf = kc % 3;
        if (kc + 1 < S1CHUNKS) cp_wait<1>(); else cp_wait<0>();
        __syncthreads();
        if (kc + 2 < S1CHUNKS) load_chunk(kc + 2, (kc + 2) % 3);
        compute_chunk(buf);
    }

#pragma unroll
    for (int j = 0; j < 2; j++)
#pragma unroll
        for (int s = 0; s < 2; s++) {
            int m = j * 16 + s * 8 + (lane & 3) * 2;
            if (m < 18) {
                float b0 = offb[m], b1 = offb[m + 1];
                int row = wid * 16 + (lane >> 2);
                float* o = offsets + ((size_t)n * 18 + m) * HW + p0;
                const float* a = acc[j * 2 + s];
                o[row]          = a[0] + b0;
                o[HW + row]     = a[1] + b1;
                o[row + 8]      = a[2] + b0;
                o[HW + row + 8] = a[3] + b1;
            }
        }
}

// ---------------------------------------------------------------------------
// Stage-2 FUSED: mask = sigmoid(deform_conv(depthT, offset) + mb)
// ---------------------------------------------------------------------------
__global__ void __launch_bounds__(256)
fused_mask(const float* __restrict__ depthT, const float* __restrict__ offs,
           const float* __restrict__ mw, const float* __restrict__ mb,
           float* __restrict__ maskbuf) {
    __shared__ float ws[9][9][64];
    __shared__ float sbias[9];
    const int tid = threadIdx.x;
    const int n = blockIdx.y;

    for (int i = tid; i < 5184; i += 256) {
        int m = i / 576;
        int rem = i - m * 576;
        int c = rem / 9;
        int k = rem - 9 * c;
        ws[k][m][c] = mw[i];
    }
    if (tid < 9) sbias[tid] = mb[tid];
    __syncthreads();

    const int wid = tid >> 5, lane = tid & 31;
    const int p = blockIdx.x * 8 + wid;
    const int h = p >> 6, w = p & 63;
    const float* dn = depthT + (size_t)n * HW * DC;
    const float* offn = offs + (size_t)n * 18 * HW;

    float acc[9];
#pragma unroll
    for (int m = 0; m < 9; m++) acc[m] = 0.f;

#pragma unroll
    for (int k = 0; k < 9; k++) {
        float dy = offn[(size_t)(2 * k) * HW + p];
        float dx = offn[(size_t)(2 * k + 1) * HW + p];
        float y = (float)(h - 1 + k / 3) + dy;
        float xx = (float)(w - 1 + k % 3) + dx;
        float y0f = floorf(y), x0f = floorf(xx);
        float ly = y - y0f, lx = xx - x0f;
        int y0 = (int)y0f, x0 = (int)x0f;
        int y1 = y0 + 1, x1 = x0 + 1;
        bool vy0 = (y0 >= 0) & (y0 < HH);
        bool vy1 = (y1 >= 0) & (y1 < HH);
        bool vx0 = (x0 >= 0) & (x0 < WW);
        bool vx1 = (x1 >= 0) & (x1 < WW);
        float w00 = (vy0 & vx0) ? (1.f - ly) * (1.f - lx) : 0.f;
        float w01 = (vy0 & vx1) ? (1.f - ly) * lx : 0.f;
        float w10 = (vy1 & vx0) ? ly * (1.f - lx) : 0.f;
        float w11 = (vy1 & vx1) ? ly * lx : 0.f;
        int i00 = (vy0 & vx0) ? y0 * WW + x0 : 0;
        int i01 = (vy0 & vx1) ? y0 * WW + x1 : 0;
        int i10 = (vy1 & vx0) ? y1 * WW + x0 : 0;
        int i11 = (vy1 & vx1) ? y1 * WW + x1 : 0;
        int cc = lane * 2;
        float2 a = *reinterpret_cast<const float2*>(dn + (size_t)i00 * DC + cc);
        float2 b = *reinterpret_cast<const float2*>(dn + (size_t)i01 * DC + cc);
        float2 cv = *reinterpret_cast<const float2*>(dn + (size_t)i10 * DC + cc);
        float2 d = *reinterpret_cast<const float2*>(dn + (size_t)i11 * DC + cc);
        float v0 = w00 * a.x + w01 * b.x + w10 * cv.x + w11 * d.x;
        float v1 = w00 * a.y + w01 * b.y + w10 * cv.y + w11 * d.y;
#pragma unroll
        for (int m = 0; m < 9; m++) {
            float2 wv = *reinterpret_cast<const float2*>(&ws[k][m][cc]);
            acc[m] += wv.x * v0 + wv.y * v1;
        }
    }

#pragma unroll
    for (int m = 0; m < 9; m++) {
#pragma unroll
        for (int off = 16; off > 0; off >>= 1)
            acc[m] += __shfl_xor_sync(0xFFFFFFFFu, acc[m], off);
    }
    if (lane == 0) {
        float* mp = maskbuf + (size_t)n * 9 * HW + p;
#pragma unroll
        for (int m = 0; m < 9; m++) {
            float v = acc[m] + sbias[m];
            mp[(size_t)m * HW] = 1.f / (1.f + expf(-v));
        }
    }
}

// ---------------------------------------------------------------------------
// Stage-3 deformable im2col: warp-per-pixel, fp16 gathers + fp16 output.
// grid (HW/8, NB), 256 threads (8 warps = 8 pixels).
// ---------------------------------------------------------------------------
__global__ void __launch_bounds__(256)
deform_im2col_f16(const __half* __restrict__ xTh, const float* __restrict__ offs,
                  const float* __restrict__ mask, __half* __restrict__ colsT) {
    const int tid = threadIdx.x;
    const int wid = tid >> 5, lane = tid & 31;
    const int n = blockIdx.y;
    const int p = blockIdx.x * 8 + wid;
    const int h = p >> 6, w = p & 63;
    const float* offn = offs + (size_t)n * 18 * HW;
    const float* maskn = mask + (size_t)n * 9 * HW;
    const __half* src = xTh + (size_t)n * HW * CIN;
    __half* outp = colsT + ((size_t)n * HW + p) * KP3;
    const int cc = lane * 8;

#pragma unroll
    for (int k = 0; k < 9; k++) {
        float dy = offn[(size_t)(2 * k) * HW + p];
        float dx = offn[(size_t)(2 * k + 1) * HW + p];
        float mk = maskn[(size_t)k * HW + p];
        float y = (float)(h - 1 + k / 3) + dy;
        float xx = (float)(w - 1 + k % 3) + dx;
        float y0f = floorf(y), x0f = floorf(xx);
        float ly = y - y0f, lx = xx - x0f;
        int y0 = (int)y0f, x0 = (int)x0f;
        int y1 = y0 + 1, x1 = x0 + 1;
        bool vy0 = (y0 >= 0) & (y0 < HH);
        bool vy1 = (y1 >= 0) & (y1 < HH);
        bool vx0 = (x0 >= 0) & (x0 < WW);
        bool vx1 = (x1 >= 0) & (x1 < WW);
        float w00 = (vy0 & vx0) ? (1.f - ly) * (1.f - lx) * mk : 0.f;
        float w01 = (vy0 & vx1) ? (1.f - ly) * lx * mk : 0.f;
        float w10 = (vy1 & vx0) ? ly * (1.f - lx) * mk : 0.f;
        float w11 = (vy1 & vx1) ? ly * lx * mk : 0.f;
        int i00 = (vy0 & vx0) ? y0 * WW + x0 : 0;
        int i01 = (vy0 & vx1) ? y0 * WW + x1 : 0;
        int i10 = (vy1 & vx0) ? y1 * WW + x0 : 0;
        int i11 = (vy1 & vx1) ? y1 * WW + x1 : 0;

        // fp16 corner gathers: 16B per lane, coalesced 512B warp requests
        uint4 A = *reinterpret_cast<const uint4*>(src + (size_t)i00 * CIN + cc);
        uint4 B = *reinterpret_cast<const uint4*>(src + (size_t)i01 * CIN + cc);
        uint4 C = *reinterpret_cast<const uint4*>(src + (size_t)i10 * CIN + cc);
        uint4 D = *reinterpret_cast<const uint4*>(src + (size_t)i11 * CIN + cc);
        const __half2* a2 = reinterpret_cast<const __half2*>(&A);
        const __half2* b2 = reinterpret_cast<const __half2*>(&B);
        const __half2* c2 = reinterpret_cast<const __half2*>(&C);
        const __half2* d2 = reinterpret_cast<const __half2*>(&D);

        __align__(16) __half hv[8];
#pragma unroll
        for (int j = 0; j < 4; j++) {
            float2 av = __half22float2(a2[j]);
            float2 bv = __half22float2(b2[j]);
            float2 cv = __half22float2(c2[j]);
            float2 dv = __half22float2(d2[j]);
            hv[2 * j]     = __float2half(w00 * av.x + w01 * bv.x + w10 * cv.x + w11 * dv.x);
            hv[2 * j + 1] = __float2half(w00 * av.y + w01 * bv.y + w10 * cv.y + w11 * dv.y);
        }
        *reinterpret_cast<uint4*>(outp + k * 256 + cc) = *reinterpret_cast<uint4*>(hv);
    }
}

// ---------------------------------------------------------------------------
// Stage-3 HMMA GEMM: fp16 single-pass, K=2304, BK=128, 2-stage.
// ---------------------------------------------------------------------------
#define ABYTES 16384
#define BBYTES 32768
#define STAGEB (ABYTES + BBYTES)
#define STAGE2B (2 * STAGEB)

__global__ void __launch_bounds__(256, 1)
hmma_gemm(const __half* __restrict__ colsT, const __half* __restrict__ wh,
          const float* __restrict__ bias, float* __restrict__ out) {
    extern __shared__ char smem[];
    const uint32_t sb = smem_u32(smem);
    const int tid = threadIdx.x;
    const int wid = tid >> 5, lane = tid & 31;
    const int wm = wid >> 2, wn = wid & 3;
    const int p0 = blockIdx.x * 128;
    const int n = blockIdx.z;

    const char* Ag = (const char*)(colsT + (size_t)(n * HW + p0) * KP3);
    const char* Bg = (const char*)wh;

    float acc[4][8][4];
#pragma unroll
    for (int i = 0; i < 4; i++)
#pragma unroll
        for (int j = 0; j < 8; j++)
#pragma unroll
            for (int r = 0; r < 4; r++) acc[i][j][r] = 0.f;

    auto load_stage = [&](int t, int s) {
#pragma unroll
        for (int half = 0; half < 2; half++) {
            int kt = 2 * t + half;
            uint32_t dA = sb + s * STAGE2B + half * STAGEB;
            uint32_t dB = dA + ABYTES;
#pragma unroll
            for (int u = 0; u < 4; u++) {
                int idx = tid + u * 256;
                int row = idx >> 3, c = idx & 7;
                cp_async16(dA + row * 128 + ((c ^ (row & 7)) << 4),
                           Ag + (size_t)row * KROW3 + kt * 128 + c * 16);
            }
#pragma unroll
            for (int u = 0; u < 8; u++) {
                int idx = tid + u * 256;
                int row = idx >> 3, c = idx & 7;
                cp_async16(dB + row * 128 + ((c ^ (row & 7)) << 4),
                           Bg + (size_t)row * KROW3 + kt * 128 + c * 16);
            }
        }
        cp_commit();
    };

    auto compute_stage = [&](int s) {
        const int rbase = ((lane >> 3) & 1) * 8 + (lane & 7);
        const int chi = (lane >> 4);
#pragma unroll
        for (int half = 0; half < 2; half++) {
            uint32_t Ab = sb + s * STAGE2B + half * STAGEB;
            uint32_t Bb = Ab + ABYTES;
#pragma unroll
            for (int ks = 0; ks < 4; ks++) {
                int c = ks * 2 + chi;
                uint32_t af[4][4], bf[4][4];
#pragma unroll
                for (int i = 0; i < 4; i++) {
                    int row = wm * 64 + i * 16 + rbase;
                    ldsm_x4(af[i], Ab + row * 128 + ((c ^ (row & 7)) << 4));
                }
#pragma unroll
                for (int j = 0; j < 4; j++) {
                    int row = wn * 64 + j * 16 + rbase;
                    ldsm_x4(bf[j], Bb + row * 128 + ((c ^ (row & 7)) << 4));
                }
#pragma unroll
                for (int i = 0; i < 4; i++)
#pragma unroll
                    for (int j = 0; j < 4; j++)
#pragma unroll
                        for (int s2 = 0; s2 < 2; s2++)
                            mma16816_f16(acc[i][j * 2 + s2], af[i], bf[j][s2], bf[j][s2 + 2]);
            }
        }
    };

    load_stage(0, 0);
    for (int t = 0; t < K3PAIRS; t++) {
        cp_wait<0>();
        __syncthreads();
        if (t + 1 < K3PAIRS) load_stage(t + 1, (t + 1) & 1);
        compute_stage(t & 1);
    }

#pragma unroll
    for (int i = 0; i < 4; i++) {
        int m = wm * 64 + i * 16 + (lane >> 2);
#pragma unroll
        for (int j = 0; j < 4; j++)
#pragma unroll
            for (int s = 0; s < 2; s++) {
                int cout = wn * 64 + j * 16 + s * 8 + (lane & 3) * 2;
                float b0 = bias[cout], b1 = bias[cout + 1];
                float* o = out + ((size_t)n * COUT + cout) * HW + p0;
                const float* a = acc[i][j * 2 + s];
                o[m]          = a[0] + b0;
                o[HW + m]     = a[1] + b1;
                o[m + 8]      = a[2] + b0;
                o[HW + m + 8] = a[3] + b1;
            }
    }
}

// ---------------------------------------------------------------------------
extern "C" void kernel_launch(void* const* d_in, const int* in_sizes, int n_in,
                              void* d_out, int out_size) {
    const float* x      = (const float*)d_in[0];
    const float* depth  = (const float*)d_in[1];
    const float* weight = (const float*)d_in[2];
    const float* bias   = (const float*)d_in[3];
    const float* off_w  = (const float*)d_in[4];
    const float* off_b  = (const float*)d_in[5];
    const float* mask_w = (const float*)d_in[6];
    const float* mask_b = (const float*)d_in[7];
    float* out = (float*)d_out;

    void *po, *pm, *pch, *pwh, *pxh, *pdt, *pxd, *pw1;
    cudaGetSymbolAddress(&po, g_offsets);
    cudaGetSymbolAddress(&pm, g_mask);
    cudaGetSymbolAddress(&pch, g_colsh);
    cudaGetSymbolAddress(&pwh, g_wh);
    cudaGetSymbolAddress(&pxh, g_xTh);
    cudaGetSymbolAddress(&pdt, g_dT);
    cudaGetSymbolAddress(&pxd, g_xdbf);
    cudaGetSymbolAddress(&pw1, g_ws1);
    float* offsets = (float*)po;
    float* maskbuf = (float*)pm;
    __half* colsh = (__half*)pch;
    __half* wh = (__half*)pwh;
    __half* xTh = (__half*)pxh;
    float* dT = (float*)pdt;
    __nv_bfloat16* xdbf = (__nv_bfloat16*)pxd;
    __nv_bfloat16* ws1 = (__nv_bfloat16*)pw1;

    // Prep (fused transpose + precision-split)
    prep_w_kernel<<<COUT, 256>>>(weight, wh);
    prep_s1w<<<32, 320>>>(off_w, ws1);
    prep_x<<<dim3(HW / 32, CIN / 32, NB), dim3(32, 8)>>>(x, xTh, xdbf);
    prep_d<<<dim3(HW / 32, DC / 32, NB), dim3(32, 8)>>>(depth, dT, xdbf);

    static int smem_set = 0;
    if (!smem_set) {
        cudaFuncSetAttribute(s1_hmma, cudaFuncAttributeMaxDynamicSharedMemorySize,
                             3 * S1_STG);
        cudaFuncSetAttribute(hmma_gemm, cudaFuncAttributeMaxDynamicSharedMemorySize,
                             2 * STAGE2B);
        smem_set = 1;
    }

    // Stage 1: offset conv via implicit-im2col HMMA GEMM (bf16 3-pass)
    s1_hmma<<<dim3(HW / 128, 1, NB), 256, 3 * S1_STG>>>(xdbf, ws1, off_b, offsets);

    // Stage 2: fused mask = sigmoid(deform_conv(depth, offset))
    fused_mask<<<dim3(HW / 8, NB), 256>>>(dT, offsets, mask_w, mask_b, maskbuf);

    // Stage 3: modulated deformable conv, fp16 single-pass HMMA GEMM
    deform_im2col_f16<<<dim3(HW / 8, NB), 256>>>(xTh, offsets, maskbuf, colsh);
    hmma_gemm<<<dim3(HW / 128, 1, NB), 256, 2 * STAGE2B>>>(colsh, wh, bias, out);
}

// round 13
// speedup vs baseline: 5.7748x; 1.0126x over previous
#include <cuda_runtime.h>
#include <cuda_bf16.h>
#include <cuda_fp16.h>
#include <cstdint>
#include <math.h>

#define NB 4
#define HH 64
#define WW 64
#define HW 4096
#define CIN 256
#define DC 64
#define COUT 256
#define KP3 2304               /* stage-3 K: single-pass fp16 */
#define KROW3 (KP3 * 2)
#define K3PAIRS 18
#define S1K 8640               /* stage-1 W cols: 3 * 2880 (bf16 split) */
#define S1CHUNKS 135

// ---------------- device scratch ----------------
__device__ float g_offsets[(size_t)NB * 18 * HW];
__device__ float g_mask[(size_t)NB * 9 * HW];
__device__ __half g_xTh[(size_t)NB * HW * CIN];            // x NHWC fp16
__device__ float g_dT[(size_t)NB * HW * DC];               // depth NHWC f32
__device__ __nv_bfloat16 g_xdbf[(size_t)NB * HW * 640];    // cat(x,d) [hi320|lo320]
__device__ __nv_bfloat16 g_ws1[(size_t)32 * S1K];          // off_w split, 32 rows
__device__ __half g_colsh[(size_t)NB * HW * KP3];          // 75 MB fp16 cols
__device__ __half g_wh[(size_t)COUT * KP3];                // fp16 weights

// ---------------- PTX helpers ----------------
__device__ __forceinline__ uint32_t smem_u32(const void* p) {
    uint32_t a;
    asm("{ .reg .u64 t; cvta.to.shared.u64 t, %1; cvt.u32.u64 %0, t; }"
        : "=r"(a) : "l"(p));
    return a;
}
__device__ __forceinline__ void cp_async16(uint32_t dst, const void* src) {
    asm volatile("cp.async.cg.shared.global [%0], [%1], 16;"
                 :: "r"(dst), "l"(src) : "memory");
}
__device__ __forceinline__ void cp_async16_z(uint32_t dst, const void* src, bool pred) {
    int sz = pred ? 16 : 0;
    asm volatile("cp.async.cg.shared.global [%0], [%1], 16, %2;"
                 :: "r"(dst), "l"(src), "r"(sz) : "memory");
}
__device__ __forceinline__ void cp_commit() {
    asm volatile("cp.async.commit_group;" ::: "memory");
}
template <int N>
__device__ __forceinline__ void cp_wait() {
    asm volatile("cp.async.wait_group %0;" :: "n"(N) : "memory");
}
__device__ __forceinline__ void ldsm_x4(uint32_t (&r)[4], uint32_t addr) {
    asm volatile("ldmatrix.sync.aligned.m8n8.x4.shared.b16 {%0,%1,%2,%3}, [%4];"
                 : "=r"(r[0]), "=r"(r[1]), "=r"(r[2]), "=r"(r[3]) : "r"(addr));
}
__device__ __forceinline__ void mma16816_bf(float (&d)[4], const uint32_t (&a)[4],
                                            uint32_t b0, uint32_t b1) {
    asm volatile(
        "mma.sync.aligned.m16n8k16.row.col.f32.bf16.bf16.f32 "
        "{%0,%1,%2,%3}, {%4,%5,%6,%7}, {%8,%9}, {%0,%1,%2,%3};"
        : "+f"(d[0]), "+f"(d[1]), "+f"(d[2]), "+f"(d[3])
        : "r"(a[0]), "r"(a[1]), "r"(a[2]), "r"(a[3]), "r"(b0), "r"(b1));
}
__device__ __forceinline__ void mma16816_f16(float (&d)[4], const uint32_t (&a)[4],
                                             uint32_t b0, uint32_t b1) {
    asm volatile(
        "mma.sync.aligned.m16n8k16.row.col.f32.f16.f16.f32 "
        "{%0,%1,%2,%3}, {%4,%5,%6,%7}, {%8,%9}, {%0,%1,%2,%3};"
        : "+f"(d[0]), "+f"(d[1]), "+f"(d[2]), "+f"(d[3])
        : "r"(a[0]), "r"(a[1]), "r"(a[2]), "r"(a[3]), "r"(b0), "r"(b1));
}

// ---------------------------------------------------------------------------
// prep_x: x[n][c][p] -> xTh[n][p][c] fp16 + xdbf hi/lo (channels 0..255)
// ---------------------------------------------------------------------------
__global__ void prep_x(const float* __restrict__ x, __half* __restrict__ xTh,
                       __nv_bfloat16* __restrict__ xd) {
    __shared__ float t[32][33];
    int n = blockIdx.z;
    int p0 = blockIdx.x * 32, c0 = blockIdx.y * 32;
    int tx = threadIdx.x, ty = threadIdx.y;
#pragma unroll
    for (int j = 0; j < 32; j += 8)
        t[ty + j][tx] = x[((size_t)n * CIN + c0 + ty + j) * HW + p0 + tx];
    __syncthreads();
#pragma unroll
    for (int j = 0; j < 32; j += 8) {
        float v = t[tx][ty + j];
        size_t prow = (size_t)n * HW + p0 + ty + j;
        int c = c0 + tx;
        xTh[prow * CIN + c] = __float2half(v);
        __nv_bfloat16 hb = __float2bfloat16(v);
        xd[prow * 640 + c] = hb;
        xd[prow * 640 + 320 + c] = __float2bfloat16(v - __bfloat162float(hb));
    }
}

// ---------------------------------------------------------------------------
// prep_d: depth[n][c][p] -> dT[n][p][c] f32 + xdbf hi/lo (channels 256..319)
// ---------------------------------------------------------------------------
__global__ void prep_d(const float* __restrict__ depth, float* __restrict__ dT,
                       __nv_bfloat16* __restrict__ xd) {
    __shared__ float t[32][33];
    int n = blockIdx.z;
    int p0 = blockIdx.x * 32, c0 = blockIdx.y * 32;
    int tx = threadIdx.x, ty = threadIdx.y;
#pragma unroll
    for (int j = 0; j < 32; j += 8)
        t[ty + j][tx] = depth[((size_t)n * DC + c0 + ty + j) * HW + p0 + tx];
    __syncthreads();
#pragma unroll
    for (int j = 0; j < 32; j += 8) {
        float v = t[tx][ty + j];
        size_t prow = (size_t)n * HW + p0 + ty + j;
        int c = c0 + tx;
        dT[prow * DC + c] = v;
        __nv_bfloat16 hb = __float2bfloat16(v);
        xd[prow * 640 + 256 + c] = hb;
        xd[prow * 640 + 576 + c] = __float2bfloat16(v - __bfloat162float(hb));
    }
}

// ---------------------------------------------------------------------------
// Weight preps
// ---------------------------------------------------------------------------
__global__ void prep_w_kernel(const float* __restrict__ w,
                              __half* __restrict__ wh) {
    int cout = blockIdx.x;
    int c = threadIdx.x;
#pragma unroll
    for (int k = 0; k < 9; k++) {
        float v = w[((size_t)cout * 256 + c) * 9 + k];
        wh[(size_t)cout * KP3 + k * 256 + c] = __float2half(v);
    }
}

__global__ void prep_s1w(const float* __restrict__ ow, __nv_bfloat16* __restrict__ ws) {
    int m = blockIdx.x;
    int c = threadIdx.x;
#pragma unroll
    for (int kk = 0; kk < 9; kk++) {
        float v = (m < 18) ? ow[((size_t)m * 320 + c) * 9 + kk] : 0.f;
        __nv_bfloat16 hb = __float2bfloat16(v);
        __nv_bfloat16 lb = __float2bfloat16(v - __bfloat162float(hb));
        size_t b = (size_t)m * S1K + kk * 320 + c;
        ws[b] = hb;
        ws[b + 2880] = hb;
        ws[b + 5760] = lb;
    }
}

// ---------------------------------------------------------------------------
// Stage-1 HMMA GEMM (implicit im2col, bf16 3-pass)
// ---------------------------------------------------------------------------
#define S1_AB 16384
#define S1_BB 4096
#define S1_STG (S1_AB + S1_BB)

__global__ void __launch_bounds__(256, 1)
s1_hmma(const __nv_bfloat16* __restrict__ xd, const __nv_bfloat16* __restrict__ ws,
        const float* __restrict__ offb, float* __restrict__ offsets) {
    extern __shared__ char smem[];
    const uint32_t sb = smem_u32(smem);
    const int tid = threadIdx.x;
    const int wid = tid >> 5, lane = tid & 31;
    const int p0 = blockIdx.x * 128;
    const int n = blockIdx.z;
    const __nv_bfloat16* xdn = xd + (size_t)n * HW * 640;

    float acc[4][4];
#pragma unroll
    for (int i = 0; i < 4; i++)
#pragma unroll
        for (int r = 0; r < 4; r++) acc[i][r] = 0.f;

    auto load_chunk = [&](int kc, int buf) {
        int pass = kc / 45;
        int r = kc - pass * 45;
        int tap = r / 5;
        int c0 = (r - tap * 5) * 64;
        int ah = (pass == 1) ? 320 : 0;
        int dr = tap / 3 - 1, dc = tap % 3 - 1;
        uint32_t dA = sb + buf * S1_STG;
        uint32_t dB = dA + S1_AB;
#pragma unroll
        for (int u = 0; u < 4; u++) {
            int idx = tid + u * 256;
            int row = idx >> 3, q = idx & 7;
            int gp = p0 + row;
            int h = gp >> 6, w = gp & 63;
            int iy = h + dr, ix = w + dc;
            bool v = (iy >= 0) & (iy < HH) & (ix >= 0) & (ix < WW);
            int pn = v ? iy * WW + ix : 0;
            cp_async16_z(dA + row * 128 + ((q ^ (row & 7)) << 4),
                         xdn + (size_t)pn * 640 + ah + c0 + q * 8, v);
        }
        {
            int row = tid >> 3, q = tid & 7;
            cp_async16(dB + row * 128 + ((q ^ (row & 7)) << 4),
                       ws + (size_t)row * S1K + kc * 64 + q * 8);
        }
        cp_commit();
    };

    auto compute_chunk = [&](int buf) {
        uint32_t Ab = sb + buf * S1_STG;
        uint32_t Bb = Ab + S1_AB;
        const int rbase = ((lane >> 3) & 1) * 8 + (lane & 7);
        const int chi = (lane >> 4);
#pragma unroll
        for (int ks = 0; ks < 4; ks++) {
            int c = ks * 2 + chi;
            uint32_t af[4], bf[2][4];
            {
                int row = wid * 16 + rbase;
                ldsm_x4(af, Ab + row * 128 + ((c ^ (row & 7)) << 4));
            }
#pragma unroll
            for (int j = 0; j < 2; j++) {
                int row = j * 16 + rbase;
                ldsm_x4(bf[j], Bb + row * 128 + ((c ^ (row & 7)) << 4));
            }
#pragma unroll
            for (int j = 0; j < 2; j++)
#pragma unroll
                for (int s = 0; s < 2; s++)
                    mma16816_bf(acc[j * 2 + s], af, bf[j][s], bf[j][s + 2]);
        }
    };

    load_chunk(0, 0);
    load_chunk(1, 1);
    for (int kc = 0; kc < S1CHUNKS; kc++) {
        int buf = kc % 3;
        if (kc + 1 < S1CHUNKS) cp_wait<1>(); else cp_wait<0>();
        __syncthreads();
        if (kc + 2 < S1CHUNKS) load_chunk(kc + 2, (kc + 2) % 3);
        compute_chunk(buf);
    }

#pragma unroll
    for (int j = 0; j < 2; j++)
#pragma unroll
        for (int s = 0; s < 2; s++) {
            int m = j * 16 + s * 8 + (lane & 3) * 2;
            if (m < 18) {
                float b0 = offb[m], b1 = offb[m + 1];
                int row = wid * 16 + (lane >> 2);
                float* o = offsets + ((size_t)n * 18 + m) * HW + p0;
                const float* a = acc[j * 2 + s];
                o[row]          = a[0] + b0;
                o[HW + row]     = a[1] + b1;
                o[row + 8]      = a[2] + b0;
                o[HW + row + 8] = a[3] + b1;
            }
        }
}

// ---------------------------------------------------------------------------
// Stage-2 FUSED: mask = sigmoid(deform_conv(depthT, offset) + mb)
// ---------------------------------------------------------------------------
__global__ void __launch_bounds__(256)
fused_mask(const float* __restrict__ depthT, const float* __restrict__ offs,
           const float* __restrict__ mw, const float* __restrict__ mb,
           float* __restrict__ maskbuf) {
    __shared__ float ws[9][9][64];
    __shared__ float sbias[9];
    const int tid = threadIdx.x;
    const int n = blockIdx.y;

    for (int i = tid; i < 5184; i += 256) {
        int m = i / 576;
        int rem = i - m * 576;
        int c = rem / 9;
        int k = rem - 9 * c;
        ws[k][m][c] = mw[i];
    }
    if (tid < 9) sbias[tid] = mb[tid];
    __syncthreads();

    const int wid = tid >> 5, lane = tid & 31;
    const int p = blockIdx.x * 8 + wid;
    const int h = p >> 6, w = p & 63;
    const float* dn = depthT + (size_t)n * HW * DC;
    const float* offn = offs + (size_t)n * 18 * HW;

    float acc[9];
#pragma unroll
    for (int m = 0; m < 9; m++) acc[m] = 0.f;

#pragma unroll
    for (int k = 0; k < 9; k++) {
        float dy = offn[(size_t)(2 * k) * HW + p];
        float dx = offn[(size_t)(2 * k + 1) * HW + p];
        float y = (float)(h - 1 + k / 3) + dy;
        float xx = (float)(w - 1 + k % 3) + dx;
        float y0f = floorf(y), x0f = floorf(xx);
        float ly = y - y0f, lx = xx - x0f;
        int y0 = (int)y0f, x0 = (int)x0f;
        int y1 = y0 + 1, x1 = x0 + 1;
        bool vy0 = (y0 >= 0) & (y0 < HH);
        bool vy1 = (y1 >= 0) & (y1 < HH);
        bool vx0 = (x0 >= 0) & (x0 < WW);
        bool vx1 = (x1 >= 0) & (x1 < WW);
        float w00 = (vy0 & vx0) ? (1.f - ly) * (1.f - lx) : 0.f;
        float w01 = (vy0 & vx1) ? (1.f - ly) * lx : 0.f;
        float w10 = (vy1 & vx0) ? ly * (1.f - lx) : 0.f;
        float w11 = (vy1 & vx1) ? ly * lx : 0.f;
        int i00 = (vy0 & vx0) ? y0 * WW + x0 : 0;
        int i01 = (vy0 & vx1) ? y0 * WW + x1 : 0;
        int i10 = (vy1 & vx0) ? y1 * WW + x0 : 0;
        int i11 = (vy1 & vx1) ? y1 * WW + x1 : 0;
        int cc = lane * 2;
        float2 a = *reinterpret_cast<const float2*>(dn + (size_t)i00 * DC + cc);
        float2 b = *reinterpret_cast<const float2*>(dn + (size_t)i01 * DC + cc);
        float2 cv = *reinterpret_cast<const float2*>(dn + (size_t)i10 * DC + cc);
        float2 d = *reinterpret_cast<const float2*>(dn + (size_t)i11 * DC + cc);
        float v0 = w00 * a.x + w01 * b.x + w10 * cv.x + w11 * d.x;
        float v1 = w00 * a.y + w01 * b.y + w10 * cv.y + w11 * d.y;
#pragma unroll
        for (int m = 0; m < 9; m++) {
            float2 wv = *reinterpret_cast<const float2*>(&ws[k][m][cc]);
            acc[m] += wv.x * v0 + wv.y * v1;
        }
    }

#pragma unroll
    for (int m = 0; m < 9; m++) {
#pragma unroll
        for (int off = 16; off > 0; off >>= 1)
            acc[m] += __shfl_xor_sync(0xFFFFFFFFu, acc[m], off);
    }
    if (lane == 0) {
        float* mp = maskbuf + (size_t)n * 9 * HW + p;
#pragma unroll
        for (int m = 0; m < 9; m++) {
            float v = acc[m] + sbias[m];
            mp[(size_t)m * HW] = 1.f / (1.f + expf(-v));
        }
    }
}

// ---------------------------------------------------------------------------
// Stage-3 deformable im2col: warp-per-pixel, fp16 gathers + fp16 output.
// ---------------------------------------------------------------------------
__global__ void __launch_bounds__(256)
deform_im2col_f16(const __half* __restrict__ xTh, const float* __restrict__ offs,
                  const float* __restrict__ mask, __half* __restrict__ colsT) {
    const int tid = threadIdx.x;
    const int wid = tid >> 5, lane = tid & 31;
    const int n = blockIdx.y;
    const int p = blockIdx.x * 8 + wid;
    const int h = p >> 6, w = p & 63;
    const float* offn = offs + (size_t)n * 18 * HW;
    const float* maskn = mask + (size_t)n * 9 * HW;
    const __half* src = xTh + (size_t)n * HW * CIN;
    __half* outp = colsT + ((size_t)n * HW + p) * KP3;
    const int cc = lane * 8;

#pragma unroll
    for (int k = 0; k < 9; k++) {
        float dy = offn[(size_t)(2 * k) * HW + p];
        float dx = offn[(size_t)(2 * k + 1) * HW + p];
        float mk = maskn[(size_t)k * HW + p];
        float y = (float)(h - 1 + k / 3) + dy;
        float xx = (float)(w - 1 + k % 3) + dx;
        float y0f = floorf(y), x0f = floorf(xx);
        float ly = y - y0f, lx = xx - x0f;
        int y0 = (int)y0f, x0 = (int)x0f;
        int y1 = y0 + 1, x1 = x0 + 1;
        bool vy0 = (y0 >= 0) & (y0 < HH);
        bool vy1 = (y1 >= 0) & (y1 < HH);
        bool vx0 = (x0 >= 0) & (x0 < WW);
        bool vx1 = (x1 >= 0) & (x1 < WW);
        float w00 = (vy0 & vx0) ? (1.f - ly) * (1.f - lx) * mk : 0.f;
        float w01 = (vy0 & vx1) ? (1.f - ly) * lx * mk : 0.f;
        float w10 = (vy1 & vx0) ? ly * (1.f - lx) * mk : 0.f;
        float w11 = (vy1 & vx1) ? ly * lx * mk : 0.f;
        int i00 = (vy0 & vx0) ? y0 * WW + x0 : 0;
        int i01 = (vy0 & vx1) ? y0 * WW + x1 : 0;
        int i10 = (vy1 & vx0) ? y1 * WW + x0 : 0;
        int i11 = (vy1 & vx1) ? y1 * WW + x1 : 0;

        uint4 A = *reinterpret_cast<const uint4*>(src + (size_t)i00 * CIN + cc);
        uint4 B = *reinterpret_cast<const uint4*>(src + (size_t)i01 * CIN + cc);
        uint4 C = *reinterpret_cast<const uint4*>(src + (size_t)i10 * CIN + cc);
        uint4 D = *reinterpret_cast<const uint4*>(src + (size_t)i11 * CIN + cc);
        const __half2* a2 = reinterpret_cast<const __half2*>(&A);
        const __half2* b2 = reinterpret_cast<const __half2*>(&B);
        const __half2* c2 = reinterpret_cast<const __half2*>(&C);
        const __half2* d2 = reinterpret_cast<const __half2*>(&D);

        __align__(16) __half hv[8];
#pragma unroll
        for (int j = 0; j < 4; j++) {
            float2 av = __half22float2(a2[j]);
            float2 bv = __half22float2(b2[j]);
            float2 cv = __half22float2(c2[j]);
            float2 dv = __half22float2(d2[j]);
            hv[2 * j]     = __float2half(w00 * av.x + w01 * bv.x + w10 * cv.x + w11 * dv.x);
            hv[2 * j + 1] = __float2half(w00 * av.y + w01 * bv.y + w10 * cv.y + w11 * dv.y);
        }
        *reinterpret_cast<uint4*>(outp + k * 256 + cc) = *reinterpret_cast<uint4*>(hv);
    }
}

// ---------------------------------------------------------------------------
// Stage-3 HMMA GEMM v2: M=256 px x N=128 couts per CTA, BK=128, 2-stage.
// grid (HW/256, 2, NB) = 128 CTAs; warp grid 4(M) x 2(N), warp tile 64x64.
// ---------------------------------------------------------------------------
#define A3BYTES 32768          /* 256 rows x 128B */
#define B3BYTES 16384          /* 128 rows x 128B */
#define STG3 (A3BYTES + B3BYTES)   /* one 64-col half-chunk: 48KB */
#define STG3x2 (2 * STG3)          /* BK=128 stage: 96KB */

__global__ void __launch_bounds__(256, 1)
hmma_gemm(const __half* __restrict__ colsT, const __half* __restrict__ wh,
          const float* __restrict__ bias, float* __restrict__ out) {
    extern __shared__ char smem[];
    const uint32_t sb = smem_u32(smem);
    const int tid = threadIdx.x;
    const int wid = tid >> 5, lane = tid & 31;
    const int wm = wid >> 1, wn = wid & 1;       // 4 x 2 warp grid
    const int p0 = blockIdx.x * 256;
    const int cout0 = blockIdx.y * 128;
    const int n = blockIdx.z;

    const char* Ag = (const char*)(colsT + (size_t)(n * HW + p0) * KP3);
    const char* Bg = (const char*)(wh + (size_t)cout0 * KP3);

    float acc[4][8][4];
#pragma unroll
    for (int i = 0; i < 4; i++)
#pragma unroll
        for (int j = 0; j < 8; j++)
#pragma unroll
            for (int r = 0; r < 4; r++) acc[i][j][r] = 0.f;

    auto load_stage = [&](int t, int s) {
#pragma unroll
        for (int half = 0; half < 2; half++) {
            int kt = 2 * t + half;
            uint32_t dA = sb + s * STG3x2 + half * STG3;
            uint32_t dB = dA + A3BYTES;
            // A: 256 rows x 8 chunks -> 8 per thread
#pragma unroll
            for (int u = 0; u < 8; u++) {
                int idx = tid + u * 256;
                int row = idx >> 3, c = idx & 7;
                cp_async16(dA + row * 128 + ((c ^ (row & 7)) << 4),
                           Ag + (size_t)row * KROW3 + kt * 128 + c * 16);
            }
            // B: 128 rows x 8 chunks -> 4 per thread
#pragma unroll
            for (int u = 0; u < 4; u++) {
                int idx = tid + u * 256;
                int row = idx >> 3, c = idx & 7;
                cp_async16(dB + row * 128 + ((c ^ (row & 7)) << 4),
                           Bg + (size_t)row * KROW3 + kt * 128 + c * 16);
            }
        }
        cp_commit();
    };

    auto compute_stage = [&](int s) {
        const int rbase = ((lane >> 3) & 1) * 8 + (lane & 7);
        const int chi = (lane >> 4);
#pragma unroll
        for (int half = 0; half < 2; half++) {
            uint32_t Ab = sb + s * STG3x2 + half * STG3;
            uint32_t Bb = Ab + A3BYTES;
#pragma unroll
            for (int ks = 0; ks < 4; ks++) {
                int c = ks * 2 + chi;
                uint32_t af[4][4], bf[4][4];
#pragma unroll
                for (int i = 0; i < 4; i++) {
                    int row = wm * 64 + i * 16 + rbase;
                    ldsm_x4(af[i], Ab + row * 128 + ((c ^ (row & 7)) << 4));
                }
#pragma unroll
                for (int j = 0; j < 4; j++) {
                    int row = wn * 64 + j * 16 + rbase;
                    ldsm_x4(bf[j], Bb + row * 128 + ((c ^ (row & 7)) << 4));
                }
#pragma unroll
                for (int i = 0; i < 4; i++)
#pragma unroll
                    for (int j = 0; j < 4; j++)
#pragma unroll
                        for (int s2 = 0; s2 < 2; s2++)
                            mma16816_f16(acc[i][j * 2 + s2], af[i], bf[j][s2], bf[j][s2 + 2]);
            }
        }
    };

    load_stage(0, 0);
    for (int t = 0; t < K3PAIRS; t++) {
        cp_wait<0>();
        __syncthreads();
        if (t + 1 < K3PAIRS) load_stage(t + 1, (t + 1) & 1);
        compute_stage(t & 1);
    }

#pragma unroll
    for (int i = 0; i < 4; i++) {
        int m = wm * 64 + i * 16 + (lane >> 2);
#pragma unroll
        for (int j = 0; j < 4; j++)
#pragma unroll
            for (int s = 0; s < 2; s++) {
                int cout = cout0 + wn * 64 + j * 16 + s * 8 + (lane & 3) * 2;
                float b0 = bias[cout], b1 = bias[cout + 1];
                float* o = out + ((size_t)n * COUT + cout) * HW + p0;
                const float* a = acc[i][j * 2 + s];
                o[m]          = a[0] + b0;
                o[HW + m]     = a[1] + b1;
                o[m + 8]      = a[2] + b0;
                o[HW + m + 8] = a[3] + b1;
            }
    }
}

// ---------------------------------------------------------------------------
extern "C" void kernel_launch(void* const* d_in, const int* in_sizes, int n_in,
                              void* d_out, int out_size) {
    const float* x      = (const float*)d_in[0];
    const float* depth  = (const float*)d_in[1];
    const float* weight = (const float*)d_in[2];
    const float* bias   = (const float*)d_in[3];
    const float* off_w  = (const float*)d_in[4];
    const float* off_b  = (const float*)d_in[5];
    const float* mask_w = (const float*)d_in[6];
    const float* mask_b = (const float*)d_in[7];
    float* out = (float*)d_out;

    void *po, *pm, *pch, *pwh, *pxh, *pdt, *pxd, *pw1;
    cudaGetSymbolAddress(&po, g_offsets);
    cudaGetSymbolAddress(&pm, g_mask);
    cudaGetSymbolAddress(&pch, g_colsh);
    cudaGetSymbolAddress(&pwh, g_wh);
    cudaGetSymbolAddress(&pxh, g_xTh);
    cudaGetSymbolAddress(&pdt, g_dT);
    cudaGetSymbolAddress(&pxd, g_xdbf);
    cudaGetSymbolAddress(&pw1, g_ws1);
    float* offsets = (float*)po;
    float* maskbuf = (float*)pm;
    __half* colsh = (__half*)pch;
    __half* wh = (__half*)pwh;
    __half* xTh = (__half*)pxh;
    float* dT = (float*)pdt;
    __nv_bfloat16* xdbf = (__nv_bfloat16*)pxd;
    __nv_bfloat16* ws1 = (__nv_bfloat16*)pw1;

    // Prep (fused transpose + precision-split)
    prep_w_kernel<<<COUT, 256>>>(weight, wh);
    prep_s1w<<<32, 320>>>(off_w, ws1);
    prep_x<<<dim3(HW / 32, CIN / 32, NB), dim3(32, 8)>>>(x, xTh, xdbf);
    prep_d<<<dim3(HW / 32, DC / 32, NB), dim3(32, 8)>>>(depth, dT, xdbf);

    static int smem_set = 0;
    if (!smem_set) {
        cudaFuncSetAttribute(s1_hmma, cudaFuncAttributeMaxDynamicSharedMemorySize,
                             3 * S1_STG);
        cudaFuncSetAttribute(hmma_gemm, cudaFuncAttributeMaxDynamicSharedMemorySize,
                             2 * STG3x2);
        smem_set = 1;
    }

    // Stage 1: offset conv via implicit-im2col HMMA GEMM (bf16 3-pass)
    s1_hmma<<<dim3(HW / 128, 1, NB), 256, 3 * S1_STG>>>(xdbf, ws1, off_b, offsets);

    // Stage 2: fused mask = sigmoid(deform_conv(depth, offset))
    fused_mask<<<dim3(HW / 8, NB), 256>>>(dT, offsets, mask_w, mask_b, maskbuf);

    // Stage 3: modulated deformable conv, fp16 single-pass HMMA GEMM
    deform_im2col_f16<<<dim3(HW / 8, NB), 256>>>(xTh, offsets, maskbuf, colsh);
    hmma_gemm<<<dim3(HW / 256, 2, NB), 256, 2 * STG3x2>>>(colsh, wh, bias, out);
}

// round 14
// speedup vs baseline: 5.9452x; 1.0295x over previous
#include <cuda_runtime.h>
#include <cuda_bf16.h>
#include <cuda_fp16.h>
#include <cstdint>
#include <math.h>

#define NB 4
#define HH 64
#define WW 64
#define HW 4096
#define CIN 256
#define DC 64
#define COUT 256
#define KP3 2304               /* stage-3 K: single-pass fp16 */
#define KROW3 (KP3 * 2)
#define K3PAIRS 18
#define S1K 8640               /* stage-1 W cols: 3 * 2880 (bf16 split) */
#define S1STAGES 45            /* 135 chunks / 3 per stage */

// ---------------- device scratch ----------------
__device__ float g_offsets[(size_t)NB * 18 * HW];
__device__ __half g_xTh[(size_t)NB * HW * CIN];            // x NHWC fp16
__device__ float g_dT[(size_t)NB * HW * DC];               // depth NHWC f32
__device__ __nv_bfloat16 g_xdbf[(size_t)NB * HW * 640];    // cat(x,d) [hi320|lo320]
__device__ __nv_bfloat16 g_ws1[(size_t)32 * S1K];          // off_w split, 32 rows
__device__ __half g_colsh[(size_t)NB * HW * KP3];          // 75 MB fp16 cols
__device__ __half g_wh[(size_t)COUT * KP3];                // fp16 weights

// ---------------- PTX helpers ----------------
__device__ __forceinline__ uint32_t smem_u32(const void* p) {
    uint32_t a;
    asm("{ .reg .u64 t; cvta.to.shared.u64 t, %1; cvt.u32.u64 %0, t; }"
        : "=r"(a) : "l"(p));
    return a;
}
__device__ __forceinline__ void cp_async16(uint32_t dst, const void* src) {
    asm volatile("cp.async.cg.shared.global [%0], [%1], 16;"
                 :: "r"(dst), "l"(src) : "memory");
}
__device__ __forceinline__ void cp_async16_z(uint32_t dst, const void* src, bool pred) {
    int sz = pred ? 16 : 0;
    asm volatile("cp.async.cg.shared.global [%0], [%1], 16, %2;"
                 :: "r"(dst), "l"(src), "r"(sz) : "memory");
}
__device__ __forceinline__ void cp_commit() {
    asm volatile("cp.async.commit_group;" ::: "memory");
}
template <int N>
__device__ __forceinline__ void cp_wait() {
    asm volatile("cp.async.wait_group %0;" :: "n"(N) : "memory");
}
__device__ __forceinline__ void ldsm_x4(uint32_t (&r)[4], uint32_t addr) {
    asm volatile("ldmatrix.sync.aligned.m8n8.x4.shared.b16 {%0,%1,%2,%3}, [%4];"
                 : "=r"(r[0]), "=r"(r[1]), "=r"(r[2]), "=r"(r[3]) : "r"(addr));
}
__device__ __forceinline__ void mma16816_bf(float (&d)[4], const uint32_t (&a)[4],
                                            uint32_t b0, uint32_t b1) {
    asm volatile(
        "mma.sync.aligned.m16n8k16.row.col.f32.bf16.bf16.f32 "
        "{%0,%1,%2,%3}, {%4,%5,%6,%7}, {%8,%9}, {%0,%1,%2,%3};"
        : "+f"(d[0]), "+f"(d[1]), "+f"(d[2]), "+f"(d[3])
        : "r"(a[0]), "r"(a[1]), "r"(a[2]), "r"(a[3]), "r"(b0), "r"(b1));
}
__device__ __forceinline__ void mma16816_f16(float (&d)[4], const uint32_t (&a)[4],
                                             uint32_t b0, uint32_t b1) {
    asm volatile(
        "mma.sync.aligned.m16n8k16.row.col.f32.f16.f16.f32 "
        "{%0,%1,%2,%3}, {%4,%5,%6,%7}, {%8,%9}, {%0,%1,%2,%3};"
        : "+f"(d[0]), "+f"(d[1]), "+f"(d[2]), "+f"(d[3])
        : "r"(a[0]), "r"(a[1]), "r"(a[2]), "r"(a[3]), "r"(b0), "r"(b1));
}

// ---------------------------------------------------------------------------
// prep_x: x[n][c][p] -> xTh[n][p][c] fp16 + xdbf hi/lo (channels 0..255)
// ---------------------------------------------------------------------------
__global__ void prep_x(const float* __restrict__ x, __half* __restrict__ xTh,
                       __nv_bfloat16* __restrict__ xd) {
    __shared__ float t[32][33];
    int n = blockIdx.z;
    int p0 = blockIdx.x * 32, c0 = blockIdx.y * 32;
    int tx = threadIdx.x, ty = threadIdx.y;
#pragma unroll
    for (int j = 0; j < 32; j += 8)
        t[ty + j][tx] = x[((size_t)n * CIN + c0 + ty + j) * HW + p0 + tx];
    __syncthreads();
#pragma unroll
    for (int j = 0; j < 32; j += 8) {
        float v = t[tx][ty + j];
        size_t prow = (size_t)n * HW + p0 + ty + j;
        int c = c0 + tx;
        xTh[prow * CIN + c] = __float2half(v);
        __nv_bfloat16 hb = __float2bfloat16(v);
        xd[prow * 640 + c] = hb;
        xd[prow * 640 + 320 + c] = __float2bfloat16(v - __bfloat162float(hb));
    }
}

// ---------------------------------------------------------------------------
// prep_d: depth[n][c][p] -> dT[n][p][c] f32 + xdbf hi/lo (channels 256..319)
// ---------------------------------------------------------------------------
__global__ void prep_d(const float* __restrict__ depth, float* __restrict__ dT,
                       __nv_bfloat16* __restrict__ xd) {
    __shared__ float t[32][33];
    int n = blockIdx.z;
    int p0 = blockIdx.x * 32, c0 = blockIdx.y * 32;
    int tx = threadIdx.x, ty = threadIdx.y;
#pragma unroll
    for (int j = 0; j < 32; j += 8)
        t[ty + j][tx] = depth[((size_t)n * DC + c0 + ty + j) * HW + p0 + tx];
    __syncthreads();
#pragma unroll
    for (int j = 0; j < 32; j += 8) {
        float v = t[tx][ty + j];
        size_t prow = (size_t)n * HW + p0 + ty + j;
        int c = c0 + tx;
        dT[prow * DC + c] = v;
        __nv_bfloat16 hb = __float2bfloat16(v);
        xd[prow * 640 + 256 + c] = hb;
        xd[prow * 640 + 576 + c] = __float2bfloat16(v - __bfloat162float(hb));
    }
}

// ---------------------------------------------------------------------------
// Weight preps
// ---------------------------------------------------------------------------
__global__ void prep_w_kernel(const float* __restrict__ w,
                              __half* __restrict__ wh) {
    int cout = blockIdx.x;
    int c = threadIdx.x;
#pragma unroll
    for (int k = 0; k < 9; k++) {
        float v = w[((size_t)cout * 256 + c) * 9 + k];
        wh[(size_t)cout * KP3 + k * 256 + c] = __float2half(v);
    }
}

__global__ void prep_s1w(const float* __restrict__ ow, __nv_bfloat16* __restrict__ ws) {
    int m = blockIdx.x;
    int c = threadIdx.x;
#pragma unroll
    for (int kk = 0; kk < 9; kk++) {
        float v = (m < 18) ? ow[((size_t)m * 320 + c) * 9 + kk] : 0.f;
        __nv_bfloat16 hb = __float2bfloat16(v);
        __nv_bfloat16 lb = __float2bfloat16(v - __bfloat162float(hb));
        size_t b = (size_t)m * S1K + kk * 320 + c;
        ws[b] = hb;
        ws[b + 2880] = hb;
        ws[b + 5760] = lb;
    }
}

// ---------------------------------------------------------------------------
// Stage-1 HMMA GEMM (implicit im2col, bf16 3-pass), BK=192, 2-stage.
// 45 stages of 3x 64-col chunks; 123 KB smem.
// ---------------------------------------------------------------------------
#define S1_AB 16384
#define S1_BB 4096
#define S1_STG (S1_AB + S1_BB)      /* one 64-col chunk: 20 KB */
#define S1_STG3 (3 * S1_STG)        /* one BK=192 stage: 61.4 KB */

__global__ void __launch_bounds__(256, 1)
s1_hmma(const __nv_bfloat16* __restrict__ xd, const __nv_bfloat16* __restrict__ ws,
        const float* __restrict__ offb, float* __restrict__ offsets) {
    extern __shared__ char smem[];
    const uint32_t sb = smem_u32(smem);
    const int tid = threadIdx.x;
    const int wid = tid >> 5, lane = tid & 31;
    const int p0 = blockIdx.x * 128;
    const int n = blockIdx.z;
    const __nv_bfloat16* xdn = xd + (size_t)n * HW * 640;

    float acc[4][4];
#pragma unroll
    for (int i = 0; i < 4; i++)
#pragma unroll
        for (int r = 0; r < 4; r++) acc[i][r] = 0.f;

    auto load_stage = [&](int st, int s) {
#pragma unroll
        for (int sub = 0; sub < 3; sub++) {
            int kc = 3 * st + sub;
            int pass = kc / 45;
            int r = kc - pass * 45;
            int tap = r / 5;
            int c0 = (r - tap * 5) * 64;
            int ah = (pass == 1) ? 320 : 0;
            int dr = tap / 3 - 1, dc = tap % 3 - 1;
            uint32_t dA = sb + s * S1_STG3 + sub * S1_STG;
            uint32_t dB = dA + S1_AB;
#pragma unroll
            for (int u = 0; u < 4; u++) {
                int idx = tid + u * 256;
                int row = idx >> 3, q = idx & 7;
                int gp = p0 + row;
                int h = gp >> 6, w = gp & 63;
                int iy = h + dr, ix = w + dc;
                bool v = (iy >= 0) & (iy < HH) & (ix >= 0) & (ix < WW);
                int pn = v ? iy * WW + ix : 0;
                cp_async16_z(dA + row * 128 + ((q ^ (row & 7)) << 4),
                             xdn + (size_t)pn * 640 + ah + c0 + q * 8, v);
            }
            {
                int row = tid >> 3, q = tid & 7;
                cp_async16(dB + row * 128 + ((q ^ (row & 7)) << 4),
                           ws + (size_t)row * S1K + kc * 64 + q * 8);
            }
        }
        cp_commit();
    };

    auto compute_stage = [&](int s) {
        const int rbase = ((lane >> 3) & 1) * 8 + (lane & 7);
        const int chi = (lane >> 4);
#pragma unroll
        for (int sub = 0; sub < 3; sub++) {
            uint32_t Ab = sb + s * S1_STG3 + sub * S1_STG;
            uint32_t Bb = Ab + S1_AB;
#pragma unroll
            for (int ks = 0; ks < 4; ks++) {
                int c = ks * 2 + chi;
                uint32_t af[4], bf[2][4];
                {
                    int row = wid * 16 + rbase;
                    ldsm_x4(af, Ab + row * 128 + ((c ^ (row & 7)) << 4));
                }
#pragma unroll
                for (int j = 0; j < 2; j++) {
                    int row = j * 16 + rbase;
                    ldsm_x4(bf[j], Bb + row * 128 + ((c ^ (row & 7)) << 4));
                }
#pragma unroll
                for (int j = 0; j < 2; j++)
#pragma unroll
                    for (int s2 = 0; s2 < 2; s2++)
                        mma16816_bf(acc[j * 2 + s2], af, bf[j][s2], bf[j][s2 + 2]);
            }
        }
    };

    load_stage(0, 0);
    for (int st = 0; st < S1STAGES; st++) {
        cp_wait<0>();
        __syncthreads();
        if (st + 1 < S1STAGES) load_stage(st + 1, (st + 1) & 1);
        compute_stage(st & 1);
    }

#pragma unroll
    for (int j = 0; j < 2; j++)
#pragma unroll
        for (int s = 0; s < 2; s++) {
            int m = j * 16 + s * 8 + (lane & 3) * 2;
            if (m < 18) {
                float b0 = offb[m], b1 = offb[m + 1];
                int row = wid * 16 + (lane >> 2);
                float* o = offsets + ((size_t)n * 18 + m) * HW + p0;
                const float* a = acc[j * 2 + s];
                o[row]          = a[0] + b0;
                o[HW + row]     = a[1] + b1;
                o[row + 8]      = a[2] + b0;
                o[HW + row + 8] = a[3] + b1;
            }
        }
}

// ---------------------------------------------------------------------------
// Stages 2+3 FUSED: per pixel, compute mask[9] = sigmoid(deform_conv(depth)),
// then immediately do the modulated x im2col into fp16 cols.
// Warp = pixel; shfl_xor reduction leaves mask sums in ALL lanes.
// grid (HW/8, NB), 256 threads.
// ---------------------------------------------------------------------------
__global__ void __launch_bounds__(256)
fused_mask_im2col(const float* __restrict__ depthT, const __half* __restrict__ xTh,
                  const float* __restrict__ offs, const float* __restrict__ mw,
                  const float* __restrict__ mb, __half* __restrict__ colsT) {
    __shared__ float ws[9][9][64];
    __shared__ float sbias[9];
    const int tid = threadIdx.x;
    const int n = blockIdx.y;

    for (int i = tid; i < 5184; i += 256) {
        int m = i / 576;
        int rem = i - m * 576;
        int c = rem / 9;
        int k = rem - 9 * c;
        ws[k][m][c] = mw[i];
    }
    if (tid < 9) sbias[tid] = mb[tid];
    __syncthreads();

    const int wid = tid >> 5, lane = tid & 31;
    const int p = blockIdx.x * 8 + wid;
    const int h = p >> 6, w = p & 63;
    const float* dn = depthT + (size_t)n * HW * DC;
    const float* offn = offs + (size_t)n * 18 * HW;

    float dyr[9], dxr[9];
    float acc[9];
#pragma unroll
    for (int m = 0; m < 9; m++) acc[m] = 0.f;

    // ---- Phase 1: mask conv over depth (64 ch, lanes = 2-ch slices) ----
#pragma unroll
    for (int k = 0; k < 9; k++) {
        float dy = offn[(size_t)(2 * k) * HW + p];
        float dx = offn[(size_t)(2 * k + 1) * HW + p];
        dyr[k] = dy; dxr[k] = dx;
        float y = (float)(h - 1 + k / 3) + dy;
        float xx = (float)(w - 1 + k % 3) + dx;
        float y0f = floorf(y), x0f = floorf(xx);
        float ly = y - y0f, lx = xx - x0f;
        int y0 = (int)y0f, x0 = (int)x0f;
        int y1 = y0 + 1, x1 = x0 + 1;
        bool vy0 = (y0 >= 0) & (y0 < HH);
        bool vy1 = (y1 >= 0) & (y1 < HH);
        bool vx0 = (x0 >= 0) & (x0 < WW);
        bool vx1 = (x1 >= 0) & (x1 < WW);
        float w00 = (vy0 & vx0) ? (1.f - ly) * (1.f - lx) : 0.f;
        float w01 = (vy0 & vx1) ? (1.f - ly) * lx : 0.f;
        float w10 = (vy1 & vx0) ? ly * (1.f - lx) : 0.f;
        float w11 = (vy1 & vx1) ? ly * lx : 0.f;
        int i00 = (vy0 & vx0) ? y0 * WW + x0 : 0;
        int i01 = (vy0 & vx1) ? y0 * WW + x1 : 0;
        int i10 = (vy1 & vx0) ? y1 * WW + x0 : 0;
        int i11 = (vy1 & vx1) ? y1 * WW + x1 : 0;
        int cc = lane * 2;
        float2 a = *reinterpret_cast<const float2*>(dn + (size_t)i00 * DC + cc);
        float2 b = *reinterpret_cast<const float2*>(dn + (size_t)i01 * DC + cc);
        float2 cv = *reinterpret_cast<const float2*>(dn + (size_t)i10 * DC + cc);
        float2 d = *reinterpret_cast<const float2*>(dn + (size_t)i11 * DC + cc);
        float v0 = w00 * a.x + w01 * b.x + w10 * cv.x + w11 * d.x;
        float v1 = w00 * a.y + w01 * b.y + w10 * cv.y + w11 * d.y;
#pragma unroll
        for (int m = 0; m < 9; m++) {
            float2 wv = *reinterpret_cast<const float2*>(&ws[k][m][cc]);
            acc[m] += wv.x * v0 + wv.y * v1;
        }
    }

#pragma unroll
    for (int m = 0; m < 9; m++) {
#pragma unroll
        for (int off = 16; off > 0; off >>= 1)
            acc[m] += __shfl_xor_sync(0xFFFFFFFFu, acc[m], off);
        acc[m] = 1.f / (1.f + expf(-(acc[m] + sbias[m])));   // mask value, all lanes
    }

    // ---- Phase 2: modulated im2col over x (256 ch, lanes = 8-ch slices) ----
    const __half* src = xTh + (size_t)n * HW * CIN;
    __half* outp = colsT + ((size_t)n * HW + p) * KP3;
    const int cc8 = lane * 8;

#pragma unroll
    for (int k = 0; k < 9; k++) {
        float mk = acc[k];
        float y = (float)(h - 1 + k / 3) + dyr[k];
        float xx = (float)(w - 1 + k % 3) + dxr[k];
        float y0f = floorf(y), x0f = floorf(xx);
        float ly = y - y0f, lx = xx - x0f;
        int y0 = (int)y0f, x0 = (int)x0f;
        int y1 = y0 + 1, x1 = x0 + 1;
        bool vy0 = (y0 >= 0) & (y0 < HH);
        bool vy1 = (y1 >= 0) & (y1 < HH);
        bool vx0 = (x0 >= 0) & (x0 < WW);
        bool vx1 = (x1 >= 0) & (x1 < WW);
        float w00 = (vy0 & vx0) ? (1.f - ly) * (1.f - lx) * mk : 0.f;
        float w01 = (vy0 & vx1) ? (1.f - ly) * lx * mk : 0.f;
        float w10 = (vy1 & vx0) ? ly * (1.f - lx) * mk : 0.f;
        float w11 = (vy1 & vx1) ? ly * lx * mk : 0.f;
        int i00 = (vy0 & vx0) ? y0 * WW + x0 : 0;
        int i01 = (vy0 & vx1) ? y0 * WW + x1 : 0;
        int i10 = (vy1 & vx0) ? y1 * WW + x0 : 0;
        int i11 = (vy1 & vx1) ? y1 * WW + x1 : 0;

        uint4 A = *reinterpret_cast<const uint4*>(src + (size_t)i00 * CIN + cc8);
        uint4 B = *reinterpret_cast<const uint4*>(src + (size_t)i01 * CIN + cc8);
        uint4 C = *reinterpret_cast<const uint4*>(src + (size_t)i10 * CIN + cc8);
        uint4 D = *reinterpret_cast<const uint4*>(src + (size_t)i11 * CIN + cc8);
        const __half2* a2 = reinterpret_cast<const __half2*>(&A);
        const __half2* b2 = reinterpret_cast<const __half2*>(&B);
        const __half2* c2 = reinterpret_cast<const __half2*>(&C);
        const __half2* d2 = reinterpret_cast<const __half2*>(&D);

        __align__(16) __half hv[8];
#pragma unroll
        for (int j = 0; j < 4; j++) {
            float2 av = __half22float2(a2[j]);
            float2 bv = __half22float2(b2[j]);
            float2 cv = __half22float2(c2[j]);
            float2 dv = __half22float2(d2[j]);
            hv[2 * j]     = __float2half(w00 * av.x + w01 * bv.x + w10 * cv.x + w11 * dv.x);
            hv[2 * j + 1] = __float2half(w00 * av.y + w01 * bv.y + w10 * cv.y + w11 * dv.y);
        }
        *reinterpret_cast<uint4*>(outp + k * 256 + cc8) = *reinterpret_cast<uint4*>(hv);
    }
}

// ---------------------------------------------------------------------------
// Stage-3 HMMA GEMM: M=256 x N=128 per CTA, BK=128, 2-stage.
// ---------------------------------------------------------------------------
#define A3BYTES 32768
#define B3BYTES 16384
#define STG3 (A3BYTES + B3BYTES)
#define STG3x2 (2 * STG3)

__global__ void __launch_bounds__(256, 1)
hmma_gemm(const __half* __restrict__ colsT, const __half* __restrict__ wh,
          const float* __restrict__ bias, float* __restrict__ out) {
    extern __shared__ char smem[];
    const uint32_t sb = smem_u32(smem);
    const int tid = threadIdx.x;
    const int wid = tid >> 5, lane = tid & 31;
    const int wm = wid >> 1, wn = wid & 1;
    const int p0 = blockIdx.x * 256;
    const int cout0 = blockIdx.y * 128;
    const int n = blockIdx.z;

    const char* Ag = (const char*)(colsT + (size_t)(n * HW + p0) * KP3);
    const char* Bg = (const char*)(wh + (size_t)cout0 * KP3);

    float acc[4][8][4];
#pragma unroll
    for (int i = 0; i < 4; i++)
#pragma unroll
        for (int j = 0; j < 8; j++)
#pragma unroll
            for (int r = 0; r < 4; r++) acc[i][j][r] = 0.f;

    auto load_stage = [&](int t, int s) {
#pragma unroll
        for (int half = 0; half < 2; half++) {
            int kt = 2 * t + half;
            uint32_t dA = sb + s * STG3x2 + half * STG3;
            uint32_t dB = dA + A3BYTES;
#pragma unroll
            for (int u = 0; u < 8; u++) {
                int idx = tid + u * 256;
                int row = idx >> 3, c = idx & 7;
                cp_async16(dA + row * 128 + ((c ^ (row & 7)) << 4),
                           Ag + (size_t)row * KROW3 + kt * 128 + c * 16);
            }
#pragma unroll
            for (int u = 0; u < 4; u++) {
                int idx = tid + u * 256;
                int row = idx >> 3, c = idx & 7;
                cp_async16(dB + row * 128 + ((c ^ (row & 7)) << 4),
                           Bg + (size_t)row * KROW3 + kt * 128 + c * 16);
            }
        }
        cp_commit();
    };

    auto compute_stage = [&](int s) {
        const int rbase = ((lane >> 3) & 1) * 8 + (lane & 7);
        const int chi = (lane >> 4);
#pragma unroll
        for (int half = 0; half < 2; half++) {
            uint32_t Ab = sb + s * STG3x2 + half * STG3;
            uint32_t Bb = Ab + A3BYTES;
#pragma unroll
            for (int ks = 0; ks < 4; ks++) {
                int c = ks * 2 + chi;
                uint32_t af[4][4], bf[4][4];
#pragma unroll
                for (int i = 0; i < 4; i++) {
                    int row = wm * 64 + i * 16 + rbase;
                    ldsm_x4(af[i], Ab + row * 128 + ((c ^ (row & 7)) << 4));
                }
#pragma unroll
                for (int j = 0; j < 4; j++) {
                    int row = wn * 64 + j * 16 + rbase;
                    ldsm_x4(bf[j], Bb + row * 128 + ((c ^ (row & 7)) << 4));
                }
#pragma unroll
                for (int i = 0; i < 4; i++)
#pragma unroll
                    for (int j = 0; j < 4; j++)
#pragma unroll
                        for (int s2 = 0; s2 < 2; s2++)
                            mma16816_f16(acc[i][j * 2 + s2], af[i], bf[j][s2], bf[j][s2 + 2]);
            }
        }
    };

    load_stage(0, 0);
    for (int t = 0; t < K3PAIRS; t++) {
        cp_wait<0>();
        __syncthreads();
        if (t + 1 < K3PAIRS) load_stage(t + 1, (t + 1) & 1);
        compute_stage(t & 1);
    }

#pragma unroll
    for (int i = 0; i < 4; i++) {
        int m = wm * 64 + i * 16 + (lane >> 2);
#pragma unroll
        for (int j = 0; j < 4; j++)
#pragma unroll
            for (int s = 0; s < 2; s++) {
                int cout = cout0 + wn * 64 + j * 16 + s * 8 + (lane & 3) * 2;
                float b0 = bias[cout], b1 = bias[cout + 1];
                float* o = out + ((size_t)n * COUT + cout) * HW + p0;
                const float* a = acc[i][j * 2 + s];
                o[m]          = a[0] + b0;
                o[HW + m]     = a[1] + b1;
                o[m + 8]      = a[2] + b0;
                o[HW + m + 8] = a[3] + b1;
            }
    }
}

// ---------------------------------------------------------------------------
extern "C" void kernel_launch(void* const* d_in, const int* in_sizes, int n_in,
                              void* d_out, int out_size) {
    const float* x      = (const float*)d_in[0];
    const float* depth  = (const float*)d_in[1];
    const float* weight = (const float*)d_in[2];
    const float* bias   = (const float*)d_in[3];
    const float* off_w  = (const float*)d_in[4];
    const float* off_b  = (const float*)d_in[5];
    const float* mask_w = (const float*)d_in[6];
    const float* mask_b = (const float*)d_in[7];
    float* out = (float*)d_out;

    void *po, *pch, *pwh, *pxh, *pdt, *pxd, *pw1;
    cudaGetSymbolAddress(&po, g_offsets);
    cudaGetSymbolAddress(&pch, g_colsh);
    cudaGetSymbolAddress(&pwh, g_wh);
    cudaGetSymbolAddress(&pxh, g_xTh);
    cudaGetSymbolAddress(&pdt, g_dT);
    cudaGetSymbolAddress(&pxd, g_xdbf);
    cudaGetSymbolAddress(&pw1, g_ws1);
    float* offsets = (float*)po;
    __half* colsh = (__half*)pch;
    __half* wh = (__half*)pwh;
    __half* xTh = (__half*)pxh;
    float* dT = (float*)pdt;
    __nv_bfloat16* xdbf = (__nv_bfloat16*)pxd;
    __nv_bfloat16* ws1 = (__nv_bfloat16*)pw1;

    // Prep (fused transpose + precision-split)
    prep_w_kernel<<<COUT, 256>>>(weight, wh);
    prep_s1w<<<32, 320>>>(off_w, ws1);
    prep_x<<<dim3(HW / 32, CIN / 32, NB), dim3(32, 8)>>>(x, xTh, xdbf);
    prep_d<<<dim3(HW / 32, DC / 32, NB), dim3(32, 8)>>>(depth, dT, xdbf);

    static int smem_set = 0;
    if (!smem_set) {
        cudaFuncSetAttribute(s1_hmma, cudaFuncAttributeMaxDynamicSharedMemorySize,
                             2 * S1_STG3);
        cudaFuncSetAttribute(hmma_gemm, cudaFuncAttributeMaxDynamicSharedMemorySize,
                             2 * STG3x2);
        smem_set = 1;
    }

    // Stage 1: offset conv via implicit-im2col HMMA GEMM (bf16 3-pass, BK=192)
    s1_hmma<<<dim3(HW / 128, 1, NB), 256, 2 * S1_STG3>>>(xdbf, ws1, off_b, offsets);

    // Stages 2+3 fused: mask conv + modulated im2col in one pass
    fused_mask_im2col<<<dim3(HW / 8, NB), 256>>>(dT, xTh, offsets, mask_w, mask_b,
                                                 colsh);

    // Stage-3 GEMM
    hmma_gemm<<<dim3(HW / 256, 2, NB), 256, 2 * STG3x2>>>(colsh, wh, bias, out);
}

// round 16
// speedup vs baseline: 6.3296x; 1.0647x over previous
#include <cuda_runtime.h>
#include <cuda_bf16.h>
#include <cuda_fp16.h>
#include <cstdint>
#include <math.h>

#define NB 4
#define HH 64
#define WW 64
#define HW 4096
#define CIN 256
#define DC 64
#define COUT 256
#define KP3 2304               /* stage-3 K: single-pass fp16 */
#define KROW3 (KP3 * 2)
#define K3PAIRS 18
#define S1K 8640               /* stage-1 W cols: 3 * 2880 (bf16 split) */
#define S1STAGES 45

#define EPW 264                /* epilogue smem row stride (floats, 16B-mult) */

// ---------------- device scratch ----------------
__device__ float g_offsets[(size_t)NB * 18 * HW];
__device__ __half g_xTh[(size_t)NB * HW * CIN];            // x NHWC fp16
__device__ float g_dT[(size_t)NB * HW * DC];               // depth NHWC f32
__device__ __nv_bfloat16 g_xdbf[(size_t)NB * HW * 640];    // cat(x,d) [hi320|lo320]
__device__ __nv_bfloat16 g_ws1[(size_t)32 * S1K];          // off_w split, 32 rows
__device__ __half g_colsh[(size_t)NB * HW * KP3];          // 75 MB fp16 cols
__device__ __half g_wh[(size_t)COUT * KP3];                // fp16 weights

// ---------------- PTX helpers ----------------
__device__ __forceinline__ uint32_t smem_u32(const void* p) {
    uint32_t a;
    asm("{ .reg .u64 t; cvta.to.shared.u64 t, %1; cvt.u32.u64 %0, t; }"
        : "=r"(a) : "l"(p));
    return a;
}
__device__ __forceinline__ void cp_async16(uint32_t dst, const void* src) {
    asm volatile("cp.async.cg.shared.global [%0], [%1], 16;"
                 :: "r"(dst), "l"(src) : "memory");
}
__device__ __forceinline__ void cp_async16_z(uint32_t dst, const void* src, bool pred) {
    int sz = pred ? 16 : 0;
    asm volatile("cp.async.cg.shared.global [%0], [%1], 16, %2;"
                 :: "r"(dst), "l"(src), "r"(sz) : "memory");
}
__device__ __forceinline__ void cp_commit() {
    asm volatile("cp.async.commit_group;" ::: "memory");
}
template <int N>
__device__ __forceinline__ void cp_wait() {
    asm volatile("cp.async.wait_group %0;" :: "n"(N) : "memory");
}
__device__ __forceinline__ void ldsm_x4(uint32_t (&r)[4], uint32_t addr) {
    asm volatile("ldmatrix.sync.aligned.m8n8.x4.shared.b16 {%0,%1,%2,%3}, [%4];"
                 : "=r"(r[0]), "=r"(r[1]), "=r"(r[2]), "=r"(r[3]) : "r"(addr));
}
__device__ __forceinline__ void mma16816_bf(float (&d)[4], const uint32_t (&a)[4],
                                            uint32_t b0, uint32_t b1) {
    asm volatile(
        "mma.sync.aligned.m16n8k16.row.col.f32.bf16.bf16.f32 "
        "{%0,%1,%2,%3}, {%4,%5,%6,%7}, {%8,%9}, {%0,%1,%2,%3};"
        : "+f"(d[0]), "+f"(d[1]), "+f"(d[2]), "+f"(d[3])
        : "r"(a[0]), "r"(a[1]), "r"(a[2]), "r"(a[3]), "r"(b0), "r"(b1));
}
__device__ __forceinline__ void mma16816_f16(float (&d)[4], const uint32_t (&a)[4],
                                             uint32_t b0, uint32_t b1) {
    asm volatile(
        "mma.sync.aligned.m16n8k16.row.col.f32.f16.f16.f32 "
        "{%0,%1,%2,%3}, {%4,%5,%6,%7}, {%8,%9}, {%0,%1,%2,%3};"
        : "+f"(d[0]), "+f"(d[1]), "+f"(d[2]), "+f"(d[3])
        : "r"(a[0]), "r"(a[1]), "r"(a[2]), "r"(a[3]), "r"(b0), "r"(b1));
}

// ---------------------------------------------------------------------------
// prep_xd: fused transpose + precision split for x AND depth.
// grid (HW/32, 10, NB): y<8 -> x channels, y>=8 -> depth channels.
// ---------------------------------------------------------------------------
__global__ void prep_xd(const float* __restrict__ x, const float* __restrict__ depth,
                        __half* __restrict__ xTh, float* __restrict__ dT,
                        __nv_bfloat16* __restrict__ xd) {
    __shared__ float t[32][33];
    int n = blockIdx.z;
    int cy = blockIdx.y;
    int p0 = blockIdx.x * 32;
    int tx = threadIdx.x, ty = threadIdx.y;
    if (cy < 8) {
        int c0 = cy * 32;
#pragma unroll
        for (int j = 0; j < 32; j += 8)
            t[ty + j][tx] = x[((size_t)n * CIN + c0 + ty + j) * HW + p0 + tx];
        __syncthreads();
#pragma unroll
        for (int j = 0; j < 32; j += 8) {
            float v = t[tx][ty + j];
            size_t prow = (size_t)n * HW + p0 + ty + j;
            int c = c0 + tx;
            xTh[prow * CIN + c] = __float2half(v);
            __nv_bfloat16 hb = __float2bfloat16(v);
            xd[prow * 640 + c] = hb;
            xd[prow * 640 + 320 + c] = __float2bfloat16(v - __bfloat162float(hb));
        }
    } else {
        int c0 = (cy - 8) * 32;
#pragma unroll
        for (int j = 0; j < 32; j += 8)
            t[ty + j][tx] = depth[((size_t)n * DC + c0 + ty + j) * HW + p0 + tx];
        __syncthreads();
#pragma unroll
        for (int j = 0; j < 32; j += 8) {
            float v = t[tx][ty + j];
            size_t prow = (size_t)n * HW + p0 + ty + j;
            int c = c0 + tx;
            dT[prow * DC + c] = v;
            __nv_bfloat16 hb = __float2bfloat16(v);
            xd[prow * 640 + 256 + c] = hb;
            xd[prow * 640 + 576 + c] = __float2bfloat16(v - __bfloat162float(hb));
        }
    }
}

// ---------------------------------------------------------------------------
// prep_weights: bid<256 -> wh; bid>=256 -> ws1 rows. 320 threads.
// ---------------------------------------------------------------------------
__global__ void prep_weights(const float* __restrict__ w, const float* __restrict__ ow,
                             __half* __restrict__ wh, __nv_bfloat16* __restrict__ ws) {
    int bid = blockIdx.x;
    int c = threadIdx.x;
    if (bid < 256) {
        if (c < 256) {
#pragma unroll
            for (int k = 0; k < 9; k++) {
                float v = w[((size_t)bid * 256 + c) * 9 + k];
                wh[(size_t)bid * KP3 + k * 256 + c] = __float2half(v);
            }
        }
    } else {
        int m = bid - 256;
#pragma unroll
        for (int kk = 0; kk < 9; kk++) {
            float v = (m < 18) ? ow[((size_t)m * 320 + c) * 9 + kk] : 0.f;
            __nv_bfloat16 hb = __float2bfloat16(v);
            __nv_bfloat16 lb = __float2bfloat16(v - __bfloat162float(hb));
            size_t b = (size_t)m * S1K + kk * 320 + c;
            ws[b] = hb;
            ws[b + 2880] = hb;
            ws[b + 5760] = lb;
        }
    }
}

// ---------------------------------------------------------------------------
// Stage-1 HMMA GEMM (implicit im2col, bf16 3-pass with A-hi reuse).
// Stage = {A-hi + B(Whi) + B(Wlo)} + {A-lo + B(Whi)}; 45 stages, 2-deep.
// ---------------------------------------------------------------------------
#define S1_AB 16384
#define S1_BB 4096
#define S1_STGB (S1_AB + 2 * S1_BB + S1_AB + S1_BB)   /* 48 KB */

__global__ void __launch_bounds__(256, 1)
s1_hmma(const __nv_bfloat16* __restrict__ xd, const __nv_bfloat16* __restrict__ ws,
        const float* __restrict__ offb, float* __restrict__ offsets) {
    extern __shared__ char smem[];
    const uint32_t sb = smem_u32(smem);
    const int tid = threadIdx.x;
    const int wid = tid >> 5, lane = tid & 31;
    const int p0 = blockIdx.x * 128;
    const int n = blockIdx.z;
    const __nv_bfloat16* xdn = xd + (size_t)n * HW * 640;

    float acc[4][4];
#pragma unroll
    for (int i = 0; i < 4; i++)
#pragma unroll
        for (int r = 0; r < 4; r++) acc[i][r] = 0.f;

    // stage layout: Ahi@0, B0@16384, B1@20480, Alo@24576, B2@40960
    auto load_stage = [&](int st, int s) {
        int tap = st / 5;
        int c0 = (st - tap * 5) * 64;
        int dr = tap / 3 - 1, dc = tap % 3 - 1;
        uint32_t base = sb + s * S1_STGB;
#pragma unroll
        for (int half = 0; half < 2; half++) {
            int ah = half ? 320 : 0;
            uint32_t dA = base + half * 24576;
#pragma unroll
            for (int u = 0; u < 4; u++) {
                int idx = tid + u * 256;
                int row = idx >> 3, q = idx & 7;
                int gp = p0 + row;
                int h = gp >> 6, w = gp & 63;
                int iy = h + dr, ix = w + dc;
                bool v = (iy >= 0) & (iy < HH) & (ix >= 0) & (ix < WW);
                int pn = v ? iy * WW + ix : 0;
                cp_async16_z(dA + row * 128 + ((q ^ (row & 7)) << 4),
                             xdn + (size_t)pn * 640 + ah + c0 + q * 8, v);
            }
        }
        {
            int row = tid >> 3, q = tid & 7;
            uint32_t soff = row * 128 + ((q ^ (row & 7)) << 4);
            cp_async16(base + 16384 + soff,
                       ws + (size_t)row * S1K + st * 64 + q * 8);
            cp_async16(base + 20480 + soff,
                       ws + (size_t)row * S1K + (90 + st) * 64 + q * 8);
            cp_async16(base + 40960 + soff,
                       ws + (size_t)row * S1K + (45 + st) * 64 + q * 8);
        }
        cp_commit();
    };

    auto compute_stage = [&](int s) {
        const int rbase = ((lane >> 3) & 1) * 8 + (lane & 7);
        const int chi = (lane >> 4);
        uint32_t base = sb + s * S1_STGB;
#pragma unroll
        for (int ks = 0; ks < 4; ks++) {
            uint32_t csh = (uint32_t)(ks * 2 + chi);
            uint32_t af[4], bf0[2][4], bf1[2][4];
            {
                int row = wid * 16 + rbase;
                ldsm_x4(af, base + row * 128 + ((csh ^ (row & 7)) << 4));
            }
#pragma unroll
            for (int j = 0; j < 2; j++) {
                int row = j * 16 + rbase;
                uint32_t soff = row * 128 + ((csh ^ (row & 7)) << 4);
                ldsm_x4(bf0[j], base + 16384 + soff);
                ldsm_x4(bf1[j], base + 20480 + soff);
            }
#pragma unroll
            for (int j = 0; j < 2; j++)
#pragma unroll
                for (int s2 = 0; s2 < 2; s2++) {
                    mma16816_bf(acc[j * 2 + s2], af, bf0[j][s2], bf0[j][s2 + 2]);
                    mma16816_bf(acc[j * 2 + s2], af, bf1[j][s2], bf1[j][s2 + 2]);
                }
            uint32_t al[4], bf2[2][4];
            {
                int row = wid * 16 + rbase;
                ldsm_x4(al, base + 24576 + row * 128 + ((csh ^ (row & 7)) << 4));
            }
#pragma unroll
            for (int j = 0; j < 2; j++) {
                int row = j * 16 + rbase;
                ldsm_x4(bf2[j], base + 40960 + row * 128 + ((csh ^ (row & 7)) << 4));
            }
#pragma unroll
            for (int j = 0; j < 2; j++)
#pragma unroll
                for (int s2 = 0; s2 < 2; s2++)
                    mma16816_bf(acc[j * 2 + s2], al, bf2[j][s2], bf2[j][s2 + 2]);
        }
    };

    load_stage(0, 0);
    for (int st = 0; st < S1STAGES; st++) {
        cp_wait<0>();
        __syncthreads();
        if (st + 1 < S1STAGES) load_stage(st + 1, (st + 1) & 1);
        compute_stage(st & 1);
    }

#pragma unroll
    for (int j = 0; j < 2; j++)
#pragma unroll
        for (int s = 0; s < 2; s++) {
            int m = j * 16 + s * 8 + (lane & 3) * 2;
            if (m < 18) {
                float b0 = offb[m], b1 = offb[m + 1];
                int row = wid * 16 + (lane >> 2);
                float* o = offsets + ((size_t)n * 18 + m) * HW + p0;
                const float* a = acc[j * 2 + s];
                o[row]          = a[0] + b0;
                o[HW + row]     = a[1] + b1;
                o[row + 8]      = a[2] + b0;
                o[HW + row + 8] = a[3] + b1;
            }
        }
}

// ---------------------------------------------------------------------------
// Stages 2+3 FUSED: mask conv + modulated im2col per pixel (warp = pixel).
// ---------------------------------------------------------------------------
__global__ void __launch_bounds__(256)
fused_mask_im2col(const float* __restrict__ depthT, const __half* __restrict__ xTh,
                  const float* __restrict__ offs, const float* __restrict__ mw,
                  const float* __restrict__ mb, __half* __restrict__ colsT) {
    __shared__ float ws[9][9][64];
    __shared__ float sbias[9];
    const int tid = threadIdx.x;
    const int n = blockIdx.y;

    for (int i = tid; i < 5184; i += 256) {
        int m = i / 576;
        int rem = i - m * 576;
        int c = rem / 9;
        int k = rem - 9 * c;
        ws[k][m][c] = mw[i];
    }
    if (tid < 9) sbias[tid] = mb[tid];
    __syncthreads();

    const int wid = tid >> 5, lane = tid & 31;
    const int p = blockIdx.x * 8 + wid;
    const int h = p >> 6, w = p & 63;
    const float* dn = depthT + (size_t)n * HW * DC;
    const float* offn = offs + (size_t)n * 18 * HW;

    float dyr[9], dxr[9];
    float acc[9];
#pragma unroll
    for (int m = 0; m < 9; m++) acc[m] = 0.f;

#pragma unroll
    for (int k = 0; k < 9; k++) {
        float dy = offn[(size_t)(2 * k) * HW + p];
        float dx = offn[(size_t)(2 * k + 1) * HW + p];
        dyr[k] = dy; dxr[k] = dx;
        float y = (float)(h - 1 + k / 3) + dy;
        float xx = (float)(w - 1 + k % 3) + dx;
        float y0f = floorf(y), x0f = floorf(xx);
        float ly = y - y0f, lx = xx - x0f;
        int y0 = (int)y0f, x0 = (int)x0f;
        int y1 = y0 + 1, x1 = x0 + 1;
        bool vy0 = (y0 >= 0) & (y0 < HH);
        bool vy1 = (y1 >= 0) & (y1 < HH);
        bool vx0 = (x0 >= 0) & (x0 < WW);
        bool vx1 = (x1 >= 0) & (x1 < WW);
        float w00 = (vy0 & vx0) ? (1.f - ly) * (1.f - lx) : 0.f;
        float w01 = (vy0 & vx1) ? (1.f - ly) * lx : 0.f;
        float w10 = (vy1 & vx0) ? ly * (1.f - lx) : 0.f;
        float w11 = (vy1 & vx1) ? ly * lx : 0.f;
        int i00 = (vy0 & vx0) ? y0 * WW + x0 : 0;
        int i01 = (vy0 & vx1) ? y0 * WW + x1 : 0;
        int i10 = (vy1 & vx0) ? y1 * WW + x0 : 0;
        int i11 = (vy1 & vx1) ? y1 * WW + x1 : 0;
        int cc = lane * 2;
        float2 a = *reinterpret_cast<const float2*>(dn + (size_t)i00 * DC + cc);
        float2 b = *reinterpret_cast<const float2*>(dn + (size_t)i01 * DC + cc);
        float2 cv = *reinterpret_cast<const float2*>(dn + (size_t)i10 * DC + cc);
        float2 d = *reinterpret_cast<const float2*>(dn + (size_t)i11 * DC + cc);
        float v0 = w00 * a.x + w01 * b.x + w10 * cv.x + w11 * d.x;
        float v1 = w00 * a.y + w01 * b.y + w10 * cv.y + w11 * d.y;
#pragma unroll
        for (int m = 0; m < 9; m++) {
            float2 wv = *reinterpret_cast<const float2*>(&ws[k][m][cc]);
            acc[m] += wv.x * v0 + wv.y * v1;
        }
    }

#pragma unroll
    for (int m = 0; m < 9; m++) {
#pragma unroll
        for (int off = 16; off > 0; off >>= 1)
            acc[m] += __shfl_xor_sync(0xFFFFFFFFu, acc[m], off);
        acc[m] = 1.f / (1.f + expf(-(acc[m] + sbias[m])));
    }

    const __half* src = xTh + (size_t)n * HW * CIN;
    __half* outp = colsT + ((size_t)n * HW + p) * KP3;
    const int cc8 = lane * 8;

#pragma unroll
    for (int k = 0; k < 9; k++) {
        float mk = acc[k];
        float y = (float)(h - 1 + k / 3) + dyr[k];
        float xx = (float)(w - 1 + k % 3) + dxr[k];
        float y0f = floorf(y), x0f = floorf(xx);
        float ly = y - y0f, lx = xx - x0f;
        int y0 = (int)y0f, x0 = (int)x0f;
        int y1 = y0 + 1, x1 = x0 + 1;
        bool vy0 = (y0 >= 0) & (y0 < HH);
        bool vy1 = (y1 >= 0) & (y1 < HH);
        bool vx0 = (x0 >= 0) & (x0 < WW);
        bool vx1 = (x1 >= 0) & (x1 < WW);
        float w00 = (vy0 & vx0) ? (1.f - ly) * (1.f - lx) * mk : 0.f;
        float w01 = (vy0 & vx1) ? (1.f - ly) * lx * mk : 0.f;
        float w10 = (vy1 & vx0) ? ly * (1.f - lx) * mk : 0.f;
        float w11 = (vy1 & vx1) ? ly * lx * mk : 0.f;
        int i00 = (vy0 & vx0) ? y0 * WW + x0 : 0;
        int i01 = (vy0 & vx1) ? y0 * WW + x1 : 0;
        int i10 = (vy1 & vx0) ? y1 * WW + x0 : 0;
        int i11 = (vy1 & vx1) ? y1 * WW + x1 : 0;

        uint4 A = *reinterpret_cast<const uint4*>(src + (size_t)i00 * CIN + cc8);
        uint4 B = *reinterpret_cast<const uint4*>(src + (size_t)i01 * CIN + cc8);
        uint4 C = *reinterpret_cast<const uint4*>(src + (size_t)i10 * CIN + cc8);
        uint4 D = *reinterpret_cast<const uint4*>(src + (size_t)i11 * CIN + cc8);
        const __half2* a2 = reinterpret_cast<const __half2*>(&A);
        const __half2* b2 = reinterpret_cast<const __half2*>(&B);
        const __half2* c2 = reinterpret_cast<const __half2*>(&C);
        const __half2* d2 = reinterpret_cast<const __half2*>(&D);

        __align__(16) __half hv[8];
#pragma unroll
        for (int j = 0; j < 4; j++) {
            float2 av = __half22float2(a2[j]);
            float2 bv = __half22float2(b2[j]);
            float2 cv = __half22float2(c2[j]);
            float2 dv = __half22float2(d2[j]);
            hv[2 * j]     = __float2half(w00 * av.x + w01 * bv.x + w10 * cv.x + w11 * dv.x);
            hv[2 * j + 1] = __float2half(w00 * av.y + w01 * bv.y + w10 * cv.y + w11 * dv.y);
        }
        *reinterpret_cast<uint4*>(outp + k * 256 + cc8) = *reinterpret_cast<uint4*>(hv);
    }
}

// ---------------------------------------------------------------------------
// Stage-3 HMMA GEMM: M=256 x N=128 per CTA, BK=128, 2-stage,
// smem-transposed coalesced epilogue (row stride EPW=264 floats, 16B-aligned).
// ---------------------------------------------------------------------------
#define A3BYTES 32768
#define B3BYTES 16384
#define STG3 (A3BYTES + B3BYTES)
#define STG3x2 (2 * STG3)

__global__ void __launch_bounds__(256, 1)
hmma_gemm(const __half* __restrict__ colsT, const __half* __restrict__ wh,
          const float* __restrict__ bias, float* __restrict__ out) {
    extern __shared__ char smem[];
    const uint32_t sb = smem_u32(smem);
    const int tid = threadIdx.x;
    const int wid = tid >> 5, lane = tid & 31;
    const int wm = wid >> 1, wn = wid & 1;
    const int p0 = blockIdx.x * 256;
    const int cout0 = blockIdx.y * 128;
    const int n = blockIdx.z;

    const char* Ag = (const char*)(colsT + (size_t)(n * HW + p0) * KP3);
    const char* Bg = (const char*)(wh + (size_t)cout0 * KP3);

    float acc[4][8][4];
#pragma unroll
    for (int i = 0; i < 4; i++)
#pragma unroll
        for (int j = 0; j < 8; j++)
#pragma unroll
            for (int r = 0; r < 4; r++) acc[i][j][r] = 0.f;

    auto load_stage = [&](int t, int s) {
#pragma unroll
        for (int half = 0; half < 2; half++) {
            int kt = 2 * t + half;
            uint32_t dA = sb + s * STG3x2 + half * STG3;
            uint32_t dB = dA + A3BYTES;
#pragma unroll
            for (int u = 0; u < 8; u++) {
                int idx = tid + u * 256;
                int row = idx >> 3, c = idx & 7;
                cp_async16(dA + row * 128 + ((c ^ (row & 7)) << 4),
                           Ag + (size_t)row * KROW3 + kt * 128 + c * 16);
            }
#pragma unroll
            for (int u = 0; u < 4; u++) {
                int idx = tid + u * 256;
                int row = idx >> 3, c = idx & 7;
                cp_async16(dB + row * 128 + ((c ^ (row & 7)) << 4),
                           Bg + (size_t)row * KROW3 + kt * 128 + c * 16);
            }
        }
        cp_commit();
    };

    auto compute_stage = [&](int s) {
        const int rbase = ((lane >> 3) & 1) * 8 + (lane & 7);
        const int chi = (lane >> 4);
#pragma unroll
        for (int half = 0; half < 2; half++) {
            uint32_t Ab = sb + s * STG3x2 + half * STG3;
            uint32_t Bb = Ab + A3BYTES;
#pragma unroll
            for (int ks = 0; ks < 4; ks++) {
                int c = ks * 2 + chi;
                uint32_t af[4][4], bf[4][4];
#pragma unroll
                for (int i = 0; i < 4; i++) {
                    int row = wm * 64 + i * 16 + rbase;
                    ldsm_x4(af[i], Ab + row * 128 + ((c ^ (row & 7)) << 4));
                }
#pragma unroll
                for (int j = 0; j < 4; j++) {
                    int row = wn * 64 + j * 16 + rbase;
                    ldsm_x4(bf[j], Bb + row * 128 + ((c ^ (row & 7)) << 4));
                }
#pragma unroll
                for (int i = 0; i < 4; i++)
#pragma unroll
                    for (int j = 0; j < 4; j++)
#pragma unroll
                        for (int s2 = 0; s2 < 2; s2++)
                            mma16816_f16(acc[i][j * 2 + s2], af[i], bf[j][s2], bf[j][s2 + 2]);
            }
        }
    };

    load_stage(0, 0);
    for (int t = 0; t < K3PAIRS; t++) {
        cp_wait<0>();
        __syncthreads();
        if (t + 1 < K3PAIRS) load_stage(t + 1, (t + 1) & 1);
        compute_stage(t & 1);
    }
    __syncthreads();   // smem reuse for epilogue

    // Coalesced epilogue via smem transpose: 4 slices of 32 couts.
    // Row stride EPW=264 floats = 1056 B (16B-multiple -> aligned float4).
    float* se = (float*)smem;          // [32][EPW]
#pragma unroll
    for (int j = 0; j < 4; j++) {
        int lc = wn * 16 + (lane & 3) * 2;
#pragma unroll
        for (int i = 0; i < 4; i++)
#pragma unroll
            for (int s = 0; s < 2; s++) {
                int lcs = lc + s * 8;
                int m = wm * 64 + i * 16 + (lane >> 2);
                const float* a = acc[i][j * 2 + s];
                se[lcs * EPW + m]           = a[0];
                se[(lcs + 1) * EPW + m]     = a[1];
                se[lcs * EPW + m + 8]       = a[2];
                se[(lcs + 1) * EPW + m + 8] = a[3];
            }
        __syncthreads();
#pragma unroll
        for (int r = 0; r < 4; r++) {
            int lcr = wid * 4 + r;
            int cout = cout0 + ((lcr < 16) ? (j * 16 + lcr) : (64 + j * 16 + lcr - 16));
            float bv = bias[cout];
            const float* row = se + lcr * EPW + lane * 8;
            float4 v0 = *reinterpret_cast<const float4*>(row);
            float4 v1 = *reinterpret_cast<const float4*>(row + 4);
            v0.x += bv; v0.y += bv; v0.z += bv; v0.w += bv;
            v1.x += bv; v1.y += bv; v1.z += bv; v1.w += bv;
            float* o = out + ((size_t)n * COUT + cout) * HW + p0 + lane * 8;
            *reinterpret_cast<float4*>(o) = v0;
            *reinterpret_cast<float4*>(o + 4) = v1;
        }
        __syncthreads();
    }
}

// ---------------------------------------------------------------------------
extern "C" void kernel_launch(void* const* d_in, const int* in_sizes, int n_in,
                              void* d_out, int out_size) {
    const float* x      = (const float*)d_in[0];
    const float* depth  = (const float*)d_in[1];
    const float* weight = (const float*)d_in[2];
    const float* bias   = (const float*)d_in[3];
    const float* off_w  = (const float*)d_in[4];
    const float* off_b  = (const float*)d_in[5];
    const float* mask_w = (const float*)d_in[6];
    const float* mask_b = (const float*)d_in[7];
    float* out = (float*)d_out;

    void *po, *pch, *pwh, *pxh, *pdt, *pxd, *pw1;
    cudaGetSymbolAddress(&po, g_offsets);
    cudaGetSymbolAddress(&pch, g_colsh);
    cudaGetSymbolAddress(&pwh, g_wh);
    cudaGetSymbolAddress(&pxh, g_xTh);
    cudaGetSymbolAddress(&pdt, g_dT);
    cudaGetSymbolAddress(&pxd, g_xdbf);
    cudaGetSymbolAddress(&pw1, g_ws1);
    float* offsets = (float*)po;
    __half* colsh = (__half*)pch;
    __half* wh = (__half*)pwh;
    __half* xTh = (__half*)pxh;
    float* dT = (float*)pdt;
    __nv_bfloat16* xdbf = (__nv_bfloat16*)pxd;
    __nv_bfloat16* ws1 = (__nv_bfloat16*)pw1;

    // Prep (consolidated)
    prep_weights<<<288, 320>>>(weight, off_w, wh, ws1);
    prep_xd<<<dim3(HW / 32, 10, NB), dim3(32, 8)>>>(x, depth, xTh, dT, xdbf);

    static int smem_set = 0;
    if (!smem_set) {
        cudaFuncSetAttribute(s1_hmma, cudaFuncAttributeMaxDynamicSharedMemorySize,
                             2 * S1_STGB);
        cudaFuncSetAttribute(hmma_gemm, cudaFuncAttributeMaxDynamicSharedMemorySize,
                             2 * STG3x2);
        smem_set = 1;
    }

    // Stage 1: offset conv (bf16 3-pass, A-hi reused across passes)
    s1_hmma<<<dim3(HW / 128, 1, NB), 256, 2 * S1_STGB>>>(xdbf, ws1, off_b, offsets);

    // Stages 2+3 fused: mask conv + modulated im2col
    fused_mask_im2col<<<dim3(HW / 8, NB), 256>>>(dT, xTh, offsets, mask_w, mask_b,
                                                 colsh);

    // Stage-3 GEMM
    hmma_gemm<<<dim3(HW / 256, 2, NB), 256, 2 * STG3x2>>>(colsh, wh, bias, out);
}

// round 17
// speedup vs baseline: 6.6085x; 1.0441x over previous
#include <cuda_runtime.h>
#include <cuda_bf16.h>
#include <cuda_fp16.h>
#include <cstdint>
#include <math.h>

#define NB 4
#define HH 64
#define WW 64
#define HW 4096
#define CIN 256
#define DC 64
#define COUT 256
#define KP3 2304               /* stage-3 K: single-pass fp16 */
#define KROW3 (KP3 * 2)
#define K3PAIRS 18
#define S1K 8640               /* stage-1 W cols: 3 * 2880 (bf16 split) */
#define S1STAGES 45

#define EPW 264                /* epilogue smem row stride (floats, 16B-mult) */

// ---------------- device scratch ----------------
__device__ float g_offsets[(size_t)NB * 18 * HW];
__device__ float g_mask[(size_t)NB * 9 * HW];
__device__ __half g_xTh[(size_t)NB * HW * CIN];            // x NHWC fp16
__device__ float g_dT[(size_t)NB * HW * DC];               // depth NHWC f32
__device__ __nv_bfloat16 g_xdbf[(size_t)NB * HW * 640];    // cat(x,d) [hi320|lo320]
__device__ __nv_bfloat16 g_ws1[(size_t)32 * S1K];          // off_w split, 32 rows
__device__ __half g_colsh[(size_t)NB * HW * KP3];          // 75 MB fp16 cols
__device__ __half g_wh[(size_t)COUT * KP3];                // fp16 weights

// ---------------- PTX helpers ----------------
__device__ __forceinline__ uint32_t smem_u32(const void* p) {
    uint32_t a;
    asm("{ .reg .u64 t; cvta.to.shared.u64 t, %1; cvt.u32.u64 %0, t; }"
        : "=r"(a) : "l"(p));
    return a;
}
__device__ __forceinline__ void cp_async16(uint32_t dst, const void* src) {
    asm volatile("cp.async.cg.shared.global [%0], [%1], 16;"
                 :: "r"(dst), "l"(src) : "memory");
}
__device__ __forceinline__ void cp_async16_z(uint32_t dst, const void* src, bool pred) {
    int sz = pred ? 16 : 0;
    asm volatile("cp.async.cg.shared.global [%0], [%1], 16, %2;"
                 :: "r"(dst), "l"(src), "r"(sz) : "memory");
}
__device__ __forceinline__ void cp_commit() {
    asm volatile("cp.async.commit_group;" ::: "memory");
}
template <int N>
__device__ __forceinline__ void cp_wait() {
    asm volatile("cp.async.wait_group %0;" :: "n"(N) : "memory");
}
__device__ __forceinline__ void ldsm_x4(uint32_t (&r)[4], uint32_t addr) {
    asm volatile("ldmatrix.sync.aligned.m8n8.x4.shared.b16 {%0,%1,%2,%3}, [%4];"
                 : "=r"(r[0]), "=r"(r[1]), "=r"(r[2]), "=r"(r[3]) : "r"(addr));
}
__device__ __forceinline__ void mma16816_bf(float (&d)[4], const uint32_t (&a)[4],
                                            uint32_t b0, uint32_t b1) {
    asm volatile(
        "mma.sync.aligned.m16n8k16.row.col.f32.bf16.bf16.f32 "
        "{%0,%1,%2,%3}, {%4,%5,%6,%7}, {%8,%9}, {%0,%1,%2,%3};"
        : "+f"(d[0]), "+f"(d[1]), "+f"(d[2]), "+f"(d[3])
        : "r"(a[0]), "r"(a[1]), "r"(a[2]), "r"(a[3]), "r"(b0), "r"(b1));
}
__device__ __forceinline__ void mma16816_f16(float (&d)[4], const uint32_t (&a)[4],
                                             uint32_t b0, uint32_t b1) {
    asm volatile(
        "mma.sync.aligned.m16n8k16.row.col.f32.f16.f16.f32 "
        "{%0,%1,%2,%3}, {%4,%5,%6,%7}, {%8,%9}, {%0,%1,%2,%3};"
        : "+f"(d[0]), "+f"(d[1]), "+f"(d[2]), "+f"(d[3])
        : "r"(a[0]), "r"(a[1]), "r"(a[2]), "r"(a[3]), "r"(b0), "r"(b1));
}

// ---------------------------------------------------------------------------
// prep_xd: fused transpose + precision split for x AND depth.
// ---------------------------------------------------------------------------
__global__ void prep_xd(const float* __restrict__ x, const float* __restrict__ depth,
                        __half* __restrict__ xTh, float* __restrict__ dT,
                        __nv_bfloat16* __restrict__ xd) {
    __shared__ float t[32][33];
    int n = blockIdx.z;
    int cy = blockIdx.y;
    int p0 = blockIdx.x * 32;
    int tx = threadIdx.x, ty = threadIdx.y;
    if (cy < 8) {
        int c0 = cy * 32;
#pragma unroll
        for (int j = 0; j < 32; j += 8)
            t[ty + j][tx] = x[((size_t)n * CIN + c0 + ty + j) * HW + p0 + tx];
        __syncthreads();
#pragma unroll
        for (int j = 0; j < 32; j += 8) {
            float v = t[tx][ty + j];
            size_t prow = (size_t)n * HW + p0 + ty + j;
            int c = c0 + tx;
            xTh[prow * CIN + c] = __float2half(v);
            __nv_bfloat16 hb = __float2bfloat16(v);
            xd[prow * 640 + c] = hb;
            xd[prow * 640 + 320 + c] = __float2bfloat16(v - __bfloat162float(hb));
        }
    } else {
        int c0 = (cy - 8) * 32;
#pragma unroll
        for (int j = 0; j < 32; j += 8)
            t[ty + j][tx] = depth[((size_t)n * DC + c0 + ty + j) * HW + p0 + tx];
        __syncthreads();
#pragma unroll
        for (int j = 0; j < 32; j += 8) {
            float v = t[tx][ty + j];
            size_t prow = (size_t)n * HW + p0 + ty + j;
            int c = c0 + tx;
            dT[prow * DC + c] = v;
            __nv_bfloat16 hb = __float2bfloat16(v);
            xd[prow * 640 + 256 + c] = hb;
            xd[prow * 640 + 576 + c] = __float2bfloat16(v - __bfloat162float(hb));
        }
    }
}

// ---------------------------------------------------------------------------
// prep_weights: bid<256 -> wh; bid>=256 -> ws1 rows. 320 threads.
// ---------------------------------------------------------------------------
__global__ void prep_weights(const float* __restrict__ w, const float* __restrict__ ow,
                             __half* __restrict__ wh, __nv_bfloat16* __restrict__ ws) {
    int bid = blockIdx.x;
    int c = threadIdx.x;
    if (bid < 256) {
        if (c < 256) {
#pragma unroll
            for (int k = 0; k < 9; k++) {
                float v = w[((size_t)bid * 256 + c) * 9 + k];
                wh[(size_t)bid * KP3 + k * 256 + c] = __float2half(v);
            }
        }
    } else {
        int m = bid - 256;
#pragma unroll
        for (int kk = 0; kk < 9; kk++) {
            float v = (m < 18) ? ow[((size_t)m * 320 + c) * 9 + kk] : 0.f;
            __nv_bfloat16 hb = __float2bfloat16(v);
            __nv_bfloat16 lb = __float2bfloat16(v - __bfloat162float(hb));
            size_t b = (size_t)m * S1K + kk * 320 + c;
            ws[b] = hb;
            ws[b + 2880] = hb;
            ws[b + 5760] = lb;
        }
    }
}

// ---------------------------------------------------------------------------
// Stage-1 HMMA GEMM (implicit im2col, bf16 3-pass with A-hi reuse).
// ---------------------------------------------------------------------------
#define S1_AB 16384
#define S1_BB 4096
#define S1_STGB (S1_AB + 2 * S1_BB + S1_AB + S1_BB)   /* 48 KB */

__global__ void __launch_bounds__(256, 1)
s1_hmma(const __nv_bfloat16* __restrict__ xd, const __nv_bfloat16* __restrict__ ws,
        const float* __restrict__ offb, float* __restrict__ offsets) {
    extern __shared__ char smem[];
    const uint32_t sb = smem_u32(smem);
    const int tid = threadIdx.x;
    const int wid = tid >> 5, lane = tid & 31;
    const int p0 = blockIdx.x * 128;
    const int n = blockIdx.z;
    const __nv_bfloat16* xdn = xd + (size_t)n * HW * 640;

    float acc[4][4];
#pragma unroll
    for (int i = 0; i < 4; i++)
#pragma unroll
        for (int r = 0; r < 4; r++) acc[i][r] = 0.f;

    // stage layout: Ahi@0, B0@16384, B1@20480, Alo@24576, B2@40960
    auto load_stage = [&](int st, int s) {
        int tap = st / 5;
        int c0 = (st - tap * 5) * 64;
        int dr = tap / 3 - 1, dc = tap % 3 - 1;
        uint32_t base = sb + s * S1_STGB;
#pragma unroll
        for (int half = 0; half < 2; half++) {
            int ah = half ? 320 : 0;
            uint32_t dA = base + half * 24576;
#pragma unroll
            for (int u = 0; u < 4; u++) {
                int idx = tid + u * 256;
                int row = idx >> 3, q = idx & 7;
                int gp = p0 + row;
                int h = gp >> 6, w = gp & 63;
                int iy = h + dr, ix = w + dc;
                bool v = (iy >= 0) & (iy < HH) & (ix >= 0) & (ix < WW);
                int pn = v ? iy * WW + ix : 0;
                cp_async16_z(dA + row * 128 + ((q ^ (row & 7)) << 4),
                             xdn + (size_t)pn * 640 + ah + c0 + q * 8, v);
            }
        }
        {
            int row = tid >> 3, q = tid & 7;
            uint32_t soff = row * 128 + ((q ^ (row & 7)) << 4);
            cp_async16(base + 16384 + soff,
                       ws + (size_t)row * S1K + st * 64 + q * 8);
            cp_async16(base + 20480 + soff,
                       ws + (size_t)row * S1K + (90 + st) * 64 + q * 8);
            cp_async16(base + 40960 + soff,
                       ws + (size_t)row * S1K + (45 + st) * 64 + q * 8);
        }
        cp_commit();
    };

    auto compute_stage = [&](int s) {
        const int rbase = ((lane >> 3) & 1) * 8 + (lane & 7);
        const int chi = (lane >> 4);
        uint32_t base = sb + s * S1_STGB;
#pragma unroll
        for (int ks = 0; ks < 4; ks++) {
            uint32_t csh = (uint32_t)(ks * 2 + chi);
            uint32_t af[4], bf0[2][4], bf1[2][4];
            {
                int row = wid * 16 + rbase;
                ldsm_x4(af, base + row * 128 + ((csh ^ (row & 7)) << 4));
            }
#pragma unroll
            for (int j = 0; j < 2; j++) {
                int row = j * 16 + rbase;
                uint32_t soff = row * 128 + ((csh ^ (row & 7)) << 4);
                ldsm_x4(bf0[j], base + 16384 + soff);
                ldsm_x4(bf1[j], base + 20480 + soff);
            }
#pragma unroll
            for (int j = 0; j < 2; j++)
#pragma unroll
                for (int s2 = 0; s2 < 2; s2++) {
                    mma16816_bf(acc[j * 2 + s2], af, bf0[j][s2], bf0[j][s2 + 2]);
                    mma16816_bf(acc[j * 2 + s2], af, bf1[j][s2], bf1[j][s2 + 2]);
                }
            uint32_t al[4], bf2[2][4];
            {
                int row = wid * 16 + rbase;
                ldsm_x4(al, base + 24576 + row * 128 + ((csh ^ (row & 7)) << 4));
            }
#pragma unroll
            for (int j = 0; j < 2; j++) {
                int row = j * 16 + rbase;
                ldsm_x4(bf2[j], base + 40960 + row * 128 + ((csh ^ (row & 7)) << 4));
            }
#pragma unroll
            for (int j = 0; j < 2; j++)
#pragma unroll
                for (int s2 = 0; s2 < 2; s2++)
                    mma16816_bf(acc[j * 2 + s2], al, bf2[j][s2], bf2[j][s2 + 2]);
        }
    };

    load_stage(0, 0);
    for (int st = 0; st < S1STAGES; st++) {
        cp_wait<0>();
        __syncthreads();
        if (st + 1 < S1STAGES) load_stage(st + 1, (st + 1) & 1);
        compute_stage(st & 1);
    }

#pragma unroll
    for (int j = 0; j < 2; j++)
#pragma unroll
        for (int s = 0; s < 2; s++) {
            int m = j * 16 + s * 8 + (lane & 3) * 2;
            if (m < 18) {
                float b0 = offb[m], b1 = offb[m + 1];
                int row = wid * 16 + (lane >> 2);
                float* o = offsets + ((size_t)n * 18 + m) * HW + p0;
                const float* a = acc[j * 2 + s];
                o[row]          = a[0] + b0;
                o[HW + row]     = a[1] + b1;
                o[row + 8]      = a[2] + b0;
                o[HW + row + 8] = a[3] + b1;
            }
        }
}

// ---------------------------------------------------------------------------
// Stage-2: mask = sigmoid(deform_conv(depthT, offset) + mb). Warp = pixel.
// ---------------------------------------------------------------------------
__global__ void __launch_bounds__(256)
fused_mask(const float* __restrict__ depthT, const float* __restrict__ offs,
           const float* __restrict__ mw, const float* __restrict__ mb,
           float* __restrict__ maskbuf) {
    __shared__ float ws[9][9][64];
    __shared__ float sbias[9];
    const int tid = threadIdx.x;
    const int n = blockIdx.y;

    for (int i = tid; i < 5184; i += 256) {
        int m = i / 576;
        int rem = i - m * 576;
        int c = rem / 9;
        int k = rem - 9 * c;
        ws[k][m][c] = mw[i];
    }
    if (tid < 9) sbias[tid] = mb[tid];
    __syncthreads();

    const int wid = tid >> 5, lane = tid & 31;
    const int p = blockIdx.x * 8 + wid;
    const int h = p >> 6, w = p & 63;
    const float* dn = depthT + (size_t)n * HW * DC;
    const float* offn = offs + (size_t)n * 18 * HW;

    float acc[9];
#pragma unroll
    for (int m = 0; m < 9; m++) acc[m] = 0.f;

#pragma unroll
    for (int k = 0; k < 9; k++) {
        float dy = offn[(size_t)(2 * k) * HW + p];
        float dx = offn[(size_t)(2 * k + 1) * HW + p];
        float y = (float)(h - 1 + k / 3) + dy;
        float xx = (float)(w - 1 + k % 3) + dx;
        float y0f = floorf(y), x0f = floorf(xx);
        float ly = y - y0f, lx = xx - x0f;
        int y0 = (int)y0f, x0 = (int)x0f;
        int y1 = y0 + 1, x1 = x0 + 1;
        bool vy0 = (y0 >= 0) & (y0 < HH);
        bool vy1 = (y1 >= 0) & (y1 < HH);
        bool vx0 = (x0 >= 0) & (x0 < WW);
        bool vx1 = (x1 >= 0) & (x1 < WW);
        float w00 = (vy0 & vx0) ? (1.f - ly) * (1.f - lx) : 0.f;
        float w01 = (vy0 & vx1) ? (1.f - ly) * lx : 0.f;
        float w10 = (vy1 & vx0) ? ly * (1.f - lx) : 0.f;
        float w11 = (vy1 & vx1) ? ly * lx : 0.f;
        int i00 = (vy0 & vx0) ? y0 * WW + x0 : 0;
        int i01 = (vy0 & vx1) ? y0 * WW + x1 : 0;
        int i10 = (vy1 & vx0) ? y1 * WW + x0 : 0;
        int i11 = (vy1 & vx1) ? y1 * WW + x1 : 0;
        int cc = lane * 2;
        float2 a = *reinterpret_cast<const float2*>(dn + (size_t)i00 * DC + cc);
        float2 b = *reinterpret_cast<const float2*>(dn + (size_t)i01 * DC + cc);
        float2 cv = *reinterpret_cast<const float2*>(dn + (size_t)i10 * DC + cc);
        float2 d = *reinterpret_cast<const float2*>(dn + (size_t)i11 * DC + cc);
        float v0 = w00 * a.x + w01 * b.x + w10 * cv.x + w11 * d.x;
        float v1 = w00 * a.y + w01 * b.y + w10 * cv.y + w11 * d.y;
#pragma unroll
        for (int m = 0; m < 9; m++) {
            float2 wv = *reinterpret_cast<const float2*>(&ws[k][m][cc]);
            acc[m] += wv.x * v0 + wv.y * v1;
        }
    }

#pragma unroll
    for (int m = 0; m < 9; m++) {
#pragma unroll
        for (int off = 16; off > 0; off >>= 1)
            acc[m] += __shfl_xor_sync(0xFFFFFFFFu, acc[m], off);
    }
    if (lane == 0) {
        float* mp = maskbuf + (size_t)n * 9 * HW + p;
#pragma unroll
        for (int m = 0; m < 9; m++) {
            float v = acc[m] + sbias[m];
            mp[(size_t)m * HW] = 1.f / (1.f + expf(-v));
        }
    }
}

// ---------------------------------------------------------------------------
// Stage-3 deformable im2col: warp-per-pixel, fp16 gathers + fp16 output.
// ---------------------------------------------------------------------------
__global__ void __launch_bounds__(256)
deform_im2col_f16(const __half* __restrict__ xTh, const float* __restrict__ offs,
                  const float* __restrict__ mask, __half* __restrict__ colsT) {
    const int tid = threadIdx.x;
    const int wid = tid >> 5, lane = tid & 31;
    const int n = blockIdx.y;
    const int p = blockIdx.x * 8 + wid;
    const int h = p >> 6, w = p & 63;
    const float* offn = offs + (size_t)n * 18 * HW;
    const float* maskn = mask + (size_t)n * 9 * HW;
    const __half* src = xTh + (size_t)n * HW * CIN;
    __half* outp = colsT + ((size_t)n * HW + p) * KP3;
    const int cc = lane * 8;

#pragma unroll
    for (int k = 0; k < 9; k++) {
        float dy = offn[(size_t)(2 * k) * HW + p];
        float dx = offn[(size_t)(2 * k + 1) * HW + p];
        float mk = maskn[(size_t)k * HW + p];
        float y = (float)(h - 1 + k / 3) + dy;
        float xx = (float)(w - 1 + k % 3) + dx;
        float y0f = floorf(y), x0f = floorf(xx);
        float ly = y - y0f, lx = xx - x0f;
        int y0 = (int)y0f, x0 = (int)x0f;
        int y1 = y0 + 1, x1 = x0 + 1;
        bool vy0 = (y0 >= 0) & (y0 < HH);
        bool vy1 = (y1 >= 0) & (y1 < HH);
        bool vx0 = (x0 >= 0) & (x0 < WW);
        bool vx1 = (x1 >= 0) & (x1 < WW);
        float w00 = (vy0 & vx0) ? (1.f - ly) * (1.f - lx) * mk : 0.f;
        float w01 = (vy0 & vx1) ? (1.f - ly) * lx * mk : 0.f;
        float w10 = (vy1 & vx0) ? ly * (1.f - lx) * mk : 0.f;
        float w11 = (vy1 & vx1) ? ly * lx * mk : 0.f;
        int i00 = (vy0 & vx0) ? y0 * WW + x0 : 0;
        int i01 = (vy0 & vx1) ? y0 * WW + x1 : 0;
        int i10 = (vy1 & vx0) ? y1 * WW + x0 : 0;
        int i11 = (vy1 & vx1) ? y1 * WW + x1 : 0;

        uint4 A = *reinterpret_cast<const uint4*>(src + (size_t)i00 * CIN + cc);
        uint4 B = *reinterpret_cast<const uint4*>(src + (size_t)i01 * CIN + cc);
        uint4 C = *reinterpret_cast<const uint4*>(src + (size_t)i10 * CIN + cc);
        uint4 D = *reinterpret_cast<const uint4*>(src + (size_t)i11 * CIN + cc);
        const __half2* a2 = reinterpret_cast<const __half2*>(&A);
        const __half2* b2 = reinterpret_cast<const __half2*>(&B);
        const __half2* c2 = reinterpret_cast<const __half2*>(&C);
        const __half2* d2 = reinterpret_cast<const __half2*>(&D);

        __align__(16) __half hv[8];
#pragma unroll
        for (int j = 0; j < 4; j++) {
            float2 av = __half22float2(a2[j]);
            float2 bv = __half22float2(b2[j]);
            float2 cv = __half22float2(c2[j]);
            float2 dv = __half22float2(d2[j]);
            hv[2 * j]     = __float2half(w00 * av.x + w01 * bv.x + w10 * cv.x + w11 * dv.x);
            hv[2 * j + 1] = __float2half(w00 * av.y + w01 * bv.y + w10 * cv.y + w11 * dv.y);
        }
        *reinterpret_cast<uint4*>(outp + k * 256 + cc) = *reinterpret_cast<uint4*>(hv);
    }
}

// ---------------------------------------------------------------------------
// Stage-3 HMMA GEMM: M=256 x N=128 per CTA, BK=128, 2-stage,
// smem-transposed coalesced epilogue (row stride EPW floats).
// ---------------------------------------------------------------------------
#define A3BYTES 32768
#define B3BYTES 16384
#define STG3 (A3BYTES + B3BYTES)
#define STG3x2 (2 * STG3)

__global__ void __launch_bounds__(256, 1)
hmma_gemm(const __half* __restrict__ colsT, const __half* __restrict__ wh,
          const float* __restrict__ bias, float* __restrict__ out) {
    extern __shared__ char smem[];
    const uint32_t sb = smem_u32(smem);
    const int tid = threadIdx.x;
    const int wid = tid >> 5, lane = tid & 31;
    const int wm = wid >> 1, wn = wid & 1;
    const int p0 = blockIdx.x * 256;
    const int cout0 = blockIdx.y * 128;
    const int n = blockIdx.z;

    const char* Ag = (const char*)(colsT + (size_t)(n * HW + p0) * KP3);
    const char* Bg = (const char*)(wh + (size_t)cout0 * KP3);

    float acc[4][8][4];
#pragma unroll
    for (int i = 0; i < 4; i++)
#pragma unroll
        for (int j = 0; j < 8; j++)
#pragma unroll
            for (int r = 0; r < 4; r++) acc[i][j][r] = 0.f;

    auto load_stage = [&](int t, int s) {
#pragma unroll
        for (int half = 0; half < 2; half++) {
            int kt = 2 * t + half;
            uint32_t dA = sb + s * STG3x2 + half * STG3;
            uint32_t dB = dA + A3BYTES;
#pragma unroll
            for (int u = 0; u < 8; u++) {
                int idx = tid + u * 256;
                int row = idx >> 3, c = idx & 7;
                cp_async16(dA + row * 128 + ((c ^ (row & 7)) << 4),
                           Ag + (size_t)row * KROW3 + kt * 128 + c * 16);
            }
#pragma unroll
            for (int u = 0; u < 4; u++) {
                int idx = tid + u * 256;
                int row = idx >> 3, c = idx & 7;
                cp_async16(dB + row * 128 + ((c ^ (row & 7)) << 4),
                           Bg + (size_t)row * KROW3 + kt * 128 + c * 16);
            }
        }
        cp_commit();
    };

    auto compute_stage = [&](int s) {
        const int rbase = ((lane >> 3) & 1) * 8 + (lane & 7);
        const int chi = (lane >> 4);
#pragma unroll
        for (int half = 0; half < 2; half++) {
            uint32_t Ab = sb + s * STG3x2 + half * STG3;
            uint32_t Bb = Ab + A3BYTES;
#pragma unroll
            for (int ks = 0; ks < 4; ks++) {
                int c = ks * 2 + chi;
                uint32_t af[4][4], bf[4][4];
#pragma unroll
                for (int i = 0; i < 4; i++) {
                    int row = wm * 64 + i * 16 + rbase;
                    ldsm_x4(af[i], Ab + row * 128 + ((c ^ (row & 7)) << 4));
                }
#pragma unroll
                for (int j = 0; j < 4; j++) {
                    int row = wn * 64 + j * 16 + rbase;
                    ldsm_x4(bf[j], Bb + row * 128 + ((c ^ (row & 7)) << 4));
                }
#pragma unroll
                for (int i = 0; i < 4; i++)
#pragma unroll
                    for (int j = 0; j < 4; j++)
#pragma unroll
                        for (int s2 = 0; s2 < 2; s2++)
                            mma16816_f16(acc[i][j * 2 + s2], af[i], bf[j][s2], bf[j][s2 + 2]);
            }
        }
    };

    load_stage(0, 0);
    for (int t = 0; t < K3PAIRS; t++) {
        cp_wait<0>();
        __syncthreads();
        if (t + 1 < K3PAIRS) load_stage(t + 1, (t + 1) & 1);
        compute_stage(t & 1);
    }
    __syncthreads();   // smem reuse for epilogue

    float* se = (float*)smem;          // [32][EPW]
#pragma unroll
    for (int j = 0; j < 4; j++) {
        int lc = wn * 16 + (lane & 3) * 2;
#pragma unroll
        for (int i = 0; i < 4; i++)
#pragma unroll
            for (int s = 0; s < 2; s++) {
                int lcs = lc + s * 8;
                int m = wm * 64 + i * 16 + (lane >> 2);
                const float* a = acc[i][j * 2 + s];
                se[lcs * EPW + m]           = a[0];
                se[(lcs + 1) * EPW + m]     = a[1];
                se[lcs * EPW + m + 8]       = a[2];
                se[(lcs + 1) * EPW + m + 8] = a[3];
            }
        __syncthreads();
#pragma unroll
        for (int r = 0; r < 4; r++) {
            int lcr = wid * 4 + r;
            int cout = cout0 + ((lcr < 16) ? (j * 16 + lcr) : (64 + j * 16 + lcr - 16));
            float bv = bias[cout];
            const float* row = se + lcr * EPW + lane * 8;
            float4 v0 = *reinterpret_cast<const float4*>(row);
            float4 v1 = *reinterpret_cast<const float4*>(row + 4);
            v0.x += bv; v0.y += bv; v0.z += bv; v0.w += bv;
            v1.x += bv; v1.y += bv; v1.z += bv; v1.w += bv;
            float* o = out + ((size_t)n * COUT + cout) * HW + p0 + lane * 8;
            *reinterpret_cast<float4*>(o) = v0;
            *reinterpret_cast<float4*>(o + 4) = v1;
        }
        __syncthreads();
    }
}

// ---------------------------------------------------------------------------
extern "C" void kernel_launch(void* const* d_in, const int* in_sizes, int n_in,
                              void* d_out, int out_size) {
    const float* x      = (const float*)d_in[0];
    const float* depth  = (const float*)d_in[1];
    const float* weight = (const float*)d_in[2];
    const float* bias   = (const float*)d_in[3];
    const float* off_w  = (const float*)d_in[4];
    const float* off_b  = (const float*)d_in[5];
    const float* mask_w = (const float*)d_in[6];
    const float* mask_b = (const float*)d_in[7];
    float* out = (float*)d_out;

    void *po, *pm, *pch, *pwh, *pxh, *pdt, *pxd, *pw1;
    cudaGetSymbolAddress(&po, g_offsets);
    cudaGetSymbolAddress(&pm, g_mask);
    cudaGetSymbolAddress(&pch, g_colsh);
    cudaGetSymbolAddress(&pwh, g_wh);
    cudaGetSymbolAddress(&pxh, g_xTh);
    cudaGetSymbolAddress(&pdt, g_dT);
    cudaGetSymbolAddress(&pxd, g_xdbf);
    cudaGetSymbolAddress(&pw1, g_ws1);
    float* offsets = (float*)po;
    float* maskbuf = (float*)pm;
    __half* colsh = (__half*)pch;
    __half* wh = (__half*)pwh;
    __half* xTh = (__half*)pxh;
    float* dT = (float*)pdt;
    __nv_bfloat16* xdbf = (__nv_bfloat16*)pxd;
    __nv_bfloat16* ws1 = (__nv_bfloat16*)pw1;

    // Prep (consolidated)
    prep_weights<<<288, 320>>>(weight, off_w, wh, ws1);
    prep_xd<<<dim3(HW / 32, 10, NB), dim3(32, 8)>>>(x, depth, xTh, dT, xdbf);

    static int smem_set = 0;
    if (!smem_set) {
        cudaFuncSetAttribute(s1_hmma, cudaFuncAttributeMaxDynamicSharedMemorySize,
                             2 * S1_STGB);
        cudaFuncSetAttribute(hmma_gemm, cudaFuncAttributeMaxDynamicSharedMemorySize,
                             2 * STG3x2);
        smem_set = 1;
    }

    // Stage 1: offset conv (bf16 3-pass, A-hi reused across passes)
    s1_hmma<<<dim3(HW / 128, 1, NB), 256, 2 * S1_STGB>>>(xdbf, ws1, off_b, offsets);

    // Stage 2: mask = sigmoid(deform_conv(depth, offset))
    fused_mask<<<dim3(HW / 8, NB), 256>>>(dT, offsets, mask_w, mask_b, maskbuf);

    // Stage 3: modulated deformable im2col + fp16 HMMA GEMM
    deform_im2col_f16<<<dim3(HW / 8, NB), 256>>>(xTh, offsets, maskbuf, colsh);
    hmma_gemm<<<dim3(HW / 256, 2, NB), 256, 2 * STG3x2>>>(colsh, wh, bias, out);
}